// round 11
// baseline (speedup 1.0000x reference)
#include <cuda_runtime.h>
#include <math.h>

#define BATCH 16
#define SEQL  2048
#define BL    (BATCH*SEQL)      // 32768
#define DM    128
#define DI    256
#define DX    384
#define NH    4
#define HD    64
#define DS    64
#define CH    64
#define NC    32
#define NPROJ 644

// paired-K layout: within each 8-col block, logical k sits at phys (k&3)*2+(k>>2)
#define KPERM(k) (((k) & 3)*2 + (((k) >> 2) & 1))

// ---------------- scratch ----------------------------------------------------
__device__ float g_z[2][BL*DI];
__device__ float g_xbc0[2][BL*DX];      // pre-conv xBC
__device__ float g_C[2][BL*DS];         // post-conv C (for k_out)
__device__ float g_dt[2][BL*NH];
__device__ float g_st[2][BATCH*NC*NH*HD*DS];   // per h: [p][n]
__device__ float g_yd[2][BL*DI];        // Ydiag + D*xs
__device__ float g_cd[2][BATCH*NH*NC];

__device__ __forceinline__ float softplusf(float x){ return x > 20.f ? x : log1pf(__expf(x)); }
__device__ __forceinline__ float siluf(float x){ return x / (1.f + __expf(-x)); }
__device__ __forceinline__ float dot4(float4 a, float4 b){
    return a.x*b.x + a.y*b.y + a.z*b.z + a.w*b.w;
}
__device__ __forceinline__ float f2tf32(float x){
    unsigned r;
    asm("cvt.rna.tf32.f32 %0, %1;" : "=r"(r) : "f"(x));
    return __uint_as_float(r);
}
__device__ __forceinline__ void mma_tf32(float c[4],
    unsigned a0, unsigned a1, unsigned a2, unsigned a3,
    unsigned b0, unsigned b1)
{
    asm("mma.sync.aligned.m16n8k8.row.col.f32.tf32.tf32.f32 "
        "{%0,%1,%2,%3}, {%4,%5,%6,%7}, {%8,%9}, {%0,%1,%2,%3};"
        : "+f"(c[0]), "+f"(c[1]), "+f"(c[2]), "+f"(c[3])
        : "r"(a0), "r"(a1), "r"(a2), "r"(a3), "r"(b0), "r"(b1));
}

// ================= K1: in_proj GEMM via tf32 MMA, paired-K smem ==============
#define IP_SMEM ((128*132 + 64*132)*4)

__device__ __forceinline__ void ip_store2(int dir, const float* db, int m, int c,
                                          float v0, float v1)
{
    if (c < DI) {
        *(float2*)&g_z[dir][m*DI + c] = make_float2(v0, v1);
    } else if (c < DI + DX) {
        *(float2*)&g_xbc0[dir][m*DX + (c - DI)] = make_float2(v0, v1);
    } else if (c < DI + DX + NH) {
        int h = c - DI - DX;
        g_dt[dir][m*NH + h]     = softplusf(v0 + db[h]);
        g_dt[dir][m*NH + h + 1] = softplusf(v1 + db[h + 1]);
    }
}

__global__ __launch_bounds__(256) void k_inproj(
    const float* __restrict__ x,
    const float* __restrict__ Wi_f, const float* __restrict__ Wi_b,
    const float* __restrict__ db_f, const float* __restrict__ db_b)
{
    extern __shared__ float sm[];
    float (*sX)[132] = (float(*)[132])sm;
    float (*sW)[132] = (float(*)[132])(sm + 128*132);
    int dir = blockIdx.y;
    const float* Wi = dir ? Wi_b : Wi_f;
    const float* db = dir ? db_b : db_f;
    int tid = threadIdx.x;
    int m0 = blockIdx.x * 128;
    int wid = tid >> 5, lane = tid & 31;
    int wm = wid & 1, wn = wid >> 1;
    int gid = lane >> 2, tig = lane & 3;

    #pragma unroll
    for (int it = 0; it < 16; it++) {
        int q = tid + it*256;
        int row = q >> 5, kq = (q & 31) * 4;
        int m = m0 + row;
        int xr = dir ? ((m & ~2047) + 2047 - (m & 2047)) : m;
        float4 v = *(const float4*)&x[xr*128 + kq];
        int pb = kq & ~7, off = (kq & 4) ? 1 : 0;
        sX[row][pb + 0 + off] = f2tf32(v.x);
        sX[row][pb + 2 + off] = f2tf32(v.y);
        sX[row][pb + 4 + off] = f2tf32(v.z);
        sX[row][pb + 6 + off] = f2tf32(v.w);
    }

    for (int nt0 = 0; nt0 < 11; nt0++) {
        int n0 = nt0 * 64;
        __syncthreads();
        #pragma unroll
        for (int it = 0; it < 8; it++) {
            int q = tid + it*256;
            int row = q >> 5, kq = (q & 31) * 4;
            int n = n0 + row;
            float4 v = make_float4(0.f,0.f,0.f,0.f);
            if (n < NPROJ) v = *(const float4*)&Wi[n*128 + kq];
            int pb = kq & ~7, off = (kq & 4) ? 1 : 0;
            sW[row][pb + 0 + off] = f2tf32(v.x);
            sW[row][pb + 2 + off] = f2tf32(v.y);
            sW[row][pb + 4 + off] = f2tf32(v.z);
            sW[row][pb + 6 + off] = f2tf32(v.w);
        }
        __syncthreads();

        float acc[4][2][4] = {};
        #pragma unroll
        for (int ks = 0; ks < 16; ks++) {
            int kb = ks*8;
            float2 bv[2];
            #pragma unroll
            for (int ni = 0; ni < 2; ni++) {
                int n = wn*16 + ni*8 + gid;
                bv[ni] = *(float2*)&sW[n][kb + tig*2];
            }
            #pragma unroll
            for (int mi = 0; mi < 4; mi++) {
                int r = wm*64 + mi*16 + gid;
                float2 va0 = *(float2*)&sX[r    ][kb + tig*2];
                float2 va1 = *(float2*)&sX[r + 8][kb + tig*2];
                unsigned a0 = __float_as_uint(va0.x);
                unsigned a1 = __float_as_uint(va1.x);
                unsigned a2 = __float_as_uint(va0.y);
                unsigned a3 = __float_as_uint(va1.y);
                mma_tf32(acc[mi][0], a0, a1, a2, a3,
                         __float_as_uint(bv[0].x), __float_as_uint(bv[0].y));
                mma_tf32(acc[mi][1], a0, a1, a2, a3,
                         __float_as_uint(bv[1].x), __float_as_uint(bv[1].y));
            }
        }
        #pragma unroll
        for (int mi = 0; mi < 4; mi++) {
            int r0 = m0 + wm*64 + mi*16 + gid;
            #pragma unroll
            for (int ni = 0; ni < 2; ni++) {
                int c = n0 + wn*16 + ni*8 + tig*2;
                ip_store2(dir, db, r0,     c, acc[mi][ni][0], acc[mi][ni][1]);
                ip_store2(dir, db, r0 + 8, c, acc[mi][ni][2], acc[mi][ni][3]);
            }
        }
    }
}

// ================= K3: fused conv+silu + diag block + chunk state ============
#define CH_SMEM (41856*4)
__global__ __launch_bounds__(512) void k_chunk(
    const float* __restrict__ Al_f, const float* __restrict__ Al_b,
    const float* __restrict__ cw_f, const float* __restrict__ cb_f,
    const float* __restrict__ cw_b, const float* __restrict__ cb_b,
    const float* __restrict__ D_f,  const float* __restrict__ D_b)
{
    extern __shared__ float sm[];
    float (*sB)[68]   = (float(*)[68])sm;
    float (*sC)[68]   = (float(*)[68])(sm + 4352);
    float (*sCB)[68]  = (float(*)[68])(sm + 8704);
    float (*sXT)[68]  = (float(*)[68])(sm + 21760);   // [h*64+p][s]
    float (*sdt)[4]   = (float(*)[4])(sm + 39168);
    float (*sAcs)[64] = (float(*)[64])(sm + 39424);
    float *scw        = sm + 39936;
    float *scb        = sm + 41472;

    int c = blockIdx.x, b = blockIdx.y, dir = blockIdx.z;
    const float* gx0 = g_xbc0[dir];
    const float* cw  = dir ? cw_b : cw_f;
    const float* cb  = dir ? cb_b : cb_f;
    const float* Dq  = dir ? D_b  : D_f;
    int tid = threadIdx.x;
    int base = b*SEQL + c*CH;
    int g = tid >> 8;
    int gtid = tid & 255;
    float (*sW)[68] = (float(*)[68])(sm + 13056 + g*4352);
    float *sdec = sm + 39680 + g*64;
    float *sed  = sm + 39808 + g*64;

    int wid8 = (tid >> 5) & 7;
    int lane = tid & 31;
    int gid = lane >> 2, tig = lane & 3;
    int wm = wid8 & 1, wn = wid8 >> 1;

    for (int i = tid; i < 384*4; i += 512) scw[i] = cw[i];
    if (tid < 384) scb[tid] = cb[tid];
    if (tid < 256) { int l = tid >> 2, h = tid & 3; sdt[l][h] = g_dt[dir][base*NH + tid]; }
    __syncthreads();

    #pragma unroll
    for (int it = 0; it < 4; it++) {
        int q = tid + it*512;
        int row = q >> 5;
        int c4 = (q & 31) * 4;
        int jj = 256 + c4;
        float4 acc = *(const float4*)&scb[jj];
        #pragma unroll
        for (int k = 0; k < 4; k++) {
            int t = c*CH + row - 3 + k;
            if (t >= 0) {
                float4 v = *(const float4*)&gx0[(b*SEQL + t)*DX + jj];
                acc.x += v.x * scw[(jj+0)*4 + k];
                acc.y += v.y * scw[(jj+1)*4 + k];
                acc.z += v.z * scw[(jj+2)*4 + k];
                acc.w += v.w * scw[(jj+3)*4 + k];
            }
        }
        acc.x = siluf(acc.x); acc.y = siluf(acc.y);
        acc.z = siluf(acc.z); acc.w = siluf(acc.w);
        if (c4 < 64) {
            sB[row][c4+0] = f2tf32(acc.x); sB[row][c4+1] = f2tf32(acc.y);
            sB[row][c4+2] = f2tf32(acc.z); sB[row][c4+3] = f2tf32(acc.w);
        } else {
            int n4 = c4 - 64;
            sC[row][n4+0] = f2tf32(acc.x); sC[row][n4+1] = f2tf32(acc.y);
            sC[row][n4+2] = f2tf32(acc.z); sC[row][n4+3] = f2tf32(acc.w);
            *(float4*)&g_C[dir][(base+row)*64 + n4] = acc;
        }
    }
    #pragma unroll
    for (int it = 0; it < 8; it++) {
        int q = tid + it*512;
        int s = q >> 6;
        int p4 = (q & 63) * 4;
        float4 acc = *(const float4*)&scb[p4];
        #pragma unroll
        for (int k = 0; k < 4; k++) {
            int t = c*CH + s - 3 + k;
            if (t >= 0) {
                float4 v = *(const float4*)&gx0[(b*SEQL + t)*DX + p4];
                acc.x += v.x * scw[(p4+0)*4 + k];
                acc.y += v.y * scw[(p4+1)*4 + k];
                acc.z += v.z * scw[(p4+2)*4 + k];
                acc.w += v.w * scw[(p4+3)*4 + k];
            }
        }
        float dtv = sdt[s][p4 >> 6];
        sXT[p4+0][s] = f2tf32(siluf(acc.x) * dtv);
        sXT[p4+1][s] = f2tf32(siluf(acc.y) * dtv);
        sXT[p4+2][s] = f2tf32(siluf(acc.z) * dtv);
        sXT[p4+3][s] = f2tf32(siluf(acc.w) * dtv);
    }
    if (tid < 4) {
        float A = -__expf((dir ? Al_b : Al_f)[tid]);
        float run = 0.f;
        for (int l = 0; l < 64; l++) { run += sdt[l][tid] * A; sAcs[tid][l] = run; }
    }
    __syncthreads();

    if (g == 0) {
        float cbf[2][2][4] = {};
        #pragma unroll
        for (int ks = 0; ks < 8; ks++) {
            int kb = ks*8;
            unsigned bfr[2][2];
            #pragma unroll
            for (int nt = 0; nt < 2; nt++) {
                int s = wn*16 + nt*8 + gid;
                bfr[nt][0] = __float_as_uint(sB[s][kb + tig]);
                bfr[nt][1] = __float_as_uint(sB[s][kb + tig + 4]);
            }
            #pragma unroll
            for (int mt = 0; mt < 2; mt++) {
                int r = wm*32 + mt*16 + gid;
                unsigned a0 = __float_as_uint(sC[r    ][kb + tig]);
                unsigned a1 = __float_as_uint(sC[r + 8][kb + tig]);
                unsigned a2 = __float_as_uint(sC[r    ][kb + tig + 4]);
                unsigned a3 = __float_as_uint(sC[r + 8][kb + tig + 4]);
                mma_tf32(cbf[mt][0], a0, a1, a2, a3, bfr[0][0], bfr[0][1]);
                mma_tf32(cbf[mt][1], a0, a1, a2, a3, bfr[1][0], bfr[1][1]);
            }
        }
        #pragma unroll
        for (int mt = 0; mt < 2; mt++) {
            #pragma unroll
            for (int half = 0; half < 2; half++) {
                int l = wm*32 + mt*16 + gid + half*8;
                #pragma unroll
                for (int nt = 0; nt < 2; nt++) {
                    int s0 = wn*16 + nt*8 + tig*2;
                    *(float2*)&sCB[l][s0] =
                        make_float2(cbf[mt][nt][half*2], cbf[mt][nt][half*2 + 1]);
                }
            }
        }
    }

    int sbase = (b*NC + c)*NH*4096;
    for (int h2 = 0; h2 < 2; h2++) {
        int h = h2*2 + g;
        __syncthreads();
        if (gtid < 64) {
            sdec[gtid] = __expf(sAcs[h][63] - sAcs[h][gtid]);
            if (gtid >= 1) sed[gtid] = __expf(sAcs[h][gtid] - sAcs[h][gtid - 1]);
        }
        __syncthreads();

        {
            int lrow = gtid >> 2, part = gtid & 3;
            int s_lo = part * 16;
            if (s_lo > lrow) {
                #pragma unroll
                for (int k = 0; k < 16; k++) sW[lrow][s_lo + k] = 0.f;
            } else {
                int shi = s_lo + 15;
                int s1 = shi < lrow ? shi : lrow;
                for (int s = shi; s > s1; s--) sW[lrow][s] = 0.f;
                float r = __expf(sAcs[h][lrow] - sAcs[h][s1]);
                float dfold = __fdividef(Dq[h], sdt[lrow][h]);
                for (int s = s1; s >= s_lo; s--) {
                    float v = sCB[lrow][s];
                    if (s == lrow) v += dfold;
                    sW[lrow][s] = f2tf32(v * r);
                    if (s > s_lo) r *= sed[s];
                }
            }
        }
        __syncthreads();

        {
            float f2[2][2][4] = {};
            #pragma unroll
            for (int ks = 0; ks < 8; ks++) {
                int kb = ks*8;
                unsigned bfr[2][2];
                #pragma unroll
                for (int nt = 0; nt < 2; nt++) {
                    int p = wn*16 + nt*8 + gid;
                    bfr[nt][0] = __float_as_uint(sXT[h*64 + p][kb + tig]);
                    bfr[nt][1] = __float_as_uint(sXT[h*64 + p][kb + tig + 4]);
                }
                #pragma unroll
                for (int mt = 0; mt < 2; mt++) {
                    int r = wm*32 + mt*16 + gid;
                    unsigned a0 = __float_as_uint(sW[r    ][kb + tig]);
                    unsigned a1 = __float_as_uint(sW[r + 8][kb + tig]);
                    unsigned a2 = __float_as_uint(sW[r    ][kb + tig + 4]);
                    unsigned a3 = __float_as_uint(sW[r + 8][kb + tig + 4]);
                    mma_tf32(f2[mt][0], a0, a1, a2, a3, bfr[0][0], bfr[0][1]);
                    mma_tf32(f2[mt][1], a0, a1, a2, a3, bfr[1][0], bfr[1][1]);
                }
            }
            #pragma unroll
            for (int mt = 0; mt < 2; mt++) {
                #pragma unroll
                for (int half = 0; half < 2; half++) {
                    int l = wm*32 + mt*16 + gid + half*8;
                    #pragma unroll
                    for (int nt = 0; nt < 2; nt++) {
                        int p = wn*16 + nt*8 + tig*2;
                        *(float2*)&g_yd[dir][(base + l)*DI + h*64 + p] =
                            make_float2(f2[mt][nt][half*2], f2[mt][nt][half*2 + 1]);
                    }
                }
            }
        }

        {
            float f3[2][2][4] = {};
            #pragma unroll
            for (int ks = 0; ks < 8; ks++) {
                int kb = ks*8;
                float d0 = sdec[kb + tig], d1 = sdec[kb + tig + 4];
                unsigned bfr[2][2];
                #pragma unroll
                for (int nt = 0; nt < 2; nt++) {
                    int n = wn*16 + nt*8 + gid;
                    bfr[nt][0] = __float_as_uint(sB[kb + tig    ][n]);
                    bfr[nt][1] = __float_as_uint(sB[kb + tig + 4][n]);
                }
                #pragma unroll
                for (int mt = 0; mt < 2; mt++) {
                    int r = h*64 + wm*32 + mt*16 + gid;
                    unsigned a0 = __float_as_uint(f2tf32(sXT[r    ][kb + tig]     * d0));
                    unsigned a1 = __float_as_uint(f2tf32(sXT[r + 8][kb + tig]     * d0));
                    unsigned a2 = __float_as_uint(f2tf32(sXT[r    ][kb + tig + 4] * d1));
                    unsigned a3 = __float_as_uint(f2tf32(sXT[r + 8][kb + tig + 4] * d1));
                    mma_tf32(f3[mt][0], a0, a1, a2, a3, bfr[0][0], bfr[0][1]);
                    mma_tf32(f3[mt][1], a0, a1, a2, a3, bfr[1][0], bfr[1][1]);
                }
            }
            #pragma unroll
            for (int mt = 0; mt < 2; mt++) {
                #pragma unroll
                for (int half = 0; half < 2; half++) {
                    int p = wm*32 + mt*16 + gid + half*8;
                    #pragma unroll
                    for (int nt = 0; nt < 2; nt++) {
                        int n = wn*16 + nt*8 + tig*2;
                        *(float2*)&g_st[dir][sbase + h*4096 + p*64 + n] =
                            make_float2(f3[mt][nt][half*2], f3[mt][nt][half*2 + 1]);
                    }
                }
            }
        }
        if (gtid == 0) g_cd[dir][(b*NH + h)*NC + c] = __expf(sAcs[h][63]);
    }
}

// ================= K4: inter-chunk scan — pipelined, vectorized ==============
__global__ __launch_bounds__(256) void k_scan()
{
    int grp = blockIdx.x;
    int bh  = blockIdx.y;
    int dir = blockIdx.z;
    int h = bh & 3, b = bh >> 2;
    int tid = threadIdx.x;
    int e0 = grp*1024 + tid*4;

    float cd[NC];
    #pragma unroll
    for (int c = 0; c < NC; c++) cd[c] = g_cd[dir][(b*NH + h)*NC + c];

    float* p = &g_st[dir][(b*NC*NH + h)*4096 + e0];
    const int cstride = NH*4096;

    float4 carry = make_float4(0.f, 0.f, 0.f, 0.f);
    float4 nxt = *(float4*)p;
    #pragma unroll
    for (int c = 0; c < NC; c++) {
        float4 cur = nxt;
        if (c + 1 < NC) nxt = *(float4*)(p + (c+1)*cstride);
        *(float4*)(p + c*cstride) = carry;
        float d = cd[c];
        carry.x = carry.x*d + cur.x;
        carry.y = carry.y*d + cur.y;
        carry.z = carry.z*d + cur.z;
        carry.w = carry.w*d + cur.w;
    }
}

// ================= K5: off-diag + epilogue + out_proj — paired-K, aliased ====
// smem floats (27136 = 108.5 KB => 2 CTAs/SM):
// region1 [0,17408): sPrev[256][68]  then  sY[64][260]
// region2 [17408,26112): sC[64][68]  then  sWo[128][68]
// sdt 26112 | sAcs 26368 | sE 26624 | snw 26880
#define OUT_SMEM (27136*4)
__global__ __launch_bounds__(256, 2) void k_out(
    const float* __restrict__ Al_f, const float* __restrict__ Al_b,
    const float* __restrict__ nw_f, const float* __restrict__ nw_b,
    const float* __restrict__ Wo_f, const float* __restrict__ Wo_b,
    float* __restrict__ out)
{
    extern __shared__ float sm[];
    float (*sPrev)[68] = (float(*)[68])sm;             // [hp=256][n] paired-K
    float (*sY)[260]   = (float(*)[260])sm;            // alias; paired-K cols
    float (*sC)[68]    = (float(*)[68])(sm + 17408);   // paired-K
    float (*sWo)[68]   = (float(*)[68])(sm + 17408);   // alias; paired-K
    float (*sdt)[4]    = (float(*)[4])(sm + 26112);
    float (*sAcs)[64]  = (float(*)[64])(sm + 26368);
    float (*sE)[64]    = (float(*)[64])(sm + 26624);
    float *snw         = sm + 26880;                   // nw, pre-permuted

    int c = blockIdx.x, b = blockIdx.y;
    int tid = threadIdx.x;
    int wid = tid >> 5, lane = tid & 31;
    int gid = lane >> 2, tig = lane & 3;

    float oacc[8][4] = {};

    for (int d = 0; d < 2; d++) {
        int cc = d ? (NC - 1 - c) : c;
        int base = b*SEQL + cc*CH;
        const float* Alog = d ? Al_b : Al_f;
        const float* nw   = d ? nw_b : nw_f;
        const float* Wo   = d ? Wo_b : Wo_f;

        __syncthreads();
        { int l = tid >> 2, h = tid & 3; sdt[l][h] = g_dt[d][base*NH + tid]; }
        { snw[(tid & ~7) + KPERM(tid & 7)] = nw[tid]; }
        __syncthreads();
        if (tid < 4) {
            float A = -__expf(Alog[tid]);
            float run = 0.f;
            for (int l = 0; l < 64; l++) { run += sdt[l][tid] * A; sAcs[tid][l] = run; }
        }
        __syncthreads();
        { int h = tid >> 6, l = tid & 63; sE[h][l] = __expf(sAcs[h][l]); }
        #pragma unroll
        for (int it = 0; it < 4; it++) {
            int q = tid + it*256;
            int row = q >> 4, nq = (q & 15) * 4;
            float4 v = *(const float4*)&g_C[d][(base+row)*64 + nq];
            int pb = nq & ~7, off = (nq & 4) ? 1 : 0;
            sC[row][pb + 0 + off] = f2tf32(v.x);
            sC[row][pb + 2 + off] = f2tf32(v.y);
            sC[row][pb + 4 + off] = f2tf32(v.z);
            sC[row][pb + 6 + off] = f2tf32(v.w);
        }
        {
            int pbase = (b*NC + cc)*NH*4096;
            #pragma unroll
            for (int it = 0; it < 16; it++) {
                int q = tid + it*256;
                int row = q >> 4, nq = (q & 15) * 4;
                float4 v = *(const float4*)&g_st[d][pbase + row*64 + nq];
                int pb = nq & ~7, off = (nq & 4) ? 1 : 0;
                sPrev[row][pb + 0 + off] = f2tf32(v.x);
                sPrev[row][pb + 2 + off] = f2tf32(v.y);
                sPrev[row][pb + 4 + off] = f2tf32(v.z);
                sPrev[row][pb + 6 + off] = f2tf32(v.w);
            }
        }
        __syncthreads();

        // ---- off-diag MMAs (paired-K loads from sPrev, sC) ----
        float facc[4][4][4];
        {
            int wn = wid;
            #pragma unroll
            for (int mt = 0; mt < 4; mt++)
                #pragma unroll
                for (int nt = 0; nt < 4; nt++)
                    #pragma unroll
                    for (int k = 0; k < 4; k++) facc[mt][nt][k] = 0.f;
            #pragma unroll
            for (int ks = 0; ks < 8; ks++) {
                int kb = ks*8;
                float2 bv[4];
                #pragma unroll
                for (int nt = 0; nt < 4; nt++) {
                    int r = wn*32 + nt*8 + gid;
                    bv[nt] = *(float2*)&sPrev[r][kb + tig*2];
                }
                #pragma unroll
                for (int mt = 0; mt < 4; mt++) {
                    int r = mt*16 + gid;
                    float2 va0 = *(float2*)&sC[r    ][kb + tig*2];
                    float2 va1 = *(float2*)&sC[r + 8][kb + tig*2];
                    unsigned a0 = __float_as_uint(va0.x);
                    unsigned a1 = __float_as_uint(va1.x);
                    unsigned a2 = __float_as_uint(va0.y);
                    unsigned a3 = __float_as_uint(va1.y);
                    #pragma unroll
                    for (int nt = 0; nt < 4; nt++)
                        mma_tf32(facc[mt][nt], a0, a1, a2, a3,
                                 __float_as_uint(bv[nt].x), __float_as_uint(bv[nt].y));
                }
            }
        }
        __syncthreads();   // all sPrev/sC reads done — sY may overwrite region1

        // ---- epilogue: combine + gate -> sY (paired-K cols, l-flip d=1) ----
        {
            int wn = wid;
            #pragma unroll
            for (int mt = 0; mt < 4; mt++) {
                #pragma unroll
                for (int nt = 0; nt < 4; nt++) {
                    int q = wn*32 + nt*8 + tig*2;
                    int h = q >> 6;
                    int blk = q & ~7;
                    int p0 = blk + KPERM(q & 7);
                    int p1 = blk + KPERM((q & 7) + 1);
                    #pragma unroll
                    for (int half = 0; half < 2; half++) {
                        int l = mt*16 + gid + half*8;
                        int row = base + l;
                        float e = sE[h][l];
                        float2 yd = *(const float2*)&g_yd[d][row*DI + q];
                        float2 z2 = *(const float2*)&g_z[d][row*DI + q];
                        float v0 = facc[mt][nt][half*2 + 0];
                        float v1 = facc[mt][nt][half*2 + 1];
                        float y0 = (yd.x + e*v0) * siluf(z2.x);
                        float y1 = (yd.y + e*v1) * siluf(z2.y);
                        int srow = d ? (63 - l) : l;
                        sY[srow][p0] = y0;
                        sY[srow][p1] = y1;
                    }
                }
            }
        }
        __syncthreads();

        // ---- RMS norm on physical layout (order-invariant), snw permuted ----
        {
            int lr = tid >> 2, part = tid & 3;
            float s = 0.f;
            #pragma unroll
            for (int q = 0; q < 16; q++) {
                float4 v = *(float4*)&sY[lr][part*64 + q*4];
                s += dot4(v, v);
            }
            s += __shfl_xor_sync(0xffffffff, s, 1);
            s += __shfl_xor_sync(0xffffffff, s, 2);
            float scale = rsqrtf(s * (1.f/256.f) + 1e-5f);
            #pragma unroll
            for (int q = 0; q < 16; q++) {
                int col = part*64 + q*4;
                float4 v = *(float4*)&sY[lr][col];
                float4 w = *(float4*)&snw[col];
                v.x = f2tf32(v.x * scale * w.x);
                v.y = f2tf32(v.y * scale * w.y);
                v.z = f2tf32(v.z * scale * w.z);
                v.w = f2tf32(v.w * scale * w.w);
                *(float4*)&sY[lr][col] = v;
            }
        }
        __syncthreads();

        // ---- out_proj: paired-K loads; oacc persists across jc and dirs ----
        {
            int wm = wid & 3, wn2 = wid >> 2;
            for (int jc = 0; jc < 4; jc++) {
                #pragma unroll
                for (int it = 0; it < 8; it++) {
                    int q = tid + it*256;
                    int row = q >> 4, jq = (q & 15) * 4;
                    float4 v = *(const float4*)&Wo[row*256 + jc*64 + jq];
                    int pb = jq & ~7, off = (jq & 4) ? 1 : 0;
                    sWo[row][pb + 0 + off] = f2tf32(v.x);
                    sWo[row][pb + 2 + off] = f2tf32(v.y);
                    sWo[row][pb + 4 + off] = f2tf32(v.z);
                    sWo[row][pb + 6 + off] = f2tf32(v.w);
                }
                __syncthreads();
                #pragma unroll
                for (int ks = 0; ks < 8; ks++) {
                    int kb = ks*8;
                    int ar = wm*16 + gid;
                    float2 va0 = *(float2*)&sY[ar    ][jc*64 + kb + tig*2];
                    float2 va1 = *(float2*)&sY[ar + 8][jc*64 + kb + tig*2];
                    unsigned a0 = __float_as_uint(va0.x);
                    unsigned a1 = __float_as_uint(va1.x);
                    unsigned a2 = __float_as_uint(va0.y);
                    unsigned a3 = __float_as_uint(va1.y);
                    #pragma unroll
                    for (int nt = 0; nt < 8; nt++) {
                        int r = wn2*64 + nt*8 + gid;
                        float2 bv = *(float2*)&sWo[r][kb + tig*2];
                        mma_tf32(oacc[nt], a0, a1, a2, a3,
                                 __float_as_uint(bv.x), __float_as_uint(bv.y));
                    }
                }
                __syncthreads();
            }
        }
    }

    // ---- final store ----
    {
        int wm = wid & 3, wn2 = wid >> 2;
        #pragma unroll
        for (int nt = 0; nt < 8; nt++) {
            int kout = wn2*64 + nt*8 + tig*2;
            #pragma unroll
            for (int half = 0; half < 2; half++) {
                int r = wm*16 + gid + half*8;
                int t = c*CH + r;
                *(float2*)&out[(b*SEQL + t)*DM + kout] =
                    make_float2(oacc[nt][half*2], oacc[nt][half*2 + 1]);
            }
        }
    }
}

extern "C" void kernel_launch(void* const* d_in, const int* in_sizes, int n_in,
                              void* d_out, int out_size)
{
    const float* x    = (const float*)d_in[0];
    const float* Wi_f = (const float*)d_in[1];
    const float* cw_f = (const float*)d_in[2];
    const float* cb_f = (const float*)d_in[3];
    const float* db_f = (const float*)d_in[4];
    const float* Al_f = (const float*)d_in[5];
    const float* D_f  = (const float*)d_in[6];
    const float* nw_f = (const float*)d_in[7];
    const float* Wo_f = (const float*)d_in[8];
    const float* Wi_b = (const float*)d_in[9];
    const float* cw_b = (const float*)d_in[10];
    const float* cb_b = (const float*)d_in[11];
    const float* db_b = (const float*)d_in[12];
    const float* Al_b = (const float*)d_in[13];
    const float* D_b  = (const float*)d_in[14];
    const float* nw_b = (const float*)d_in[15];
    const float* Wo_b = (const float*)d_in[16];
    float* out = (float*)d_out;

    cudaFuncSetAttribute(k_inproj, cudaFuncAttributeMaxDynamicSharedMemorySize, IP_SMEM);
    cudaFuncSetAttribute(k_chunk,  cudaFuncAttributeMaxDynamicSharedMemorySize, CH_SMEM);
    cudaFuncSetAttribute(k_out,    cudaFuncAttributeMaxDynamicSharedMemorySize, OUT_SMEM);

    dim3 g1(BL/128, 2);
    k_inproj<<<g1, 256, IP_SMEM>>>(x, Wi_f, Wi_b, db_f, db_b);

    dim3 g3(NC, BATCH, 2);
    k_chunk<<<g3, 512, CH_SMEM>>>(Al_f, Al_b, cw_f, cb_f, cw_b, cb_b, D_f, D_b);

    dim3 g4(4, BATCH*NH, 2);
    k_scan<<<g4, 256>>>();

    dim3 g5(NC, BATCH);
    k_out<<<g5, 256, OUT_SMEM>>>(Al_f, Al_b, nw_f, nw_b, Wo_f, Wo_b, out);
}

// round 12
// speedup vs baseline: 1.1107x; 1.1107x over previous
#include <cuda_runtime.h>
#include <math.h>

#define BATCH 16
#define SEQL  2048
#define BL    (BATCH*SEQL)      // 32768
#define DM    128
#define DI    256
#define DX    384
#define NH    4
#define HD    64
#define DS    64
#define CH    64
#define NC    32
#define NPROJ 644

// paired-K layout: within each 8-col block, logical k sits at phys (k&3)*2+(k>>2)
#define KPERM(k) (((k) & 3)*2 + (((k) >> 2) & 1))

// ---------------- scratch ----------------------------------------------------
__device__ float g_z[2][BL*DI];
__device__ float g_xbc0[2][BL*DX];      // pre-conv xBC
__device__ float g_C[2][BL*DS];         // post-conv C (for k_out)
__device__ float g_dt[2][BL*NH];
__device__ float g_st[2][BATCH*NC*NH*HD*DS];   // per h: [p][n]
__device__ float g_yd[2][BL*DI];        // Ydiag + D*xs
__device__ float g_cd[2][BATCH*NH*NC];

__device__ __forceinline__ float softplusf(float x){ return x > 20.f ? x : log1pf(__expf(x)); }
__device__ __forceinline__ float siluf(float x){ return x / (1.f + __expf(-x)); }
__device__ __forceinline__ float dot4(float4 a, float4 b){
    return a.x*b.x + a.y*b.y + a.z*b.z + a.w*b.w;
}
__device__ __forceinline__ float f2tf32(float x){
    unsigned r;
    asm("cvt.rna.tf32.f32 %0, %1;" : "=r"(r) : "f"(x));
    return __uint_as_float(r);
}
__device__ __forceinline__ void mma_tf32(float c[4],
    unsigned a0, unsigned a1, unsigned a2, unsigned a3,
    unsigned b0, unsigned b1)
{
    asm("mma.sync.aligned.m16n8k8.row.col.f32.tf32.tf32.f32 "
        "{%0,%1,%2,%3}, {%4,%5,%6,%7}, {%8,%9}, {%0,%1,%2,%3};"
        : "+f"(c[0]), "+f"(c[1]), "+f"(c[2]), "+f"(c[3])
        : "r"(a0), "r"(a1), "r"(a2), "r"(a3), "r"(b0), "r"(b1));
}

// ================= K1: in_proj GEMM via tf32 MMA, paired-K stride 136 ========
#define IP_SMEM ((128*136 + 64*136)*4)

__device__ __forceinline__ void ip_store2(int dir, const float* db, int m, int c,
                                          float v0, float v1)
{
    if (c < DI) {
        *(float2*)&g_z[dir][m*DI + c] = make_float2(v0, v1);
    } else if (c < DI + DX) {
        *(float2*)&g_xbc0[dir][m*DX + (c - DI)] = make_float2(v0, v1);
    } else if (c < DI + DX + NH) {
        int h = c - DI - DX;
        g_dt[dir][m*NH + h]     = softplusf(v0 + db[h]);
        g_dt[dir][m*NH + h + 1] = softplusf(v1 + db[h + 1]);
    }
}

__global__ __launch_bounds__(256) void k_inproj(
    const float* __restrict__ x,
    const float* __restrict__ Wi_f, const float* __restrict__ Wi_b,
    const float* __restrict__ db_f, const float* __restrict__ db_b)
{
    extern __shared__ float sm[];
    float (*sX)[136] = (float(*)[136])sm;
    float (*sW)[136] = (float(*)[136])(sm + 128*136);
    int dir = blockIdx.y;
    const float* Wi = dir ? Wi_b : Wi_f;
    const float* db = dir ? db_b : db_f;
    int tid = threadIdx.x;
    int m0 = blockIdx.x * 128;
    int wid = tid >> 5, lane = tid & 31;
    int wm = wid & 1, wn = wid >> 1;
    int gid = lane >> 2, tig = lane & 3;

    #pragma unroll
    for (int it = 0; it < 16; it++) {
        int q = tid + it*256;
        int row = q >> 5, kq = (q & 31) * 4;
        int m = m0 + row;
        int xr = dir ? ((m & ~2047) + 2047 - (m & 2047)) : m;
        float4 v = *(const float4*)&x[xr*128 + kq];
        int pb = kq & ~7, off = (kq & 4) ? 1 : 0;
        sX[row][pb + 0 + off] = f2tf32(v.x);
        sX[row][pb + 2 + off] = f2tf32(v.y);
        sX[row][pb + 4 + off] = f2tf32(v.z);
        sX[row][pb + 6 + off] = f2tf32(v.w);
    }

    for (int nt0 = 0; nt0 < 11; nt0++) {
        int n0 = nt0 * 64;
        __syncthreads();
        #pragma unroll
        for (int it = 0; it < 8; it++) {
            int q = tid + it*256;
            int row = q >> 5, kq = (q & 31) * 4;
            int n = n0 + row;
            float4 v = make_float4(0.f,0.f,0.f,0.f);
            if (n < NPROJ) v = *(const float4*)&Wi[n*128 + kq];
            int pb = kq & ~7, off = (kq & 4) ? 1 : 0;
            sW[row][pb + 0 + off] = f2tf32(v.x);
            sW[row][pb + 2 + off] = f2tf32(v.y);
            sW[row][pb + 4 + off] = f2tf32(v.z);
            sW[row][pb + 6 + off] = f2tf32(v.w);
        }
        __syncthreads();

        float acc[4][2][4] = {};
        #pragma unroll
        for (int ks = 0; ks < 16; ks++) {
            int kb = ks*8;
            float2 bv[2];
            #pragma unroll
            for (int ni = 0; ni < 2; ni++) {
                int n = wn*16 + ni*8 + gid;
                bv[ni] = *(float2*)&sW[n][kb + tig*2];
            }
            #pragma unroll
            for (int mi = 0; mi < 4; mi++) {
                int r = wm*64 + mi*16 + gid;
                float2 va0 = *(float2*)&sX[r    ][kb + tig*2];
                float2 va1 = *(float2*)&sX[r + 8][kb + tig*2];
                unsigned a0 = __float_as_uint(va0.x);
                unsigned a1 = __float_as_uint(va1.x);
                unsigned a2 = __float_as_uint(va0.y);
                unsigned a3 = __float_as_uint(va1.y);
                mma_tf32(acc[mi][0], a0, a1, a2, a3,
                         __float_as_uint(bv[0].x), __float_as_uint(bv[0].y));
                mma_tf32(acc[mi][1], a0, a1, a2, a3,
                         __float_as_uint(bv[1].x), __float_as_uint(bv[1].y));
            }
        }
        #pragma unroll
        for (int mi = 0; mi < 4; mi++) {
            int r0 = m0 + wm*64 + mi*16 + gid;
            #pragma unroll
            for (int ni = 0; ni < 2; ni++) {
                int c = n0 + wn*16 + ni*8 + tig*2;
                ip_store2(dir, db, r0,     c, acc[mi][ni][0], acc[mi][ni][1]);
                ip_store2(dir, db, r0 + 8, c, acc[mi][ni][2], acc[mi][ni][3]);
            }
        }
    }
}

// ================= K3: fused conv+silu + diag block + chunk state ============
#define CH_SMEM (41856*4)
__global__ __launch_bounds__(512) void k_chunk(
    const float* __restrict__ Al_f, const float* __restrict__ Al_b,
    const float* __restrict__ cw_f, const float* __restrict__ cb_f,
    const float* __restrict__ cw_b, const float* __restrict__ cb_b,
    const float* __restrict__ D_f,  const float* __restrict__ D_b)
{
    extern __shared__ float sm[];
    float (*sB)[68]   = (float(*)[68])sm;
    float (*sC)[68]   = (float(*)[68])(sm + 4352);
    float (*sCB)[68]  = (float(*)[68])(sm + 8704);
    float (*sXT)[68]  = (float(*)[68])(sm + 21760);   // [h*64+p][s]
    float (*sdt)[4]   = (float(*)[4])(sm + 39168);
    float (*sAcs)[64] = (float(*)[64])(sm + 39424);
    float *scw        = sm + 39936;
    float *scb        = sm + 41472;

    int c = blockIdx.x, b = blockIdx.y, dir = blockIdx.z;
    const float* gx0 = g_xbc0[dir];
    const float* cw  = dir ? cw_b : cw_f;
    const float* cb  = dir ? cb_b : cb_f;
    const float* Dq  = dir ? D_b  : D_f;
    int tid = threadIdx.x;
    int base = b*SEQL + c*CH;
    int g = tid >> 8;
    int gtid = tid & 255;
    float (*sW)[68] = (float(*)[68])(sm + 13056 + g*4352);
    float *sdec = sm + 39680 + g*64;
    float *sed  = sm + 39808 + g*64;

    int wid8 = (tid >> 5) & 7;
    int lane = tid & 31;
    int gid = lane >> 2, tig = lane & 3;
    int wm = wid8 & 1, wn = wid8 >> 1;

    for (int i = tid; i < 384*4; i += 512) scw[i] = cw[i];
    if (tid < 384) scb[tid] = cb[tid];
    if (tid < 256) { int l = tid >> 2, h = tid & 3; sdt[l][h] = g_dt[dir][base*NH + tid]; }
    __syncthreads();

    #pragma unroll
    for (int it = 0; it < 4; it++) {
        int q = tid + it*512;
        int row = q >> 5;
        int c4 = (q & 31) * 4;
        int jj = 256 + c4;
        float4 acc = *(const float4*)&scb[jj];
        #pragma unroll
        for (int k = 0; k < 4; k++) {
            int t = c*CH + row - 3 + k;
            if (t >= 0) {
                float4 v = *(const float4*)&gx0[(b*SEQL + t)*DX + jj];
                acc.x += v.x * scw[(jj+0)*4 + k];
                acc.y += v.y * scw[(jj+1)*4 + k];
                acc.z += v.z * scw[(jj+2)*4 + k];
                acc.w += v.w * scw[(jj+3)*4 + k];
            }
        }
        acc.x = siluf(acc.x); acc.y = siluf(acc.y);
        acc.z = siluf(acc.z); acc.w = siluf(acc.w);
        if (c4 < 64) {
            sB[row][c4+0] = f2tf32(acc.x); sB[row][c4+1] = f2tf32(acc.y);
            sB[row][c4+2] = f2tf32(acc.z); sB[row][c4+3] = f2tf32(acc.w);
        } else {
            int n4 = c4 - 64;
            sC[row][n4+0] = f2tf32(acc.x); sC[row][n4+1] = f2tf32(acc.y);
            sC[row][n4+2] = f2tf32(acc.z); sC[row][n4+3] = f2tf32(acc.w);
            *(float4*)&g_C[dir][(base+row)*64 + n4] = acc;
        }
    }
    #pragma unroll
    for (int it = 0; it < 8; it++) {
        int q = tid + it*512;
        int s = q >> 6;
        int p4 = (q & 63) * 4;
        float4 acc = *(const float4*)&scb[p4];
        #pragma unroll
        for (int k = 0; k < 4; k++) {
            int t = c*CH + s - 3 + k;
            if (t >= 0) {
                float4 v = *(const float4*)&gx0[(b*SEQL + t)*DX + p4];
                acc.x += v.x * scw[(p4+0)*4 + k];
                acc.y += v.y * scw[(p4+1)*4 + k];
                acc.z += v.z * scw[(p4+2)*4 + k];
                acc.w += v.w * scw[(p4+3)*4 + k];
            }
        }
        float dtv = sdt[s][p4 >> 6];
        sXT[p4+0][s] = f2tf32(siluf(acc.x) * dtv);
        sXT[p4+1][s] = f2tf32(siluf(acc.y) * dtv);
        sXT[p4+2][s] = f2tf32(siluf(acc.z) * dtv);
        sXT[p4+3][s] = f2tf32(siluf(acc.w) * dtv);
    }
    if (tid < 4) {
        float A = -__expf((dir ? Al_b : Al_f)[tid]);
        float run = 0.f;
        for (int l = 0; l < 64; l++) { run += sdt[l][tid] * A; sAcs[tid][l] = run; }
    }
    __syncthreads();

    if (g == 0) {
        float cbf[2][2][4] = {};
        #pragma unroll
        for (int ks = 0; ks < 8; ks++) {
            int kb = ks*8;
            unsigned bfr[2][2];
            #pragma unroll
            for (int nt = 0; nt < 2; nt++) {
                int s = wn*16 + nt*8 + gid;
                bfr[nt][0] = __float_as_uint(sB[s][kb + tig]);
                bfr[nt][1] = __float_as_uint(sB[s][kb + tig + 4]);
            }
            #pragma unroll
            for (int mt = 0; mt < 2; mt++) {
                int r = wm*32 + mt*16 + gid;
                unsigned a0 = __float_as_uint(sC[r    ][kb + tig]);
                unsigned a1 = __float_as_uint(sC[r + 8][kb + tig]);
                unsigned a2 = __float_as_uint(sC[r    ][kb + tig + 4]);
                unsigned a3 = __float_as_uint(sC[r + 8][kb + tig + 4]);
                mma_tf32(cbf[mt][0], a0, a1, a2, a3, bfr[0][0], bfr[0][1]);
                mma_tf32(cbf[mt][1], a0, a1, a2, a3, bfr[1][0], bfr[1][1]);
            }
        }
        #pragma unroll
        for (int mt = 0; mt < 2; mt++) {
            #pragma unroll
            for (int half = 0; half < 2; half++) {
                int l = wm*32 + mt*16 + gid + half*8;
                #pragma unroll
                for (int nt = 0; nt < 2; nt++) {
                    int s0 = wn*16 + nt*8 + tig*2;
                    *(float2*)&sCB[l][s0] =
                        make_float2(cbf[mt][nt][half*2], cbf[mt][nt][half*2 + 1]);
                }
            }
        }
    }

    int sbase = (b*NC + c)*NH*4096;
    for (int h2 = 0; h2 < 2; h2++) {
        int h = h2*2 + g;
        __syncthreads();
        if (gtid < 64) {
            sdec[gtid] = __expf(sAcs[h][63] - sAcs[h][gtid]);
            if (gtid >= 1) sed[gtid] = __expf(sAcs[h][gtid] - sAcs[h][gtid - 1]);
        }
        __syncthreads();

        {
            int lrow = gtid >> 2, part = gtid & 3;
            int s_lo = part * 16;
            if (s_lo > lrow) {
                #pragma unroll
                for (int k = 0; k < 16; k++) sW[lrow][s_lo + k] = 0.f;
            } else {
                int shi = s_lo + 15;
                int s1 = shi < lrow ? shi : lrow;
                for (int s = shi; s > s1; s--) sW[lrow][s] = 0.f;
                float r = __expf(sAcs[h][lrow] - sAcs[h][s1]);
                float dfold = __fdividef(Dq[h], sdt[lrow][h]);
                for (int s = s1; s >= s_lo; s--) {
                    float v = sCB[lrow][s];
                    if (s == lrow) v += dfold;
                    sW[lrow][s] = f2tf32(v * r);
                    if (s > s_lo) r *= sed[s];
                }
            }
        }
        __syncthreads();

        {
            float f2[2][2][4] = {};
            #pragma unroll
            for (int ks = 0; ks < 8; ks++) {
                int kb = ks*8;
                unsigned bfr[2][2];
                #pragma unroll
                for (int nt = 0; nt < 2; nt++) {
                    int p = wn*16 + nt*8 + gid;
                    bfr[nt][0] = __float_as_uint(sXT[h*64 + p][kb + tig]);
                    bfr[nt][1] = __float_as_uint(sXT[h*64 + p][kb + tig + 4]);
                }
                #pragma unroll
                for (int mt = 0; mt < 2; mt++) {
                    int r = wm*32 + mt*16 + gid;
                    unsigned a0 = __float_as_uint(sW[r    ][kb + tig]);
                    unsigned a1 = __float_as_uint(sW[r + 8][kb + tig]);
                    unsigned a2 = __float_as_uint(sW[r    ][kb + tig + 4]);
                    unsigned a3 = __float_as_uint(sW[r + 8][kb + tig + 4]);
                    mma_tf32(f2[mt][0], a0, a1, a2, a3, bfr[0][0], bfr[0][1]);
                    mma_tf32(f2[mt][1], a0, a1, a2, a3, bfr[1][0], bfr[1][1]);
                }
            }
            #pragma unroll
            for (int mt = 0; mt < 2; mt++) {
                #pragma unroll
                for (int half = 0; half < 2; half++) {
                    int l = wm*32 + mt*16 + gid + half*8;
                    #pragma unroll
                    for (int nt = 0; nt < 2; nt++) {
                        int p = wn*16 + nt*8 + tig*2;
                        *(float2*)&g_yd[dir][(base + l)*DI + h*64 + p] =
                            make_float2(f2[mt][nt][half*2], f2[mt][nt][half*2 + 1]);
                    }
                }
            }
        }

        {
            float f3[2][2][4] = {};
            #pragma unroll
            for (int ks = 0; ks < 8; ks++) {
                int kb = ks*8;
                float d0 = sdec[kb + tig], d1 = sdec[kb + tig + 4];
                unsigned bfr[2][2];
                #pragma unroll
                for (int nt = 0; nt < 2; nt++) {
                    int n = wn*16 + nt*8 + gid;
                    bfr[nt][0] = __float_as_uint(sB[kb + tig    ][n]);
                    bfr[nt][1] = __float_as_uint(sB[kb + tig + 4][n]);
                }
                #pragma unroll
                for (int mt = 0; mt < 2; mt++) {
                    int r = h*64 + wm*32 + mt*16 + gid;
                    unsigned a0 = __float_as_uint(f2tf32(sXT[r    ][kb + tig]     * d0));
                    unsigned a1 = __float_as_uint(f2tf32(sXT[r + 8][kb + tig]     * d0));
                    unsigned a2 = __float_as_uint(f2tf32(sXT[r    ][kb + tig + 4] * d1));
                    unsigned a3 = __float_as_uint(f2tf32(sXT[r + 8][kb + tig + 4] * d1));
                    mma_tf32(f3[mt][0], a0, a1, a2, a3, bfr[0][0], bfr[0][1]);
                    mma_tf32(f3[mt][1], a0, a1, a2, a3, bfr[1][0], bfr[1][1]);
                }
            }
            #pragma unroll
            for (int mt = 0; mt < 2; mt++) {
                #pragma unroll
                for (int half = 0; half < 2; half++) {
                    int p = wm*32 + mt*16 + gid + half*8;
                    #pragma unroll
                    for (int nt = 0; nt < 2; nt++) {
                        int n = wn*16 + nt*8 + tig*2;
                        *(float2*)&g_st[dir][sbase + h*4096 + p*64 + n] =
                            make_float2(f3[mt][nt][half*2], f3[mt][nt][half*2 + 1]);
                    }
                }
            }
        }
        if (gtid == 0) g_cd[dir][(b*NH + h)*NC + c] = __expf(sAcs[h][63]);
    }
}

// ================= K4: inter-chunk scan — pipelined, vectorized ==============
__global__ __launch_bounds__(256) void k_scan()
{
    int grp = blockIdx.x;
    int bh  = blockIdx.y;
    int dir = blockIdx.z;
    int h = bh & 3, b = bh >> 2;
    int tid = threadIdx.x;
    int e0 = grp*1024 + tid*4;

    float cd[NC];
    #pragma unroll
    for (int c = 0; c < NC; c++) cd[c] = g_cd[dir][(b*NH + h)*NC + c];

    float* p = &g_st[dir][(b*NC*NH + h)*4096 + e0];
    const int cstride = NH*4096;

    float4 carry = make_float4(0.f, 0.f, 0.f, 0.f);
    float4 nxt = *(float4*)p;
    #pragma unroll
    for (int c = 0; c < NC; c++) {
        float4 cur = nxt;
        if (c + 1 < NC) nxt = *(float4*)(p + (c+1)*cstride);
        *(float4*)(p + c*cstride) = carry;
        float d = cd[c];
        carry.x = carry.x*d + cur.x;
        carry.y = carry.y*d + cur.y;
        carry.z = carry.z*d + cur.z;
        carry.w = carry.w*d + cur.w;
    }
}

// ================= K5: off-diag + epilogue + out_proj — paired-K stride 72 ===
// smem floats (28672 = 112 KB => 2 CTAs/SM):
// region1 [0,18432): sPrev[256][72]  then  sY[64][264] (16896)
// region2 [18432,27648): sC[64][72]  then  sWo[128][72]
// sdt 27648 | sAcs 27904 | sE 28160 | snw 28416
#define OUT_SMEM (28672*4)
__global__ __launch_bounds__(256, 2) void k_out(
    const float* __restrict__ Al_f, const float* __restrict__ Al_b,
    const float* __restrict__ nw_f, const float* __restrict__ nw_b,
    const float* __restrict__ Wo_f, const float* __restrict__ Wo_b,
    float* __restrict__ out)
{
    extern __shared__ float sm[];
    float (*sPrev)[72] = (float(*)[72])sm;             // [hp=256][n] paired-K
    float (*sY)[264]   = (float(*)[264])sm;            // alias; paired-K cols
    float (*sC)[72]    = (float(*)[72])(sm + 18432);   // paired-K
    float (*sWo)[72]   = (float(*)[72])(sm + 18432);   // alias; paired-K
    float (*sdt)[4]    = (float(*)[4])(sm + 27648);
    float (*sAcs)[64]  = (float(*)[64])(sm + 27904);
    float (*sE)[64]    = (float(*)[64])(sm + 28160);
    float *snw         = sm + 28416;                   // nw, pre-permuted

    int c = blockIdx.x, b = blockIdx.y;
    int tid = threadIdx.x;
    int wid = tid >> 5, lane = tid & 31;
    int gid = lane >> 2, tig = lane & 3;

    float oacc[8][4] = {};

    for (int d = 0; d < 2; d++) {
        int cc = d ? (NC - 1 - c) : c;
        int base = b*SEQL + cc*CH;
        const float* Alog = d ? Al_b : Al_f;
        const float* nw   = d ? nw_b : nw_f;
        const float* Wo   = d ? Wo_b : Wo_f;

        __syncthreads();
        { int l = tid >> 2, h = tid & 3; sdt[l][h] = g_dt[d][base*NH + tid]; }
        { snw[(tid & ~7) + KPERM(tid & 7)] = nw[tid]; }
        __syncthreads();
        if (tid < 4) {
            float A = -__expf(Alog[tid]);
            float run = 0.f;
            for (int l = 0; l < 64; l++) { run += sdt[l][tid] * A; sAcs[tid][l] = run; }
        }
        __syncthreads();
        { int h = tid >> 6, l = tid & 63; sE[h][l] = __expf(sAcs[h][l]); }
        #pragma unroll
        for (int it = 0; it < 4; it++) {
            int q = tid + it*256;
            int row = q >> 4, nq = (q & 15) * 4;
            float4 v = *(const float4*)&g_C[d][(base+row)*64 + nq];
            int pb = nq & ~7, off = (nq & 4) ? 1 : 0;
            sC[row][pb + 0 + off] = f2tf32(v.x);
            sC[row][pb + 2 + off] = f2tf32(v.y);
            sC[row][pb + 4 + off] = f2tf32(v.z);
            sC[row][pb + 6 + off] = f2tf32(v.w);
        }
        {
            int pbase = (b*NC + cc)*NH*4096;
            #pragma unroll
            for (int it = 0; it < 16; it++) {
                int q = tid + it*256;
                int row = q >> 4, nq = (q & 15) * 4;
                float4 v = *(const float4*)&g_st[d][pbase + row*64 + nq];
                int pb = nq & ~7, off = (nq & 4) ? 1 : 0;
                sPrev[row][pb + 0 + off] = f2tf32(v.x);
                sPrev[row][pb + 2 + off] = f2tf32(v.y);
                sPrev[row][pb + 4 + off] = f2tf32(v.z);
                sPrev[row][pb + 6 + off] = f2tf32(v.w);
            }
        }
        __syncthreads();

        // ---- off-diag MMAs (paired-K, conflict-free stride 72) ----
        float facc[4][4][4];
        {
            int wn = wid;
            #pragma unroll
            for (int mt = 0; mt < 4; mt++)
                #pragma unroll
                for (int nt = 0; nt < 4; nt++)
                    #pragma unroll
                    for (int k = 0; k < 4; k++) facc[mt][nt][k] = 0.f;
            #pragma unroll
            for (int ks = 0; ks < 8; ks++) {
                int kb = ks*8;
                float2 bv[4];
                #pragma unroll
                for (int nt = 0; nt < 4; nt++) {
                    int r = wn*32 + nt*8 + gid;
                    bv[nt] = *(float2*)&sPrev[r][kb + tig*2];
                }
                #pragma unroll
                for (int mt = 0; mt < 4; mt++) {
                    int r = mt*16 + gid;
                    float2 va0 = *(float2*)&sC[r    ][kb + tig*2];
                    float2 va1 = *(float2*)&sC[r + 8][kb + tig*2];
                    unsigned a0 = __float_as_uint(va0.x);
                    unsigned a1 = __float_as_uint(va1.x);
                    unsigned a2 = __float_as_uint(va0.y);
                    unsigned a3 = __float_as_uint(va1.y);
                    #pragma unroll
                    for (int nt = 0; nt < 4; nt++)
                        mma_tf32(facc[mt][nt], a0, a1, a2, a3,
                                 __float_as_uint(bv[nt].x), __float_as_uint(bv[nt].y));
                }
            }
        }
        __syncthreads();   // all sPrev/sC reads done — sY may overwrite region1

        // ---- epilogue: combine + gate -> sY (paired-K cols, l-flip d=1) ----
        {
            int wn = wid;
            #pragma unroll
            for (int mt = 0; mt < 4; mt++) {
                #pragma unroll
                for (int nt = 0; nt < 4; nt++) {
                    int q = wn*32 + nt*8 + tig*2;
                    int h = q >> 6;
                    int blk = q & ~7;
                    int p0 = blk + KPERM(q & 7);
                    int p1 = blk + KPERM((q & 7) + 1);
                    #pragma unroll
                    for (int half = 0; half < 2; half++) {
                        int l = mt*16 + gid + half*8;
                        int row = base + l;
                        float e = sE[h][l];
                        float2 yd = *(const float2*)&g_yd[d][row*DI + q];
                        float2 z2 = *(const float2*)&g_z[d][row*DI + q];
                        float v0 = facc[mt][nt][half*2 + 0];
                        float v1 = facc[mt][nt][half*2 + 1];
                        float y0 = (yd.x + e*v0) * siluf(z2.x);
                        float y1 = (yd.y + e*v1) * siluf(z2.y);
                        int srow = d ? (63 - l) : l;
                        sY[srow][p0] = y0;
                        sY[srow][p1] = y1;
                    }
                }
            }
        }
        __syncthreads();

        // ---- RMS norm on physical layout (order-invariant), snw permuted ----
        {
            int lr = tid >> 2, part = tid & 3;
            float s = 0.f;
            #pragma unroll
            for (int q = 0; q < 16; q++) {
                float4 v = *(float4*)&sY[lr][part*64 + q*4];
                s += dot4(v, v);
            }
            s += __shfl_xor_sync(0xffffffff, s, 1);
            s += __shfl_xor_sync(0xffffffff, s, 2);
            float scale = rsqrtf(s * (1.f/256.f) + 1e-5f);
            #pragma unroll
            for (int q = 0; q < 16; q++) {
                int col = part*64 + q*4;
                float4 v = *(float4*)&sY[lr][col];
                float4 w = *(float4*)&snw[col];
                v.x = f2tf32(v.x * scale * w.x);
                v.y = f2tf32(v.y * scale * w.y);
                v.z = f2tf32(v.z * scale * w.z);
                v.w = f2tf32(v.w * scale * w.w);
                *(float4*)&sY[lr][col] = v;
            }
        }
        __syncthreads();

        // ---- out_proj: paired-K loads; oacc persists across jc and dirs ----
        {
            int wm = wid & 3, wn2 = wid >> 2;
            for (int jc = 0; jc < 4; jc++) {
                #pragma unroll
                for (int it = 0; it < 8; it++) {
                    int q = tid + it*256;
                    int row = q >> 4, jq = (q & 15) * 4;
                    float4 v = *(const float4*)&Wo[row*256 + jc*64 + jq];
                    int pb = jq & ~7, off = (jq & 4) ? 1 : 0;
                    sWo[row][pb + 0 + off] = f2tf32(v.x);
                    sWo[row][pb + 2 + off] = f2tf32(v.y);
                    sWo[row][pb + 4 + off] = f2tf32(v.z);
                    sWo[row][pb + 6 + off] = f2tf32(v.w);
                }
                __syncthreads();
                #pragma unroll
                for (int ks = 0; ks < 8; ks++) {
                    int kb = ks*8;
                    int ar = wm*16 + gid;
                    float2 va0 = *(float2*)&sY[ar    ][jc*64 + kb + tig*2];
                    float2 va1 = *(float2*)&sY[ar + 8][jc*64 + kb + tig*2];
                    unsigned a0 = __float_as_uint(va0.x);
                    unsigned a1 = __float_as_uint(va1.x);
                    unsigned a2 = __float_as_uint(va0.y);
                    unsigned a3 = __float_as_uint(va1.y);
                    #pragma unroll
                    for (int nt = 0; nt < 8; nt++) {
                        int r = wn2*64 + nt*8 + gid;
                        float2 bv = *(float2*)&sWo[r][kb + tig*2];
                        mma_tf32(oacc[nt], a0, a1, a2, a3,
                                 __float_as_uint(bv.x), __float_as_uint(bv.y));
                    }
                }
                __syncthreads();
            }
        }
    }

    // ---- final store ----
    {
        int wm = wid & 3, wn2 = wid >> 2;
        #pragma unroll
        for (int nt = 0; nt < 8; nt++) {
            int kout = wn2*64 + nt*8 + tig*2;
            #pragma unroll
            for (int half = 0; half < 2; half++) {
                int r = wm*16 + gid + half*8;
                int t = c*CH + r;
                *(float2*)&out[(b*SEQL + t)*DM + kout] =
                    make_float2(oacc[nt][half*2], oacc[nt][half*2 + 1]);
            }
        }
    }
}

extern "C" void kernel_launch(void* const* d_in, const int* in_sizes, int n_in,
                              void* d_out, int out_size)
{
    const float* x    = (const float*)d_in[0];
    const float* Wi_f = (const float*)d_in[1];
    const float* cw_f = (const float*)d_in[2];
    const float* cb_f = (const float*)d_in[3];
    const float* db_f = (const float*)d_in[4];
    const float* Al_f = (const float*)d_in[5];
    const float* D_f  = (const float*)d_in[6];
    const float* nw_f = (const float*)d_in[7];
    const float* Wo_f = (const float*)d_in[8];
    const float* Wi_b = (const float*)d_in[9];
    const float* cw_b = (const float*)d_in[10];
    const float* cb_b = (const float*)d_in[11];
    const float* db_b = (const float*)d_in[12];
    const float* Al_b = (const float*)d_in[13];
    const float* D_b  = (const float*)d_in[14];
    const float* nw_b = (const float*)d_in[15];
    const float* Wo_b = (const float*)d_in[16];
    float* out = (float*)d_out;

    cudaFuncSetAttribute(k_inproj, cudaFuncAttributeMaxDynamicSharedMemorySize, IP_SMEM);
    cudaFuncSetAttribute(k_chunk,  cudaFuncAttributeMaxDynamicSharedMemorySize, CH_SMEM);
    cudaFuncSetAttribute(k_out,    cudaFuncAttributeMaxDynamicSharedMemorySize, OUT_SMEM);

    dim3 g1(BL/128, 2);
    k_inproj<<<g1, 256, IP_SMEM>>>(x, Wi_f, Wi_b, db_f, db_b);

    dim3 g3(NC, BATCH, 2);
    k_chunk<<<g3, 512, CH_SMEM>>>(Al_f, Al_b, cw_f, cb_f, cw_b, cb_b, D_f, D_b);

    dim3 g4(4, BATCH*NH, 2);
    k_scan<<<g4, 256>>>();

    dim3 g5(NC, BATCH);
    k_out<<<g5, 256, OUT_SMEM>>>(Al_f, Al_b, nw_f, nw_b, Wo_f, Wo_b, out);
}

// round 13
// speedup vs baseline: 1.2077x; 1.0873x over previous
#include <cuda_runtime.h>
#include <math.h>

#define BATCH 16
#define SEQL  2048
#define BL    (BATCH*SEQL)      // 32768
#define DM    128
#define DI    256
#define DX    384
#define NH    4
#define HD    64
#define DS    64
#define CH    64
#define NC    32
#define NPROJ 644

// ---------------- scratch ----------------------------------------------------
__device__ float g_z[2][BL*DI];
__device__ float g_xbc0[2][BL*DX];      // pre-conv xBC
__device__ float g_C[2][BL*DS];         // post-conv C (for k_out)
__device__ float g_dt[2][BL*NH];
__device__ float g_st[2][BATCH*NC*NH*HD*DS];   // per h: [p][n]
__device__ float g_yd[2][BL*DI];        // Ydiag + D*xs
__device__ float g_cd[2][BATCH*NH*NC];

__device__ __forceinline__ float softplusf(float x){ return x > 20.f ? x : log1pf(__expf(x)); }
__device__ __forceinline__ float siluf(float x){ return x / (1.f + __expf(-x)); }
__device__ __forceinline__ float dot4(float4 a, float4 b){
    return a.x*b.x + a.y*b.y + a.z*b.z + a.w*b.w;
}
__device__ __forceinline__ float f2tf32(float x){
    unsigned r;
    asm("cvt.rna.tf32.f32 %0, %1;" : "=r"(r) : "f"(x));
    return __uint_as_float(r);
}
__device__ __forceinline__ void mma_tf32(float c[4],
    unsigned a0, unsigned a1, unsigned a2, unsigned a3,
    unsigned b0, unsigned b1)
{
    asm("mma.sync.aligned.m16n8k8.row.col.f32.tf32.tf32.f32 "
        "{%0,%1,%2,%3}, {%4,%5,%6,%7}, {%8,%9}, {%0,%1,%2,%3};"
        : "+f"(c[0]), "+f"(c[1]), "+f"(c[2]), "+f"(c[3])
        : "r"(a0), "r"(a1), "r"(a2), "r"(a3), "r"(b0), "r"(b1));
}

// ================= K1: in_proj GEMM via tf32 MMA (R10 version) ===============
#define IP_SMEM ((128*132 + 64*132)*4)

__device__ __forceinline__ void ip_store2(int dir, const float* db, int m, int c,
                                          float v0, float v1)
{
    if (c < DI) {
        *(float2*)&g_z[dir][m*DI + c] = make_float2(v0, v1);
    } else if (c < DI + DX) {
        *(float2*)&g_xbc0[dir][m*DX + (c - DI)] = make_float2(v0, v1);
    } else if (c < DI + DX + NH) {
        int h = c - DI - DX;
        g_dt[dir][m*NH + h]     = softplusf(v0 + db[h]);
        g_dt[dir][m*NH + h + 1] = softplusf(v1 + db[h + 1]);
    }
}

__global__ __launch_bounds__(256) void k_inproj(
    const float* __restrict__ x,
    const float* __restrict__ Wi_f, const float* __restrict__ Wi_b,
    const float* __restrict__ db_f, const float* __restrict__ db_b)
{
    extern __shared__ float sm[];
    float (*sX)[132] = (float(*)[132])sm;
    float (*sW)[132] = (float(*)[132])(sm + 128*132);
    int dir = blockIdx.y;
    const float* Wi = dir ? Wi_b : Wi_f;
    const float* db = dir ? db_b : db_f;
    int tid = threadIdx.x;
    int m0 = blockIdx.x * 128;
    int wid = tid >> 5, lane = tid & 31;
    int wm = wid & 1, wn = wid >> 1;
    int gid = lane >> 2, tig = lane & 3;

    #pragma unroll
    for (int it = 0; it < 16; it++) {
        int q = tid + it*256;
        int row = q >> 5, kq = (q & 31) * 4;
        int m = m0 + row;
        int xr = dir ? ((m & ~2047) + 2047 - (m & 2047)) : m;
        float4 v = *(const float4*)&x[xr*128 + kq];
        sX[row][kq+0] = f2tf32(v.x); sX[row][kq+1] = f2tf32(v.y);
        sX[row][kq+2] = f2tf32(v.z); sX[row][kq+3] = f2tf32(v.w);
    }

    for (int nt0 = 0; nt0 < 11; nt0++) {
        int n0 = nt0 * 64;
        __syncthreads();
        #pragma unroll
        for (int it = 0; it < 8; it++) {
            int q = tid + it*256;
            int row = q >> 5, kq = (q & 31) * 4;
            int n = n0 + row;
            float4 v = make_float4(0.f,0.f,0.f,0.f);
            if (n < NPROJ) v = *(const float4*)&Wi[n*128 + kq];
            sW[row][kq+0] = f2tf32(v.x); sW[row][kq+1] = f2tf32(v.y);
            sW[row][kq+2] = f2tf32(v.z); sW[row][kq+3] = f2tf32(v.w);
        }
        __syncthreads();

        float acc[4][2][4] = {};
        #pragma unroll
        for (int ks = 0; ks < 16; ks++) {
            int kb = ks*8;
            unsigned bfr[2][2];
            #pragma unroll
            for (int ni = 0; ni < 2; ni++) {
                int n = wn*16 + ni*8 + gid;
                bfr[ni][0] = __float_as_uint(sW[n][kb + tig]);
                bfr[ni][1] = __float_as_uint(sW[n][kb + tig + 4]);
            }
            #pragma unroll
            for (int mi = 0; mi < 4; mi++) {
                int r = wm*64 + mi*16 + gid;
                unsigned a0 = __float_as_uint(sX[r    ][kb + tig]);
                unsigned a1 = __float_as_uint(sX[r + 8][kb + tig]);
                unsigned a2 = __float_as_uint(sX[r    ][kb + tig + 4]);
                unsigned a3 = __float_as_uint(sX[r + 8][kb + tig + 4]);
                mma_tf32(acc[mi][0], a0, a1, a2, a3, bfr[0][0], bfr[0][1]);
                mma_tf32(acc[mi][1], a0, a1, a2, a3, bfr[1][0], bfr[1][1]);
            }
        }
        #pragma unroll
        for (int mi = 0; mi < 4; mi++) {
            int r0 = m0 + wm*64 + mi*16 + gid;
            #pragma unroll
            for (int ni = 0; ni < 2; ni++) {
                int c = n0 + wn*16 + ni*8 + tig*2;
                ip_store2(dir, db, r0,     c, acc[mi][ni][0], acc[mi][ni][1]);
                ip_store2(dir, db, r0 + 8, c, acc[mi][ni][2], acc[mi][ni][3]);
            }
        }
    }
}

// ================= K3: fused conv+silu + diag + chunk state — 2-CTA ==========
// 256 threads. per-head sXTh. smem floats (19968 = 78 KB => 2 CTAs/SM):
// sB 0 | sCW 4352 (C then W) | sCB 8704 | sXTh 13056 | sdt 17408 | sAcs 17664 |
// sdec 17920 | sed 17984 | scw 18048 | scb 19584
#define CH_SMEM (19968*4)
__global__ __launch_bounds__(256, 2) void k_chunk(
    const float* __restrict__ Al_f, const float* __restrict__ Al_b,
    const float* __restrict__ cw_f, const float* __restrict__ cb_f,
    const float* __restrict__ cw_b, const float* __restrict__ cb_b,
    const float* __restrict__ D_f,  const float* __restrict__ D_b)
{
    extern __shared__ float sm[];
    float (*sB)[68]   = (float(*)[68])sm;
    float (*sCW)[68]  = (float(*)[68])(sm + 4352);    // C for phase1, W per head
    float (*sCB)[68]  = (float(*)[68])(sm + 8704);
    float (*sXTh)[68] = (float(*)[68])(sm + 13056);   // per-head [p][s]
    float (*sdt)[4]   = (float(*)[4])(sm + 17408);
    float (*sAcs)[64] = (float(*)[64])(sm + 17664);
    float *sdec       = sm + 17920;
    float *sed        = sm + 17984;
    float *scw        = sm + 18048;
    float *scb        = sm + 19584;

    int c = blockIdx.x, b = blockIdx.y, dir = blockIdx.z;
    const float* gx0 = g_xbc0[dir];
    const float* cw  = dir ? cw_b : cw_f;
    const float* cb  = dir ? cb_b : cb_f;
    const float* Dq  = dir ? D_b  : D_f;
    int tid = threadIdx.x;
    int base = b*SEQL + c*CH;
    int wid = tid >> 5, lane = tid & 31;
    int gid = lane >> 2, tig = lane & 3;
    int wm = wid & 1, wn = wid >> 1;

    for (int i = tid; i < 384*4; i += 256) scw[i] = cw[i];
    for (int i = tid; i < 384; i += 256) scb[i] = cb[i];
    { int l = tid >> 2, h = tid & 3; sdt[l][h] = g_dt[dir][base*NH + tid]; }
    __syncthreads();

    // ---- conv+silu staging: B/C columns (xbc idx 256..383) ----
    #pragma unroll
    for (int it = 0; it < 8; it++) {
        int q = tid + it*256;             // 2048 quads
        int row = q >> 5;
        int c4 = (q & 31) * 4;            // 0..124
        int jj = 256 + c4;
        float4 acc = *(const float4*)&scb[jj];
        #pragma unroll
        for (int k = 0; k < 4; k++) {
            int t = c*CH + row - 3 + k;
            if (t >= 0) {
                float4 v = *(const float4*)&gx0[(b*SEQL + t)*DX + jj];
                acc.x += v.x * scw[(jj+0)*4 + k];
                acc.y += v.y * scw[(jj+1)*4 + k];
                acc.z += v.z * scw[(jj+2)*4 + k];
                acc.w += v.w * scw[(jj+3)*4 + k];
            }
        }
        acc.x = siluf(acc.x); acc.y = siluf(acc.y);
        acc.z = siluf(acc.z); acc.w = siluf(acc.w);
        if (c4 < 64) {
            sB[row][c4+0] = f2tf32(acc.x); sB[row][c4+1] = f2tf32(acc.y);
            sB[row][c4+2] = f2tf32(acc.z); sB[row][c4+3] = f2tf32(acc.w);
        } else {
            int n4 = c4 - 64;
            sCW[row][n4+0] = f2tf32(acc.x); sCW[row][n4+1] = f2tf32(acc.y);
            sCW[row][n4+2] = f2tf32(acc.z); sCW[row][n4+3] = f2tf32(acc.w);
            *(float4*)&g_C[dir][(base+row)*64 + n4] = acc;
        }
    }
    if (tid < 4) {
        float A = -__expf((dir ? Al_b : Al_f)[tid]);
        float run = 0.f;
        for (int l = 0; l < 64; l++) { run += sdt[l][tid] * A; sAcs[tid][l] = run; }
    }
    __syncthreads();

    // ---- phase 1: CB = C @ B^T -> sCB ----
    {
        float cbf[2][2][4] = {};
        #pragma unroll
        for (int ks = 0; ks < 8; ks++) {
            int kb = ks*8;
            unsigned bfr[2][2];
            #pragma unroll
            for (int nt = 0; nt < 2; nt++) {
                int s = wn*16 + nt*8 + gid;
                bfr[nt][0] = __float_as_uint(sB[s][kb + tig]);
                bfr[nt][1] = __float_as_uint(sB[s][kb + tig + 4]);
            }
            #pragma unroll
            for (int mt = 0; mt < 2; mt++) {
                int r = wm*32 + mt*16 + gid;
                unsigned a0 = __float_as_uint(sCW[r    ][kb + tig]);
                unsigned a1 = __float_as_uint(sCW[r + 8][kb + tig]);
                unsigned a2 = __float_as_uint(sCW[r    ][kb + tig + 4]);
                unsigned a3 = __float_as_uint(sCW[r + 8][kb + tig + 4]);
                mma_tf32(cbf[mt][0], a0, a1, a2, a3, bfr[0][0], bfr[0][1]);
                mma_tf32(cbf[mt][1], a0, a1, a2, a3, bfr[1][0], bfr[1][1]);
            }
        }
        #pragma unroll
        for (int mt = 0; mt < 2; mt++) {
            #pragma unroll
            for (int half = 0; half < 2; half++) {
                int l = wm*32 + mt*16 + gid + half*8;
                #pragma unroll
                for (int nt = 0; nt < 2; nt++) {
                    int s0 = wn*16 + nt*8 + tig*2;
                    *(float2*)&sCB[l][s0] =
                        make_float2(cbf[mt][nt][half*2], cbf[mt][nt][half*2 + 1]);
                }
            }
        }
    }

    int sbase = (b*NC + c)*NH*4096;
    for (int h = 0; h < NH; h++) {
        __syncthreads();   // phase1/prev-head reads of sCW, sXTh done

        // ---- per-head conv+silu staging of X columns h*64..h*64+63 ----
        #pragma unroll
        for (int it = 0; it < 4; it++) {
            int q = tid + it*256;           // 1024 quads
            int s = q >> 4;
            int p4 = (q & 15) * 4;
            int jj = h*64 + p4;
            float4 acc = *(const float4*)&scb[jj];
            #pragma unroll
            for (int k = 0; k < 4; k++) {
                int t = c*CH + s - 3 + k;
                if (t >= 0) {
                    float4 v = *(const float4*)&gx0[(b*SEQL + t)*DX + jj];
                    acc.x += v.x * scw[(jj+0)*4 + k];
                    acc.y += v.y * scw[(jj+1)*4 + k];
                    acc.z += v.z * scw[(jj+2)*4 + k];
                    acc.w += v.w * scw[(jj+3)*4 + k];
                }
            }
            float dtv = sdt[s][h];
            sXTh[p4+0][s] = f2tf32(siluf(acc.x) * dtv);
            sXTh[p4+1][s] = f2tf32(siluf(acc.y) * dtv);
            sXTh[p4+2][s] = f2tf32(siluf(acc.z) * dtv);
            sXTh[p4+3][s] = f2tf32(siluf(acc.w) * dtv);
        }
        if (tid < 64) {
            sdec[tid] = __expf(sAcs[h][63] - sAcs[h][tid]);
            if (tid >= 1) sed[tid] = __expf(sAcs[h][tid] - sAcs[h][tid - 1]);
        }
        __syncthreads();

        // ---- build W[l][s] via row scan; fold D/dt into the diagonal ----
        {
            int lrow = tid >> 2, part = tid & 3;
            int s_lo = part * 16;
            if (s_lo > lrow) {
                #pragma unroll
                for (int k = 0; k < 16; k++) sCW[lrow][s_lo + k] = 0.f;
            } else {
                int shi = s_lo + 15;
                int s1 = shi < lrow ? shi : lrow;
                for (int s = shi; s > s1; s--) sCW[lrow][s] = 0.f;
                float r = __expf(sAcs[h][lrow] - sAcs[h][s1]);
                float dfold = __fdividef(Dq[h], sdt[lrow][h]);
                for (int s = s1; s >= s_lo; s--) {
                    float v = sCB[lrow][s];
                    if (s == lrow) v += dfold;
                    sCW[lrow][s] = f2tf32(v * r);
                    if (s > s_lo) r *= sed[s];
                }
            }
        }
        __syncthreads();

        // ---- phase 2: Ydiag+D*xs: [l][p] = sum_s W[l][s]*XTh[p][s] ----
        {
            float f2[2][2][4] = {};
            #pragma unroll
            for (int ks = 0; ks < 8; ks++) {
                int kb = ks*8;
                unsigned bfr[2][2];
                #pragma unroll
                for (int nt = 0; nt < 2; nt++) {
                    int p = wn*16 + nt*8 + gid;
                    bfr[nt][0] = __float_as_uint(sXTh[p][kb + tig]);
                    bfr[nt][1] = __float_as_uint(sXTh[p][kb + tig + 4]);
                }
                #pragma unroll
                for (int mt = 0; mt < 2; mt++) {
                    int r = wm*32 + mt*16 + gid;
                    unsigned a0 = __float_as_uint(sCW[r    ][kb + tig]);
                    unsigned a1 = __float_as_uint(sCW[r + 8][kb + tig]);
                    unsigned a2 = __float_as_uint(sCW[r    ][kb + tig + 4]);
                    unsigned a3 = __float_as_uint(sCW[r + 8][kb + tig + 4]);
                    mma_tf32(f2[mt][0], a0, a1, a2, a3, bfr[0][0], bfr[0][1]);
                    mma_tf32(f2[mt][1], a0, a1, a2, a3, bfr[1][0], bfr[1][1]);
                }
            }
            #pragma unroll
            for (int mt = 0; mt < 2; mt++) {
                #pragma unroll
                for (int half = 0; half < 2; half++) {
                    int l = wm*32 + mt*16 + gid + half*8;
                    #pragma unroll
                    for (int nt = 0; nt < 2; nt++) {
                        int p = wn*16 + nt*8 + tig*2;
                        *(float2*)&g_yd[dir][(base + l)*DI + h*64 + p] =
                            make_float2(f2[mt][nt][half*2], f2[mt][nt][half*2 + 1]);
                    }
                }
            }
        }

        // ---- phase 3: st[p][n] = sum_l dec[l]*XTh[p][l]*B[l][n] ----
        {
            float f3[2][2][4] = {};
            #pragma unroll
            for (int ks = 0; ks < 8; ks++) {
                int kb = ks*8;
                float d0 = sdec[kb + tig], d1 = sdec[kb + tig + 4];
                unsigned bfr[2][2];
                #pragma unroll
                for (int nt = 0; nt < 2; nt++) {
                    int n = wn*16 + nt*8 + gid;
                    bfr[nt][0] = __float_as_uint(sB[kb + tig    ][n]);
                    bfr[nt][1] = __float_as_uint(sB[kb + tig + 4][n]);
                }
                #pragma unroll
                for (int mt = 0; mt < 2; mt++) {
                    int r = wm*32 + mt*16 + gid;
                    unsigned a0 = __float_as_uint(f2tf32(sXTh[r    ][kb + tig]     * d0));
                    unsigned a1 = __float_as_uint(f2tf32(sXTh[r + 8][kb + tig]     * d0));
                    unsigned a2 = __float_as_uint(f2tf32(sXTh[r    ][kb + tig + 4] * d1));
                    unsigned a3 = __float_as_uint(f2tf32(sXTh[r + 8][kb + tig + 4] * d1));
                    mma_tf32(f3[mt][0], a0, a1, a2, a3, bfr[0][0], bfr[0][1]);
                    mma_tf32(f3[mt][1], a0, a1, a2, a3, bfr[1][0], bfr[1][1]);
                }
            }
            #pragma unroll
            for (int mt = 0; mt < 2; mt++) {
                #pragma unroll
                for (int half = 0; half < 2; half++) {
                    int p = wm*32 + mt*16 + gid + half*8;
                    #pragma unroll
                    for (int nt = 0; nt < 2; nt++) {
                        int n = wn*16 + nt*8 + tig*2;
                        *(float2*)&g_st[dir][sbase + h*4096 + p*64 + n] =
                            make_float2(f3[mt][nt][half*2], f3[mt][nt][half*2 + 1]);
                    }
                }
            }
        }
        if (tid == 0) g_cd[dir][(b*NH + h)*NC + c] = __expf(sAcs[h][63]);
    }
}

// ================= K4: inter-chunk scan — pipelined, vectorized ==============
__global__ __launch_bounds__(256) void k_scan()
{
    int grp = blockIdx.x;
    int bh  = blockIdx.y;
    int dir = blockIdx.z;
    int h = bh & 3, b = bh >> 2;
    int tid = threadIdx.x;
    int e0 = grp*1024 + tid*4;

    float cd[NC];
    #pragma unroll
    for (int c = 0; c < NC; c++) cd[c] = g_cd[dir][(b*NH + h)*NC + c];

    float* p = &g_st[dir][(b*NC*NH + h)*4096 + e0];
    const int cstride = NH*4096;

    float4 carry = make_float4(0.f, 0.f, 0.f, 0.f);
    float4 nxt = *(float4*)p;
    #pragma unroll
    for (int c = 0; c < NC; c++) {
        float4 cur = nxt;
        if (c + 1 < NC) nxt = *(float4*)(p + (c+1)*cstride);
        *(float4*)(p + c*cstride) = carry;
        float d = cd[c];
        carry.x = carry.x*d + cur.x;
        carry.y = carry.y*d + cur.y;
        carry.z = carry.z*d + cur.z;
        carry.w = carry.w*d + cur.w;
    }
}

// ================= K5: off-diag + epilogue + out_proj (R10 version) ==========
// smem floats (26880 = 107.5 KB => 2 CTAs/SM):
// region1 [0,17408): sPrev[256][68]  then  sY[64][260]
// region2 [17408,26112): sC[64][68]  then  sWo[128][68]
// sdt 26112 | sAcs 26368 | sE 26624
#define OUT_SMEM (26880*4)
__global__ __launch_bounds__(256, 2) void k_out(
    const float* __restrict__ Al_f, const float* __restrict__ Al_b,
    const float* __restrict__ nw_f, const float* __restrict__ nw_b,
    const float* __restrict__ Wo_f, const float* __restrict__ Wo_b,
    float* __restrict__ out)
{
    extern __shared__ float sm[];
    float (*sPrev)[68] = (float(*)[68])sm;             // [hp=256][n]
    float (*sY)[260]   = (float(*)[260])sm;            // alias over sPrev
    float (*sC)[68]    = (float(*)[68])(sm + 17408);
    float (*sWo)[68]   = (float(*)[68])(sm + 17408);   // alias over sC
    float (*sdt)[4]    = (float(*)[4])(sm + 26112);
    float (*sAcs)[64]  = (float(*)[64])(sm + 26368);
    float (*sE)[64]    = (float(*)[64])(sm + 26624);

    int c = blockIdx.x, b = blockIdx.y;
    int tid = threadIdx.x;
    int wid = tid >> 5, lane = tid & 31;
    int gid = lane >> 2, tig = lane & 3;

    float oacc[8][4] = {};

    for (int d = 0; d < 2; d++) {
        int cc = d ? (NC - 1 - c) : c;
        int base = b*SEQL + cc*CH;
        const float* Alog = d ? Al_b : Al_f;
        const float* nw   = d ? nw_b : nw_f;
        const float* Wo   = d ? Wo_b : Wo_f;

        __syncthreads();
        { int l = tid >> 2, h = tid & 3; sdt[l][h] = g_dt[d][base*NH + tid]; }
        __syncthreads();
        if (tid < 4) {
            float A = -__expf(Alog[tid]);
            float run = 0.f;
            for (int l = 0; l < 64; l++) { run += sdt[l][tid] * A; sAcs[tid][l] = run; }
        }
        __syncthreads();
        { int h = tid >> 6, l = tid & 63; sE[h][l] = __expf(sAcs[h][l]); }
        #pragma unroll
        for (int it = 0; it < 4; it++) {
            int q = tid + it*256;
            int row = q >> 4, nq = (q & 15) * 4;
            float4 v = *(const float4*)&g_C[d][(base+row)*64 + nq];
            sC[row][nq+0] = f2tf32(v.x); sC[row][nq+1] = f2tf32(v.y);
            sC[row][nq+2] = f2tf32(v.z); sC[row][nq+3] = f2tf32(v.w);
        }
        {
            int pbase = (b*NC + cc)*NH*4096;
            #pragma unroll
            for (int it = 0; it < 16; it++) {
                int q = tid + it*256;
                int row = q >> 4, nq = (q & 15) * 4;
                float4 v = *(const float4*)&g_st[d][pbase + row*64 + nq];
                sPrev[row][nq+0] = f2tf32(v.x); sPrev[row][nq+1] = f2tf32(v.y);
                sPrev[row][nq+2] = f2tf32(v.z); sPrev[row][nq+3] = f2tf32(v.w);
            }
        }
        __syncthreads();

        // ---- off-diag MMAs (reads sPrev, sC) ----
        float facc[4][4][4];
        {
            int wn = wid;
            #pragma unroll
            for (int mt = 0; mt < 4; mt++)
                #pragma unroll
                for (int nt = 0; nt < 4; nt++)
                    #pragma unroll
                    for (int k = 0; k < 4; k++) facc[mt][nt][k] = 0.f;
            #pragma unroll
            for (int ks = 0; ks < 8; ks++) {
                int kb = ks*8;
                unsigned bf[4][2];
                #pragma unroll
                for (int nt = 0; nt < 4; nt++) {
                    int r = wn*32 + nt*8 + gid;
                    bf[nt][0] = __float_as_uint(sPrev[r][kb + tig]);
                    bf[nt][1] = __float_as_uint(sPrev[r][kb + tig + 4]);
                }
                #pragma unroll
                for (int mt = 0; mt < 4; mt++) {
                    int r = mt*16 + gid;
                    unsigned a0 = __float_as_uint(sC[r    ][kb + tig]);
                    unsigned a1 = __float_as_uint(sC[r + 8][kb + tig]);
                    unsigned a2 = __float_as_uint(sC[r    ][kb + tig + 4]);
                    unsigned a3 = __float_as_uint(sC[r + 8][kb + tig + 4]);
                    #pragma unroll
                    for (int nt = 0; nt < 4; nt++)
                        mma_tf32(facc[mt][nt], a0, a1, a2, a3, bf[nt][0], bf[nt][1]);
                }
            }
        }
        __syncthreads();   // all sPrev/sC reads done — sY may overwrite region1

        // ---- epilogue: combine + gate -> sY (l-flip for d=1) ----
        {
            int wn = wid;
            #pragma unroll
            for (int mt = 0; mt < 4; mt++) {
                #pragma unroll
                for (int nt = 0; nt < 4; nt++) {
                    int q = wn*32 + nt*8 + tig*2;
                    int h = q >> 6;
                    #pragma unroll
                    for (int half = 0; half < 2; half++) {
                        int l = mt*16 + gid + half*8;
                        int row = base + l;
                        float e = sE[h][l];
                        float2 yd = *(const float2*)&g_yd[d][row*DI + q];
                        float2 z2 = *(const float2*)&g_z[d][row*DI + q];
                        float v0 = facc[mt][nt][half*2 + 0];
                        float v1 = facc[mt][nt][half*2 + 1];
                        float y0 = (yd.x + e*v0) * siluf(z2.x);
                        float y1 = (yd.y + e*v1) * siluf(z2.y);
                        int srow = d ? (63 - l) : l;
                        *(float2*)&sY[srow][q] = make_float2(y0, y1);
                    }
                }
            }
        }
        __syncthreads();

        // ---- RMS norm per row (4 threads/row), re-quantize to tf32 ----
        {
            int lr = tid >> 2, part = tid & 3;
            float s = 0.f;
            #pragma unroll
            for (int q = 0; q < 16; q++) {
                float4 v = *(float4*)&sY[lr][part*64 + q*4];
                s += dot4(v, v);
            }
            s += __shfl_xor_sync(0xffffffff, s, 1);
            s += __shfl_xor_sync(0xffffffff, s, 2);
            float scale = rsqrtf(s * (1.f/256.f) + 1e-5f);
            #pragma unroll
            for (int q = 0; q < 16; q++) {
                int col = part*64 + q*4;
                float4 v = *(float4*)&sY[lr][col];
                float4 w = *(const float4*)&nw[col];
                v.x = f2tf32(v.x * scale * w.x);
                v.y = f2tf32(v.y * scale * w.y);
                v.z = f2tf32(v.z * scale * w.z);
                v.w = f2tf32(v.w * scale * w.w);
                *(float4*)&sY[lr][col] = v;
            }
        }
        __syncthreads();

        // ---- out_proj: sWo (region2) x sY; oacc persists across jc and dirs --
        {
            int wm = wid & 3, wn2 = wid >> 2;
            for (int jc = 0; jc < 4; jc++) {
                #pragma unroll
                for (int it = 0; it < 8; it++) {
                    int q = tid + it*256;
                    int row = q >> 4, jq = (q & 15) * 4;
                    float4 v = *(const float4*)&Wo[row*256 + jc*64 + jq];
                    sWo[row][jq+0] = f2tf32(v.x); sWo[row][jq+1] = f2tf32(v.y);
                    sWo[row][jq+2] = f2tf32(v.z); sWo[row][jq+3] = f2tf32(v.w);
                }
                __syncthreads();
                #pragma unroll
                for (int ks = 0; ks < 8; ks++) {
                    int kb = ks*8;
                    int ar = wm*16 + gid;
                    unsigned a0 = __float_as_uint(sY[ar    ][jc*64 + kb + tig]);
                    unsigned a1 = __float_as_uint(sY[ar + 8][jc*64 + kb + tig]);
                    unsigned a2 = __float_as_uint(sY[ar    ][jc*64 + kb + tig + 4]);
                    unsigned a3 = __float_as_uint(sY[ar + 8][jc*64 + kb + tig + 4]);
                    #pragma unroll
                    for (int nt = 0; nt < 8; nt++) {
                        int r = wn2*64 + nt*8 + gid;
                        unsigned b0 = __float_as_uint(sWo[r][kb + tig]);
                        unsigned b1 = __float_as_uint(sWo[r][kb + tig + 4]);
                        mma_tf32(oacc[nt], a0, a1, a2, a3, b0, b1);
                    }
                }
                __syncthreads();
            }
        }
    }

    // ---- final store ----
    {
        int wm = wid & 3, wn2 = wid >> 2;
        #pragma unroll
        for (int nt = 0; nt < 8; nt++) {
            int kout = wn2*64 + nt*8 + tig*2;
            #pragma unroll
            for (int half = 0; half < 2; half++) {
                int r = wm*16 + gid + half*8;
                int t = c*CH + r;
                *(float2*)&out[(b*SEQL + t)*DM + kout] =
                    make_float2(oacc[nt][half*2], oacc[nt][half*2 + 1]);
            }
        }
    }
}

extern "C" void kernel_launch(void* const* d_in, const int* in_sizes, int n_in,
                              void* d_out, int out_size)
{
    const float* x    = (const float*)d_in[0];
    const float* Wi_f = (const float*)d_in[1];
    const float* cw_f = (const float*)d_in[2];
    const float* cb_f = (const float*)d_in[3];
    const float* db_f = (const float*)d_in[4];
    const float* Al_f = (const float*)d_in[5];
    const float* D_f  = (const float*)d_in[6];
    const float* nw_f = (const float*)d_in[7];
    const float* Wo_f = (const float*)d_in[8];
    const float* Wi_b = (const float*)d_in[9];
    const float* cw_b = (const float*)d_in[10];
    const float* cb_b = (const float*)d_in[11];
    const float* db_b = (const float*)d_in[12];
    const float* Al_b = (const float*)d_in[13];
    const float* D_b  = (const float*)d_in[14];
    const float* nw_b = (const float*)d_in[15];
    const float* Wo_b = (const float*)d_in[16];
    float* out = (float*)d_out;

    cudaFuncSetAttribute(k_inproj, cudaFuncAttributeMaxDynamicSharedMemorySize, IP_SMEM);
    cudaFuncSetAttribute(k_chunk,  cudaFuncAttributeMaxDynamicSharedMemorySize, CH_SMEM);
    cudaFuncSetAttribute(k_out,    cudaFuncAttributeMaxDynamicSharedMemorySize, OUT_SMEM);

    dim3 g1(BL/128, 2);
    k_inproj<<<g1, 256, IP_SMEM>>>(x, Wi_f, Wi_b, db_f, db_b);

    dim3 g3(NC, BATCH, 2);
    k_chunk<<<g3, 256, CH_SMEM>>>(Al_f, Al_b, cw_f, cb_f, cw_b, cb_b, D_f, D_b);

    dim3 g4(4, BATCH*NH, 2);
    k_scan<<<g4, 256>>>();

    dim3 g5(NC, BATCH);
    k_out<<<g5, 256, OUT_SMEM>>>(Al_f, Al_b, nw_f, nw_b, Wo_f, Wo_b, out);
}

// round 14
// speedup vs baseline: 1.2651x; 1.0475x over previous
#include <cuda_runtime.h>
#include <cuda_fp16.h>
#include <math.h>

#define BATCH 16
#define SEQL  2048
#define BL    (BATCH*SEQL)      // 32768
#define DM    128
#define DI    256
#define DX    384
#define NH    4
#define HD    64
#define DS    64
#define CH    64
#define NC    32
#define NPROJ 644

// ---------------- scratch ----------------------------------------------------
__device__ __half g_z[2][BL*DI];        // fp16
__device__ __half g_xbc0[2][BL*DX];     // fp16 pre-conv xBC
__device__ __half g_C[2][BL*DS];        // fp16 post-conv C
__device__ float  g_dt[2][BL*NH];
__device__ float  g_st[2][BATCH*NC*NH*HD*DS];  // fp32 (scan precision)
__device__ __half g_yd[2][BL*DI];       // fp16 Ydiag + D*xs
__device__ float  g_cd[2][BATCH*NH*NC];

__device__ __forceinline__ float softplusf(float x){ return x > 20.f ? x : log1pf(__expf(x)); }
__device__ __forceinline__ float siluf(float x){ return x / (1.f + __expf(-x)); }
__device__ __forceinline__ float dot4(float4 a, float4 b){
    return a.x*b.x + a.y*b.y + a.z*b.z + a.w*b.w;
}
__device__ __forceinline__ float f2tf32(float x){
    unsigned r;
    asm("cvt.rna.tf32.f32 %0, %1;" : "=r"(r) : "f"(x));
    return __uint_as_float(r);
}
__device__ __forceinline__ float4 h4tof4(const __half* p){
    __half2 a = *(const __half2*)p;
    __half2 b = *(const __half2*)(p + 2);
    float2 fa = __half22float2(a), fb = __half22float2(b);
    return make_float4(fa.x, fa.y, fb.x, fb.y);
}
__device__ __forceinline__ void mma_tf32(float c[4],
    unsigned a0, unsigned a1, unsigned a2, unsigned a3,
    unsigned b0, unsigned b1)
{
    asm("mma.sync.aligned.m16n8k8.row.col.f32.tf32.tf32.f32 "
        "{%0,%1,%2,%3}, {%4,%5,%6,%7}, {%8,%9}, {%0,%1,%2,%3};"
        : "+f"(c[0]), "+f"(c[1]), "+f"(c[2]), "+f"(c[3])
        : "r"(a0), "r"(a1), "r"(a2), "r"(a3), "r"(b0), "r"(b1));
}

// ================= K1: in_proj GEMM via tf32 MMA =============================
#define IP_SMEM ((128*132 + 64*132)*4)

__device__ __forceinline__ void ip_store2(int dir, const float* db, int m, int c,
                                          float v0, float v1)
{
    if (c < DI) {
        *(__half2*)&g_z[dir][m*DI + c] = __floats2half2_rn(v0, v1);
    } else if (c < DI + DX) {
        *(__half2*)&g_xbc0[dir][m*DX + (c - DI)] = __floats2half2_rn(v0, v1);
    } else if (c < DI + DX + NH) {
        int h = c - DI - DX;
        g_dt[dir][m*NH + h]     = softplusf(v0 + db[h]);
        g_dt[dir][m*NH + h + 1] = softplusf(v1 + db[h + 1]);
    }
}

__global__ __launch_bounds__(256) void k_inproj(
    const float* __restrict__ x,
    const float* __restrict__ Wi_f, const float* __restrict__ Wi_b,
    const float* __restrict__ db_f, const float* __restrict__ db_b)
{
    extern __shared__ float sm[];
    float (*sX)[132] = (float(*)[132])sm;
    float (*sW)[132] = (float(*)[132])(sm + 128*132);
    int dir = blockIdx.y;
    const float* Wi = dir ? Wi_b : Wi_f;
    const float* db = dir ? db_b : db_f;
    int tid = threadIdx.x;
    int m0 = blockIdx.x * 128;
    int wid = tid >> 5, lane = tid & 31;
    int wm = wid & 1, wn = wid >> 1;
    int gid = lane >> 2, tig = lane & 3;

    #pragma unroll
    for (int it = 0; it < 16; it++) {
        int q = tid + it*256;
        int row = q >> 5, kq = (q & 31) * 4;
        int m = m0 + row;
        int xr = dir ? ((m & ~2047) + 2047 - (m & 2047)) : m;
        float4 v = *(const float4*)&x[xr*128 + kq];
        sX[row][kq+0] = f2tf32(v.x); sX[row][kq+1] = f2tf32(v.y);
        sX[row][kq+2] = f2tf32(v.z); sX[row][kq+3] = f2tf32(v.w);
    }

    for (int nt0 = 0; nt0 < 11; nt0++) {
        int n0 = nt0 * 64;
        __syncthreads();
        #pragma unroll
        for (int it = 0; it < 8; it++) {
            int q = tid + it*256;
            int row = q >> 5, kq = (q & 31) * 4;
            int n = n0 + row;
            float4 v = make_float4(0.f,0.f,0.f,0.f);
            if (n < NPROJ) v = *(const float4*)&Wi[n*128 + kq];
            sW[row][kq+0] = f2tf32(v.x); sW[row][kq+1] = f2tf32(v.y);
            sW[row][kq+2] = f2tf32(v.z); sW[row][kq+3] = f2tf32(v.w);
        }
        __syncthreads();

        float acc[4][2][4] = {};
        #pragma unroll
        for (int ks = 0; ks < 16; ks++) {
            int kb = ks*8;
            unsigned bfr[2][2];
            #pragma unroll
            for (int ni = 0; ni < 2; ni++) {
                int n = wn*16 + ni*8 + gid;
                bfr[ni][0] = __float_as_uint(sW[n][kb + tig]);
                bfr[ni][1] = __float_as_uint(sW[n][kb + tig + 4]);
            }
            #pragma unroll
            for (int mi = 0; mi < 4; mi++) {
                int r = wm*64 + mi*16 + gid;
                unsigned a0 = __float_as_uint(sX[r    ][kb + tig]);
                unsigned a1 = __float_as_uint(sX[r + 8][kb + tig]);
                unsigned a2 = __float_as_uint(sX[r    ][kb + tig + 4]);
                unsigned a3 = __float_as_uint(sX[r + 8][kb + tig + 4]);
                mma_tf32(acc[mi][0], a0, a1, a2, a3, bfr[0][0], bfr[0][1]);
                mma_tf32(acc[mi][1], a0, a1, a2, a3, bfr[1][0], bfr[1][1]);
            }
        }
        #pragma unroll
        for (int mi = 0; mi < 4; mi++) {
            int r0 = m0 + wm*64 + mi*16 + gid;
            #pragma unroll
            for (int ni = 0; ni < 2; ni++) {
                int c = n0 + wn*16 + ni*8 + tig*2;
                ip_store2(dir, db, r0,     c, acc[mi][ni][0], acc[mi][ni][1]);
                ip_store2(dir, db, r0 + 8, c, acc[mi][ni][2], acc[mi][ni][3]);
            }
        }
    }
}

// ================= K3: fused conv+silu + diag + chunk state — 2-CTA ==========
// 256 threads. per-head sXTh. smem floats (19968 = 78 KB => 2 CTAs/SM)
#define CH_SMEM (19968*4)
__global__ __launch_bounds__(256, 2) void k_chunk(
    const float* __restrict__ Al_f, const float* __restrict__ Al_b,
    const float* __restrict__ cw_f, const float* __restrict__ cb_f,
    const float* __restrict__ cw_b, const float* __restrict__ cb_b,
    const float* __restrict__ D_f,  const float* __restrict__ D_b)
{
    extern __shared__ float sm[];
    float (*sB)[68]   = (float(*)[68])sm;
    float (*sCW)[68]  = (float(*)[68])(sm + 4352);    // C for phase1, W per head
    float (*sCB)[68]  = (float(*)[68])(sm + 8704);
    float (*sXTh)[68] = (float(*)[68])(sm + 13056);   // per-head [p][s]
    float (*sdt)[4]   = (float(*)[4])(sm + 17408);
    float (*sAcs)[64] = (float(*)[64])(sm + 17664);
    float *sdec       = sm + 17920;
    float *sed        = sm + 17984;
    float *scw        = sm + 18048;
    float *scb        = sm + 19584;

    int c = blockIdx.x, b = blockIdx.y, dir = blockIdx.z;
    const __half* gx0 = g_xbc0[dir];
    const float* cw  = dir ? cw_b : cw_f;
    const float* cb  = dir ? cb_b : cb_f;
    const float* Dq  = dir ? D_b  : D_f;
    int tid = threadIdx.x;
    int base = b*SEQL + c*CH;
    int wid = tid >> 5, lane = tid & 31;
    int gid = lane >> 2, tig = lane & 3;
    int wm = wid & 1, wn = wid >> 1;

    for (int i = tid; i < 384*4; i += 256) scw[i] = cw[i];
    for (int i = tid; i < 384; i += 256) scb[i] = cb[i];
    { int l = tid >> 2, h = tid & 3; sdt[l][h] = g_dt[dir][base*NH + tid]; }
    __syncthreads();

    // ---- conv+silu staging: B/C columns (xbc idx 256..383) ----
    #pragma unroll
    for (int it = 0; it < 8; it++) {
        int q = tid + it*256;
        int row = q >> 5;
        int c4 = (q & 31) * 4;
        int jj = 256 + c4;
        float4 acc = *(const float4*)&scb[jj];
        #pragma unroll
        for (int k = 0; k < 4; k++) {
            int t = c*CH + row - 3 + k;
            if (t >= 0) {
                float4 v = h4tof4(&gx0[(b*SEQL + t)*DX + jj]);
                acc.x += v.x * scw[(jj+0)*4 + k];
                acc.y += v.y * scw[(jj+1)*4 + k];
                acc.z += v.z * scw[(jj+2)*4 + k];
                acc.w += v.w * scw[(jj+3)*4 + k];
            }
        }
        acc.x = siluf(acc.x); acc.y = siluf(acc.y);
        acc.z = siluf(acc.z); acc.w = siluf(acc.w);
        if (c4 < 64) {
            sB[row][c4+0] = f2tf32(acc.x); sB[row][c4+1] = f2tf32(acc.y);
            sB[row][c4+2] = f2tf32(acc.z); sB[row][c4+3] = f2tf32(acc.w);
        } else {
            int n4 = c4 - 64;
            sCW[row][n4+0] = f2tf32(acc.x); sCW[row][n4+1] = f2tf32(acc.y);
            sCW[row][n4+2] = f2tf32(acc.z); sCW[row][n4+3] = f2tf32(acc.w);
            *(__half2*)&g_C[dir][(base+row)*64 + n4]     = __floats2half2_rn(acc.x, acc.y);
            *(__half2*)&g_C[dir][(base+row)*64 + n4 + 2] = __floats2half2_rn(acc.z, acc.w);
        }
    }
    if (tid < 4) {
        float A = -__expf((dir ? Al_b : Al_f)[tid]);
        float run = 0.f;
        for (int l = 0; l < 64; l++) { run += sdt[l][tid] * A; sAcs[tid][l] = run; }
    }
    __syncthreads();

    // ---- phase 1: CB = C @ B^T -> sCB ----
    {
        float cbf[2][2][4] = {};
        #pragma unroll
        for (int ks = 0; ks < 8; ks++) {
            int kb = ks*8;
            unsigned bfr[2][2];
            #pragma unroll
            for (int nt = 0; nt < 2; nt++) {
                int s = wn*16 + nt*8 + gid;
                bfr[nt][0] = __float_as_uint(sB[s][kb + tig]);
                bfr[nt][1] = __float_as_uint(sB[s][kb + tig + 4]);
            }
            #pragma unroll
            for (int mt = 0; mt < 2; mt++) {
                int r = wm*32 + mt*16 + gid;
                unsigned a0 = __float_as_uint(sCW[r    ][kb + tig]);
                unsigned a1 = __float_as_uint(sCW[r + 8][kb + tig]);
                unsigned a2 = __float_as_uint(sCW[r    ][kb + tig + 4]);
                unsigned a3 = __float_as_uint(sCW[r + 8][kb + tig + 4]);
                mma_tf32(cbf[mt][0], a0, a1, a2, a3, bfr[0][0], bfr[0][1]);
                mma_tf32(cbf[mt][1], a0, a1, a2, a3, bfr[1][0], bfr[1][1]);
            }
        }
        #pragma unroll
        for (int mt = 0; mt < 2; mt++) {
            #pragma unroll
            for (int half = 0; half < 2; half++) {
                int l = wm*32 + mt*16 + gid + half*8;
                #pragma unroll
                for (int nt = 0; nt < 2; nt++) {
                    int s0 = wn*16 + nt*8 + tig*2;
                    *(float2*)&sCB[l][s0] =
                        make_float2(cbf[mt][nt][half*2], cbf[mt][nt][half*2 + 1]);
                }
            }
        }
    }

    int sbase = (b*NC + c)*NH*4096;
    for (int h = 0; h < NH; h++) {
        __syncthreads();   // phase1/prev-head reads of sCW, sXTh done

        // ---- per-head conv+silu staging of X columns h*64..h*64+63 ----
        #pragma unroll
        for (int it = 0; it < 4; it++) {
            int q = tid + it*256;
            int s = q >> 4;
            int p4 = (q & 15) * 4;
            int jj = h*64 + p4;
            float4 acc = *(const float4*)&scb[jj];
            #pragma unroll
            for (int k = 0; k < 4; k++) {
                int t = c*CH + s - 3 + k;
                if (t >= 0) {
                    float4 v = h4tof4(&gx0[(b*SEQL + t)*DX + jj]);
                    acc.x += v.x * scw[(jj+0)*4 + k];
                    acc.y += v.y * scw[(jj+1)*4 + k];
                    acc.z += v.z * scw[(jj+2)*4 + k];
                    acc.w += v.w * scw[(jj+3)*4 + k];
                }
            }
            float dtv = sdt[s][h];
            sXTh[p4+0][s] = f2tf32(siluf(acc.x) * dtv);
            sXTh[p4+1][s] = f2tf32(siluf(acc.y) * dtv);
            sXTh[p4+2][s] = f2tf32(siluf(acc.z) * dtv);
            sXTh[p4+3][s] = f2tf32(siluf(acc.w) * dtv);
        }
        if (tid < 64) {
            sdec[tid] = __expf(sAcs[h][63] - sAcs[h][tid]);
            if (tid >= 1) sed[tid] = __expf(sAcs[h][tid] - sAcs[h][tid - 1]);
        }
        __syncthreads();

        // ---- build W[l][s] via row scan; fold D/dt into the diagonal ----
        {
            int lrow = tid >> 2, part = tid & 3;
            int s_lo = part * 16;
            if (s_lo > lrow) {
                #pragma unroll
                for (int k = 0; k < 16; k++) sCW[lrow][s_lo + k] = 0.f;
            } else {
                int shi = s_lo + 15;
                int s1 = shi < lrow ? shi : lrow;
                for (int s = shi; s > s1; s--) sCW[lrow][s] = 0.f;
                float r = __expf(sAcs[h][lrow] - sAcs[h][s1]);
                float dfold = __fdividef(Dq[h], sdt[lrow][h]);
                for (int s = s1; s >= s_lo; s--) {
                    float v = sCB[lrow][s];
                    if (s == lrow) v += dfold;
                    sCW[lrow][s] = f2tf32(v * r);
                    if (s > s_lo) r *= sed[s];
                }
            }
        }
        __syncthreads();

        // ---- phase 2: Ydiag+D*xs -> g_yd (fp16) ----
        {
            float f2[2][2][4] = {};
            #pragma unroll
            for (int ks = 0; ks < 8; ks++) {
                int kb = ks*8;
                unsigned bfr[2][2];
                #pragma unroll
                for (int nt = 0; nt < 2; nt++) {
                    int p = wn*16 + nt*8 + gid;
                    bfr[nt][0] = __float_as_uint(sXTh[p][kb + tig]);
                    bfr[nt][1] = __float_as_uint(sXTh[p][kb + tig + 4]);
                }
                #pragma unroll
                for (int mt = 0; mt < 2; mt++) {
                    int r = wm*32 + mt*16 + gid;
                    unsigned a0 = __float_as_uint(sCW[r    ][kb + tig]);
                    unsigned a1 = __float_as_uint(sCW[r + 8][kb + tig]);
                    unsigned a2 = __float_as_uint(sCW[r    ][kb + tig + 4]);
                    unsigned a3 = __float_as_uint(sCW[r + 8][kb + tig + 4]);
                    mma_tf32(f2[mt][0], a0, a1, a2, a3, bfr[0][0], bfr[0][1]);
                    mma_tf32(f2[mt][1], a0, a1, a2, a3, bfr[1][0], bfr[1][1]);
                }
            }
            #pragma unroll
            for (int mt = 0; mt < 2; mt++) {
                #pragma unroll
                for (int half = 0; half < 2; half++) {
                    int l = wm*32 + mt*16 + gid + half*8;
                    #pragma unroll
                    for (int nt = 0; nt < 2; nt++) {
                        int p = wn*16 + nt*8 + tig*2;
                        *(__half2*)&g_yd[dir][(base + l)*DI + h*64 + p] =
                            __floats2half2_rn(f2[mt][nt][half*2], f2[mt][nt][half*2 + 1]);
                    }
                }
            }
        }

        // ---- phase 3: st[p][n] = sum_l dec[l]*XTh[p][l]*B[l][n] ----
        {
            float f3[2][2][4] = {};
            #pragma unroll
            for (int ks = 0; ks < 8; ks++) {
                int kb = ks*8;
                float d0 = sdec[kb + tig], d1 = sdec[kb + tig + 4];
                unsigned bfr[2][2];
                #pragma unroll
                for (int nt = 0; nt < 2; nt++) {
                    int n = wn*16 + nt*8 + gid;
                    bfr[nt][0] = __float_as_uint(sB[kb + tig    ][n]);
                    bfr[nt][1] = __float_as_uint(sB[kb + tig + 4][n]);
                }
                #pragma unroll
                for (int mt = 0; mt < 2; mt++) {
                    int r = wm*32 + mt*16 + gid;
                    unsigned a0 = __float_as_uint(f2tf32(sXTh[r    ][kb + tig]     * d0));
                    unsigned a1 = __float_as_uint(f2tf32(sXTh[r + 8][kb + tig]     * d0));
                    unsigned a2 = __float_as_uint(f2tf32(sXTh[r    ][kb + tig + 4] * d1));
                    unsigned a3 = __float_as_uint(f2tf32(sXTh[r + 8][kb + tig + 4] * d1));
                    mma_tf32(f3[mt][0], a0, a1, a2, a3, bfr[0][0], bfr[0][1]);
                    mma_tf32(f3[mt][1], a0, a1, a2, a3, bfr[1][0], bfr[1][1]);
                }
            }
            #pragma unroll
            for (int mt = 0; mt < 2; mt++) {
                #pragma unroll
                for (int half = 0; half < 2; half++) {
                    int p = wm*32 + mt*16 + gid + half*8;
                    #pragma unroll
                    for (int nt = 0; nt < 2; nt++) {
                        int n = wn*16 + nt*8 + tig*2;
                        *(float2*)&g_st[dir][sbase + h*4096 + p*64 + n] =
                            make_float2(f3[mt][nt][half*2], f3[mt][nt][half*2 + 1]);
                    }
                }
            }
        }
        if (tid == 0) g_cd[dir][(b*NH + h)*NC + c] = __expf(sAcs[h][63]);
    }
}

// ================= K4: inter-chunk scan — pipelined, vectorized ==============
__global__ __launch_bounds__(256) void k_scan()
{
    int grp = blockIdx.x;
    int bh  = blockIdx.y;
    int dir = blockIdx.z;
    int h = bh & 3, b = bh >> 2;
    int tid = threadIdx.x;
    int e0 = grp*1024 + tid*4;

    float cd[NC];
    #pragma unroll
    for (int c = 0; c < NC; c++) cd[c] = g_cd[dir][(b*NH + h)*NC + c];

    float* p = &g_st[dir][(b*NC*NH + h)*4096 + e0];
    const int cstride = NH*4096;

    float4 carry = make_float4(0.f, 0.f, 0.f, 0.f);
    float4 nxt = *(float4*)p;
    #pragma unroll
    for (int c = 0; c < NC; c++) {
        float4 cur = nxt;
        if (c + 1 < NC) nxt = *(float4*)(p + (c+1)*cstride);
        *(float4*)(p + c*cstride) = carry;
        float d = cd[c];
        carry.x = carry.x*d + cur.x;
        carry.y = carry.y*d + cur.y;
        carry.z = carry.z*d + cur.z;
        carry.w = carry.w*d + cur.w;
    }
}

// ================= K5: off-diag + epilogue + out_proj ========================
// smem floats (26880 = 107.5 KB => 2 CTAs/SM)
#define OUT_SMEM (26880*4)
__global__ __launch_bounds__(256, 2) void k_out(
    const float* __restrict__ Al_f, const float* __restrict__ Al_b,
    const float* __restrict__ nw_f, const float* __restrict__ nw_b,
    const float* __restrict__ Wo_f, const float* __restrict__ Wo_b,
    float* __restrict__ out)
{
    extern __shared__ float sm[];
    float (*sPrev)[68] = (float(*)[68])sm;             // [hp=256][n]
    float (*sY)[260]   = (float(*)[260])sm;            // alias over sPrev
    float (*sC)[68]    = (float(*)[68])(sm + 17408);
    float (*sWo)[68]   = (float(*)[68])(sm + 17408);   // alias over sC
    float (*sdt)[4]    = (float(*)[4])(sm + 26112);
    float (*sAcs)[64]  = (float(*)[64])(sm + 26368);
    float (*sE)[64]    = (float(*)[64])(sm + 26624);

    int c = blockIdx.x, b = blockIdx.y;
    int tid = threadIdx.x;
    int wid = tid >> 5, lane = tid & 31;
    int gid = lane >> 2, tig = lane & 3;

    float oacc[8][4] = {};

    for (int d = 0; d < 2; d++) {
        int cc = d ? (NC - 1 - c) : c;
        int base = b*SEQL + cc*CH;
        const float* Alog = d ? Al_b : Al_f;
        const float* nw   = d ? nw_b : nw_f;
        const float* Wo   = d ? Wo_b : Wo_f;

        __syncthreads();
        { int l = tid >> 2, h = tid & 3; sdt[l][h] = g_dt[d][base*NH + tid]; }
        __syncthreads();
        if (tid < 4) {
            float A = -__expf(Alog[tid]);
            float run = 0.f;
            for (int l = 0; l < 64; l++) { run += sdt[l][tid] * A; sAcs[tid][l] = run; }
        }
        __syncthreads();
        { int h = tid >> 6, l = tid & 63; sE[h][l] = __expf(sAcs[h][l]); }
        #pragma unroll
        for (int it = 0; it < 4; it++) {
            int q = tid + it*256;
            int row = q >> 4, nq = (q & 15) * 4;
            float4 v = h4tof4(&g_C[d][(base+row)*64 + nq]);
            sC[row][nq+0] = f2tf32(v.x); sC[row][nq+1] = f2tf32(v.y);
            sC[row][nq+2] = f2tf32(v.z); sC[row][nq+3] = f2tf32(v.w);
        }
        {
            int pbase = (b*NC + cc)*NH*4096;
            #pragma unroll
            for (int it = 0; it < 16; it++) {
                int q = tid + it*256;
                int row = q >> 4, nq = (q & 15) * 4;
                float4 v = *(const float4*)&g_st[d][pbase + row*64 + nq];
                sPrev[row][nq+0] = f2tf32(v.x); sPrev[row][nq+1] = f2tf32(v.y);
                sPrev[row][nq+2] = f2tf32(v.z); sPrev[row][nq+3] = f2tf32(v.w);
            }
        }
        __syncthreads();

        // ---- off-diag MMAs (reads sPrev, sC) ----
        float facc[4][4][4];
        {
            int wn = wid;
            #pragma unroll
            for (int mt = 0; mt < 4; mt++)
                #pragma unroll
                for (int nt = 0; nt < 4; nt++)
                    #pragma unroll
                    for (int k = 0; k < 4; k++) facc[mt][nt][k] = 0.f;
            #pragma unroll
            for (int ks = 0; ks < 8; ks++) {
                int kb = ks*8;
                unsigned bf[4][2];
                #pragma unroll
                for (int nt = 0; nt < 4; nt++) {
                    int r = wn*32 + nt*8 + gid;
                    bf[nt][0] = __float_as_uint(sPrev[r][kb + tig]);
                    bf[nt][1] = __float_as_uint(sPrev[r][kb + tig + 4]);
                }
                #pragma unroll
                for (int mt = 0; mt < 4; mt++) {
                    int r = mt*16 + gid;
                    unsigned a0 = __float_as_uint(sC[r    ][kb + tig]);
                    unsigned a1 = __float_as_uint(sC[r + 8][kb + tig]);
                    unsigned a2 = __float_as_uint(sC[r    ][kb + tig + 4]);
                    unsigned a3 = __float_as_uint(sC[r + 8][kb + tig + 4]);
                    #pragma unroll
                    for (int nt = 0; nt < 4; nt++)
                        mma_tf32(facc[mt][nt], a0, a1, a2, a3, bf[nt][0], bf[nt][1]);
                }
            }
        }
        __syncthreads();   // all sPrev/sC reads done — sY may overwrite region1

        // ---- epilogue: combine + gate -> sY (l-flip for d=1) ----
        {
            int wn = wid;
            #pragma unroll
            for (int mt = 0; mt < 4; mt++) {
                #pragma unroll
                for (int nt = 0; nt < 4; nt++) {
                    int q = wn*32 + nt*8 + tig*2;
                    int h = q >> 6;
                    #pragma unroll
                    for (int half = 0; half < 2; half++) {
                        int l = mt*16 + gid + half*8;
                        int row = base + l;
                        float e = sE[h][l];
                        float2 yd = __half22float2(*(const __half2*)&g_yd[d][row*DI + q]);
                        float2 z2 = __half22float2(*(const __half2*)&g_z[d][row*DI + q]);
                        float v0 = facc[mt][nt][half*2 + 0];
                        float v1 = facc[mt][nt][half*2 + 1];
                        float y0 = (yd.x + e*v0) * siluf(z2.x);
                        float y1 = (yd.y + e*v1) * siluf(z2.y);
                        int srow = d ? (63 - l) : l;
                        *(float2*)&sY[srow][q] = make_float2(y0, y1);
                    }
                }
            }
        }
        __syncthreads();

        // ---- RMS norm per row (4 threads/row), re-quantize to tf32 ----
        {
            int lr = tid >> 2, part = tid & 3;
            float s = 0.f;
            #pragma unroll
            for (int q = 0; q < 16; q++) {
                float4 v = *(float4*)&sY[lr][part*64 + q*4];
                s += dot4(v, v);
            }
            s += __shfl_xor_sync(0xffffffff, s, 1);
            s += __shfl_xor_sync(0xffffffff, s, 2);
            float scale = rsqrtf(s * (1.f/256.f) + 1e-5f);
            #pragma unroll
            for (int q = 0; q < 16; q++) {
                int col = part*64 + q*4;
                float4 v = *(float4*)&sY[lr][col];
                float4 w = *(const float4*)&nw[col];
                v.x = f2tf32(v.x * scale * w.x);
                v.y = f2tf32(v.y * scale * w.y);
                v.z = f2tf32(v.z * scale * w.z);
                v.w = f2tf32(v.w * scale * w.w);
                *(float4*)&sY[lr][col] = v;
            }
        }
        __syncthreads();

        // ---- out_proj: sWo (region2) x sY; oacc persists across jc and dirs --
        {
            int wm = wid & 3, wn2 = wid >> 2;
            for (int jc = 0; jc < 4; jc++) {
                #pragma unroll
                for (int it = 0; it < 8; it++) {
                    int q = tid + it*256;
                    int row = q >> 4, jq = (q & 15) * 4;
                    float4 v = *(const float4*)&Wo[row*256 + jc*64 + jq];
                    sWo[row][jq+0] = f2tf32(v.x); sWo[row][jq+1] = f2tf32(v.y);
                    sWo[row][jq+2] = f2tf32(v.z); sWo[row][jq+3] = f2tf32(v.w);
                }
                __syncthreads();
                #pragma unroll
                for (int ks = 0; ks < 8; ks++) {
                    int kb = ks*8;
                    int ar = wm*16 + gid;
                    unsigned a0 = __float_as_uint(sY[ar    ][jc*64 + kb + tig]);
                    unsigned a1 = __float_as_uint(sY[ar + 8][jc*64 + kb + tig]);
                    unsigned a2 = __float_as_uint(sY[ar    ][jc*64 + kb + tig + 4]);
                    unsigned a3 = __float_as_uint(sY[ar + 8][jc*64 + kb + tig + 4]);
                    #pragma unroll
                    for (int nt = 0; nt < 8; nt++) {
                        int r = wn2*64 + nt*8 + gid;
                        unsigned b0 = __float_as_uint(sWo[r][kb + tig]);
                        unsigned b1 = __float_as_uint(sWo[r][kb + tig + 4]);
                        mma_tf32(oacc[nt], a0, a1, a2, a3, b0, b1);
                    }
                }
                __syncthreads();
            }
        }
    }

    // ---- final store ----
    {
        int wm = wid & 3, wn2 = wid >> 2;
        #pragma unroll
        for (int nt = 0; nt < 8; nt++) {
            int kout = wn2*64 + nt*8 + tig*2;
            #pragma unroll
            for (int half = 0; half < 2; half++) {
                int r = wm*16 + gid + half*8;
                int t = c*CH + r;
                *(float2*)&out[(b*SEQL + t)*DM + kout] =
                    make_float2(oacc[nt][half*2], oacc[nt][half*2 + 1]);
            }
        }
    }
}

extern "C" void kernel_launch(void* const* d_in, const int* in_sizes, int n_in,
                              void* d_out, int out_size)
{
    const float* x    = (const float*)d_in[0];
    const float* Wi_f = (const float*)d_in[1];
    const float* cw_f = (const float*)d_in[2];
    const float* cb_f = (const float*)d_in[3];
    const float* db_f = (const float*)d_in[4];
    const float* Al_f = (const float*)d_in[5];
    const float* D_f  = (const float*)d_in[6];
    const float* nw_f = (const float*)d_in[7];
    const float* Wo_f = (const float*)d_in[8];
    const float* Wi_b = (const float*)d_in[9];
    const float* cw_b = (const float*)d_in[10];
    const float* cb_b = (const float*)d_in[11];
    const float* db_b = (const float*)d_in[12];
    const float* Al_b = (const float*)d_in[13];
    const float* D_b  = (const float*)d_in[14];
    const float* nw_b = (const float*)d_in[15];
    const float* Wo_b = (const float*)d_in[16];
    float* out = (float*)d_out;

    cudaFuncSetAttribute(k_inproj, cudaFuncAttributeMaxDynamicSharedMemorySize, IP_SMEM);
    cudaFuncSetAttribute(k_chunk,  cudaFuncAttributeMaxDynamicSharedMemorySize, CH_SMEM);
    cudaFuncSetAttribute(k_out,    cudaFuncAttributeMaxDynamicSharedMemorySize, OUT_SMEM);

    dim3 g1(BL/128, 2);
    k_inproj<<<g1, 256, IP_SMEM>>>(x, Wi_f, Wi_b, db_f, db_b);

    dim3 g3(NC, BATCH, 2);
    k_chunk<<<g3, 256, CH_SMEM>>>(Al_f, Al_b, cw_f, cb_f, cw_b, cb_b, D_f, D_b);

    dim3 g4(4, BATCH*NH, 2);
    k_scan<<<g4, 256>>>();

    dim3 g5(NC, BATCH);
    k_out<<<g5, 256, OUT_SMEM>>>(Al_f, Al_b, nw_f, nw_b, Wo_f, Wo_b, out);
}

// round 15
// speedup vs baseline: 1.5065x; 1.1908x over previous
#include <cuda_runtime.h>
#include <cuda_fp16.h>
#include <math.h>

#define BATCH 16
#define SEQL  2048
#define BL    (BATCH*SEQL)      // 32768
#define DM    128
#define DI    256
#define DX    384
#define NH    4
#define HD    64
#define DS    64
#define CH    64
#define NC    32
#define NPROJ 644

// ---------------- scratch ----------------------------------------------------
__device__ __half g_z[2][BL*DI];        // fp16
__device__ __half g_xbc0[2][BL*DX];     // fp16 pre-conv xBC
__device__ __half g_C[2][BL*DS];        // fp16 post-conv C
__device__ float  g_dt[2][BL*NH];
__device__ float  g_st[2][BATCH*NC*NH*HD*DS];  // fp32 (scan precision)
__device__ __half g_yd[2][BL*DI];       // fp16 Ydiag + D*xs
__device__ float  g_cd[2][BATCH*NH*NC];

__device__ __forceinline__ float softplusf(float x){ return x > 20.f ? x : log1pf(__expf(x)); }
__device__ __forceinline__ float siluf(float x){ return x / (1.f + __expf(-x)); }
__device__ __forceinline__ float dot4(float4 a, float4 b){
    return a.x*b.x + a.y*b.y + a.z*b.z + a.w*b.w;
}
__device__ __forceinline__ float f2tf32(float x){
    unsigned r;
    asm("cvt.rna.tf32.f32 %0, %1;" : "=r"(r) : "f"(x));
    return __uint_as_float(r);
}
__device__ __forceinline__ float4 h4tof4(const __half* p){
    __half2 a = *(const __half2*)p;
    __half2 b = *(const __half2*)(p + 2);
    float2 fa = __half22float2(a), fb = __half22float2(b);
    return make_float4(fa.x, fa.y, fb.x, fb.y);
}
__device__ __forceinline__ void mma_tf32(float c[4],
    unsigned a0, unsigned a1, unsigned a2, unsigned a3,
    unsigned b0, unsigned b1)
{
    asm("mma.sync.aligned.m16n8k8.row.col.f32.tf32.tf32.f32 "
        "{%0,%1,%2,%3}, {%4,%5,%6,%7}, {%8,%9}, {%0,%1,%2,%3};"
        : "+f"(c[0]), "+f"(c[1]), "+f"(c[2]), "+f"(c[3])
        : "r"(a0), "r"(a1), "r"(a2), "r"(a3), "r"(b0), "r"(b1));
}
// fp16 MMA, K=16: A=4 regs (8 halves), B=2 regs (4 halves), C=f32 x4
__device__ __forceinline__ void mma_f16(float c[4],
    unsigned a0, unsigned a1, unsigned a2, unsigned a3,
    unsigned b0, unsigned b1)
{
    asm("mma.sync.aligned.m16n8k16.row.col.f32.f16.f16.f32 "
        "{%0,%1,%2,%3}, {%4,%5,%6,%7}, {%8,%9}, {%0,%1,%2,%3};"
        : "+f"(c[0]), "+f"(c[1]), "+f"(c[2]), "+f"(c[3])
        : "r"(a0), "r"(a1), "r"(a2), "r"(a3), "r"(b0), "r"(b1));
}

// ================= K1: in_proj GEMM via fp16 MMA =============================
// smem: sX[128][136]h + sW[64][136]h = 52224 B. stride 136h = 68 words (≡4 mod 32)
#define IP_SMEM ((128*136 + 64*136)*2)

__device__ __forceinline__ void ip_store2(int dir, const float* db, int m, int c,
                                          float v0, float v1)
{
    if (c < DI) {
        *(__half2*)&g_z[dir][m*DI + c] = __floats2half2_rn(v0, v1);
    } else if (c < DI + DX) {
        *(__half2*)&g_xbc0[dir][m*DX + (c - DI)] = __floats2half2_rn(v0, v1);
    } else if (c < DI + DX + NH) {
        int h = c - DI - DX;
        g_dt[dir][m*NH + h]     = softplusf(v0 + db[h]);
        g_dt[dir][m*NH + h + 1] = softplusf(v1 + db[h + 1]);
    }
}

__global__ __launch_bounds__(256) void k_inproj(
    const float* __restrict__ x,
    const float* __restrict__ Wi_f, const float* __restrict__ Wi_b,
    const float* __restrict__ db_f, const float* __restrict__ db_b)
{
    extern __shared__ __align__(16) char smraw[];
    __half (*sX)[136] = (__half(*)[136])smraw;
    __half (*sW)[136] = (__half(*)[136])(smraw + 128*136*2);
    int dir = blockIdx.y;
    const float* Wi = dir ? Wi_b : Wi_f;
    const float* db = dir ? db_b : db_f;
    int tid = threadIdx.x;
    int m0 = blockIdx.x * 128;
    int wid = tid >> 5, lane = tid & 31;
    int wm = wid & 1, wn = wid >> 1;
    int gid = lane >> 2, tig = lane & 3;

    #pragma unroll
    for (int it = 0; it < 16; it++) {
        int q = tid + it*256;
        int row = q >> 5, kq = (q & 31) * 4;
        int m = m0 + row;
        int xr = dir ? ((m & ~2047) + 2047 - (m & 2047)) : m;
        float4 v = *(const float4*)&x[xr*128 + kq];
        *(__half2*)&sX[row][kq]     = __floats2half2_rn(v.x, v.y);
        *(__half2*)&sX[row][kq + 2] = __floats2half2_rn(v.z, v.w);
    }

    for (int nt0 = 0; nt0 < 11; nt0++) {
        int n0 = nt0 * 64;
        __syncthreads();
        #pragma unroll
        for (int it = 0; it < 8; it++) {
            int q = tid + it*256;
            int row = q >> 5, kq = (q & 31) * 4;
            int n = n0 + row;
            float4 v = make_float4(0.f,0.f,0.f,0.f);
            if (n < NPROJ) v = *(const float4*)&Wi[n*128 + kq];
            *(__half2*)&sW[row][kq]     = __floats2half2_rn(v.x, v.y);
            *(__half2*)&sW[row][kq + 2] = __floats2half2_rn(v.z, v.w);
        }
        __syncthreads();

        float acc[4][2][4] = {};
        #pragma unroll
        for (int ks = 0; ks < 8; ks++) {
            int kb = ks*16;
            unsigned bfr[2][2];
            #pragma unroll
            for (int ni = 0; ni < 2; ni++) {
                int n = wn*16 + ni*8 + gid;
                bfr[ni][0] = *(unsigned*)&sW[n][kb + tig*2];
                bfr[ni][1] = *(unsigned*)&sW[n][kb + tig*2 + 8];
            }
            #pragma unroll
            for (int mi = 0; mi < 4; mi++) {
                int r = wm*64 + mi*16 + gid;
                unsigned a0 = *(unsigned*)&sX[r    ][kb + tig*2];
                unsigned a1 = *(unsigned*)&sX[r + 8][kb + tig*2];
                unsigned a2 = *(unsigned*)&sX[r    ][kb + tig*2 + 8];
                unsigned a3 = *(unsigned*)&sX[r + 8][kb + tig*2 + 8];
                mma_f16(acc[mi][0], a0, a1, a2, a3, bfr[0][0], bfr[0][1]);
                mma_f16(acc[mi][1], a0, a1, a2, a3, bfr[1][0], bfr[1][1]);
            }
        }
        #pragma unroll
        for (int mi = 0; mi < 4; mi++) {
            int r0 = m0 + wm*64 + mi*16 + gid;
            #pragma unroll
            for (int ni = 0; ni < 2; ni++) {
                int c = n0 + wn*16 + ni*8 + tig*2;
                ip_store2(dir, db, r0,     c, acc[mi][ni][0], acc[mi][ni][1]);
                ip_store2(dir, db, r0 + 8, c, acc[mi][ni][2], acc[mi][ni][3]);
            }
        }
    }
}

// ================= K3: fused conv+silu + diag + chunk state — 2-CTA ==========
#define CH_SMEM (19968*4)
__global__ __launch_bounds__(256, 2) void k_chunk(
    const float* __restrict__ Al_f, const float* __restrict__ Al_b,
    const float* __restrict__ cw_f, const float* __restrict__ cb_f,
    const float* __restrict__ cw_b, const float* __restrict__ cb_b,
    const float* __restrict__ D_f,  const float* __restrict__ D_b)
{
    extern __shared__ float sm[];
    float (*sB)[68]   = (float(*)[68])sm;
    float (*sCW)[68]  = (float(*)[68])(sm + 4352);
    float (*sCB)[68]  = (float(*)[68])(sm + 8704);
    float (*sXTh)[68] = (float(*)[68])(sm + 13056);
    float (*sdt)[4]   = (float(*)[4])(sm + 17408);
    float (*sAcs)[64] = (float(*)[64])(sm + 17664);
    float *sdec       = sm + 17920;
    float *sed        = sm + 17984;
    float *scw        = sm + 18048;
    float *scb        = sm + 19584;

    int c = blockIdx.x, b = blockIdx.y, dir = blockIdx.z;
    const __half* gx0 = g_xbc0[dir];
    const float* cw  = dir ? cw_b : cw_f;
    const float* cb  = dir ? cb_b : cb_f;
    const float* Dq  = dir ? D_b  : D_f;
    int tid = threadIdx.x;
    int base = b*SEQL + c*CH;
    int wid = tid >> 5, lane = tid & 31;
    int gid = lane >> 2, tig = lane & 3;
    int wm = wid & 1, wn = wid >> 1;

    for (int i = tid; i < 384*4; i += 256) scw[i] = cw[i];
    for (int i = tid; i < 384; i += 256) scb[i] = cb[i];
    { int l = tid >> 2, h = tid & 3; sdt[l][h] = g_dt[dir][base*NH + tid]; }
    __syncthreads();

    #pragma unroll
    for (int it = 0; it < 8; it++) {
        int q = tid + it*256;
        int row = q >> 5;
        int c4 = (q & 31) * 4;
        int jj = 256 + c4;
        float4 acc = *(const float4*)&scb[jj];
        #pragma unroll
        for (int k = 0; k < 4; k++) {
            int t = c*CH + row - 3 + k;
            if (t >= 0) {
                float4 v = h4tof4(&gx0[(b*SEQL + t)*DX + jj]);
                acc.x += v.x * scw[(jj+0)*4 + k];
                acc.y += v.y * scw[(jj+1)*4 + k];
                acc.z += v.z * scw[(jj+2)*4 + k];
                acc.w += v.w * scw[(jj+3)*4 + k];
            }
        }
        acc.x = siluf(acc.x); acc.y = siluf(acc.y);
        acc.z = siluf(acc.z); acc.w = siluf(acc.w);
        if (c4 < 64) {
            sB[row][c4+0] = f2tf32(acc.x); sB[row][c4+1] = f2tf32(acc.y);
            sB[row][c4+2] = f2tf32(acc.z); sB[row][c4+3] = f2tf32(acc.w);
        } else {
            int n4 = c4 - 64;
            sCW[row][n4+0] = f2tf32(acc.x); sCW[row][n4+1] = f2tf32(acc.y);
            sCW[row][n4+2] = f2tf32(acc.z); sCW[row][n4+3] = f2tf32(acc.w);
            *(__half2*)&g_C[dir][(base+row)*64 + n4]     = __floats2half2_rn(acc.x, acc.y);
            *(__half2*)&g_C[dir][(base+row)*64 + n4 + 2] = __floats2half2_rn(acc.z, acc.w);
        }
    }
    if (tid < 4) {
        float A = -__expf((dir ? Al_b : Al_f)[tid]);
        float run = 0.f;
        for (int l = 0; l < 64; l++) { run += sdt[l][tid] * A; sAcs[tid][l] = run; }
    }
    __syncthreads();

    // ---- phase 1: CB = C @ B^T -> sCB (tf32) ----
    {
        float cbf[2][2][4] = {};
        #pragma unroll
        for (int ks = 0; ks < 8; ks++) {
            int kb = ks*8;
            unsigned bfr[2][2];
            #pragma unroll
            for (int nt = 0; nt < 2; nt++) {
                int s = wn*16 + nt*8 + gid;
                bfr[nt][0] = __float_as_uint(sB[s][kb + tig]);
                bfr[nt][1] = __float_as_uint(sB[s][kb + tig + 4]);
            }
            #pragma unroll
            for (int mt = 0; mt < 2; mt++) {
                int r = wm*32 + mt*16 + gid;
                unsigned a0 = __float_as_uint(sCW[r    ][kb + tig]);
                unsigned a1 = __float_as_uint(sCW[r + 8][kb + tig]);
                unsigned a2 = __float_as_uint(sCW[r    ][kb + tig + 4]);
                unsigned a3 = __float_as_uint(sCW[r + 8][kb + tig + 4]);
                mma_tf32(cbf[mt][0], a0, a1, a2, a3, bfr[0][0], bfr[0][1]);
                mma_tf32(cbf[mt][1], a0, a1, a2, a3, bfr[1][0], bfr[1][1]);
            }
        }
        #pragma unroll
        for (int mt = 0; mt < 2; mt++) {
            #pragma unroll
            for (int half = 0; half < 2; half++) {
                int l = wm*32 + mt*16 + gid + half*8;
                #pragma unroll
                for (int nt = 0; nt < 2; nt++) {
                    int s0 = wn*16 + nt*8 + tig*2;
                    *(float2*)&sCB[l][s0] =
                        make_float2(cbf[mt][nt][half*2], cbf[mt][nt][half*2 + 1]);
                }
            }
        }
    }

    int sbase = (b*NC + c)*NH*4096;
    for (int h = 0; h < NH; h++) {
        __syncthreads();

        #pragma unroll
        for (int it = 0; it < 4; it++) {
            int q = tid + it*256;
            int s = q >> 4;
            int p4 = (q & 15) * 4;
            int jj = h*64 + p4;
            float4 acc = *(const float4*)&scb[jj];
            #pragma unroll
            for (int k = 0; k < 4; k++) {
                int t = c*CH + s - 3 + k;
                if (t >= 0) {
                    float4 v = h4tof4(&gx0[(b*SEQL + t)*DX + jj]);
                    acc.x += v.x * scw[(jj+0)*4 + k];
                    acc.y += v.y * scw[(jj+1)*4 + k];
                    acc.z += v.z * scw[(jj+2)*4 + k];
                    acc.w += v.w * scw[(jj+3)*4 + k];
                }
            }
            float dtv = sdt[s][h];
            sXTh[p4+0][s] = f2tf32(siluf(acc.x) * dtv);
            sXTh[p4+1][s] = f2tf32(siluf(acc.y) * dtv);
            sXTh[p4+2][s] = f2tf32(siluf(acc.z) * dtv);
            sXTh[p4+3][s] = f2tf32(siluf(acc.w) * dtv);
        }
        if (tid < 64) {
            sdec[tid] = __expf(sAcs[h][63] - sAcs[h][tid]);
            if (tid >= 1) sed[tid] = __expf(sAcs[h][tid] - sAcs[h][tid - 1]);
        }
        __syncthreads();

        {
            int lrow = tid >> 2, part = tid & 3;
            int s_lo = part * 16;
            if (s_lo > lrow) {
                #pragma unroll
                for (int k = 0; k < 16; k++) sCW[lrow][s_lo + k] = 0.f;
            } else {
                int shi = s_lo + 15;
                int s1 = shi < lrow ? shi : lrow;
                for (int s = shi; s > s1; s--) sCW[lrow][s] = 0.f;
                float r = __expf(sAcs[h][lrow] - sAcs[h][s1]);
                float dfold = __fdividef(Dq[h], sdt[lrow][h]);
                for (int s = s1; s >= s_lo; s--) {
                    float v = sCB[lrow][s];
                    if (s == lrow) v += dfold;
                    sCW[lrow][s] = f2tf32(v * r);
                    if (s > s_lo) r *= sed[s];
                }
            }
        }
        __syncthreads();

        // ---- phase 2: Ydiag+D*xs -> g_yd (fp16) ----
        {
            float f2[2][2][4] = {};
            #pragma unroll
            for (int ks = 0; ks < 8; ks++) {
                int kb = ks*8;
                unsigned bfr[2][2];
                #pragma unroll
                for (int nt = 0; nt < 2; nt++) {
                    int p = wn*16 + nt*8 + gid;
                    bfr[nt][0] = __float_as_uint(sXTh[p][kb + tig]);
                    bfr[nt][1] = __float_as_uint(sXTh[p][kb + tig + 4]);
                }
                #pragma unroll
                for (int mt = 0; mt < 2; mt++) {
                    int r = wm*32 + mt*16 + gid;
                    unsigned a0 = __float_as_uint(sCW[r    ][kb + tig]);
                    unsigned a1 = __float_as_uint(sCW[r + 8][kb + tig]);
                    unsigned a2 = __float_as_uint(sCW[r    ][kb + tig + 4]);
                    unsigned a3 = __float_as_uint(sCW[r + 8][kb + tig + 4]);
                    mma_tf32(f2[mt][0], a0, a1, a2, a3, bfr[0][0], bfr[0][1]);
                    mma_tf32(f2[mt][1], a0, a1, a2, a3, bfr[1][0], bfr[1][1]);
                }
            }
            #pragma unroll
            for (int mt = 0; mt < 2; mt++) {
                #pragma unroll
                for (int half = 0; half < 2; half++) {
                    int l = wm*32 + mt*16 + gid + half*8;
                    #pragma unroll
                    for (int nt = 0; nt < 2; nt++) {
                        int p = wn*16 + nt*8 + tig*2;
                        *(__half2*)&g_yd[dir][(base + l)*DI + h*64 + p] =
                            __floats2half2_rn(f2[mt][nt][half*2], f2[mt][nt][half*2 + 1]);
                    }
                }
            }
        }

        // ---- phase 3 ----
        {
            float f3[2][2][4] = {};
            #pragma unroll
            for (int ks = 0; ks < 8; ks++) {
                int kb = ks*8;
                float d0 = sdec[kb + tig], d1 = sdec[kb + tig + 4];
                unsigned bfr[2][2];
                #pragma unroll
                for (int nt = 0; nt < 2; nt++) {
                    int n = wn*16 + nt*8 + gid;
                    bfr[nt][0] = __float_as_uint(sB[kb + tig    ][n]);
                    bfr[nt][1] = __float_as_uint(sB[kb + tig + 4][n]);
                }
                #pragma unroll
                for (int mt = 0; mt < 2; mt++) {
                    int r = wm*32 + mt*16 + gid;
                    unsigned a0 = __float_as_uint(f2tf32(sXTh[r    ][kb + tig]     * d0));
                    unsigned a1 = __float_as_uint(f2tf32(sXTh[r + 8][kb + tig]     * d0));
                    unsigned a2 = __float_as_uint(f2tf32(sXTh[r    ][kb + tig + 4] * d1));
                    unsigned a3 = __float_as_uint(f2tf32(sXTh[r + 8][kb + tig + 4] * d1));
                    mma_tf32(f3[mt][0], a0, a1, a2, a3, bfr[0][0], bfr[0][1]);
                    mma_tf32(f3[mt][1], a0, a1, a2, a3, bfr[1][0], bfr[1][1]);
                }
            }
            #pragma unroll
            for (int mt = 0; mt < 2; mt++) {
                #pragma unroll
                for (int half = 0; half < 2; half++) {
                    int p = wm*32 + mt*16 + gid + half*8;
                    #pragma unroll
                    for (int nt = 0; nt < 2; nt++) {
                        int n = wn*16 + nt*8 + tig*2;
                        *(float2*)&g_st[dir][sbase + h*4096 + p*64 + n] =
                            make_float2(f3[mt][nt][half*2], f3[mt][nt][half*2 + 1]);
                    }
                }
            }
        }
        if (tid == 0) g_cd[dir][(b*NH + h)*NC + c] = __expf(sAcs[h][63]);
    }
}

// ================= K4: inter-chunk scan ======================================
__global__ __launch_bounds__(256) void k_scan()
{
    int grp = blockIdx.x;
    int bh  = blockIdx.y;
    int dir = blockIdx.z;
    int h = bh & 3, b = bh >> 2;
    int tid = threadIdx.x;
    int e0 = grp*1024 + tid*4;

    float cd[NC];
    #pragma unroll
    for (int c = 0; c < NC; c++) cd[c] = g_cd[dir][(b*NH + h)*NC + c];

    float* p = &g_st[dir][(b*NC*NH + h)*4096 + e0];
    const int cstride = NH*4096;

    float4 carry = make_float4(0.f, 0.f, 0.f, 0.f);
    float4 nxt = *(float4*)p;
    #pragma unroll
    for (int c = 0; c < NC; c++) {
        float4 cur = nxt;
        if (c + 1 < NC) nxt = *(float4*)(p + (c+1)*cstride);
        *(float4*)(p + c*cstride) = carry;
        float d = cd[c];
        carry.x = carry.x*d + cur.x;
        carry.y = carry.y*d + cur.y;
        carry.z = carry.z*d + cur.z;
        carry.w = carry.w*d + cur.w;
    }
}

// ================= K5: off-diag + epilogue + out_proj via fp16 MMA ===========
// smem: region1 [0,18432h): sPrev[256][72]h then sY[64][264]h (16896h)
//       region2 [18432h,27648h): sC[64][72]h then sWo[128][72]h
//       floats at 27648h: sdt 256 | sAcs 256 | sE 256  => total 58368 B
#define OUT_SMEM (27648*2 + 768*4)
__global__ __launch_bounds__(256, 2) void k_out(
    const float* __restrict__ Al_f, const float* __restrict__ Al_b,
    const float* __restrict__ nw_f, const float* __restrict__ nw_b,
    const float* __restrict__ Wo_f, const float* __restrict__ Wo_b,
    float* __restrict__ out)
{
    extern __shared__ __align__(16) char smraw[];
    __half (*sPrev)[72] = (__half(*)[72])smraw;
    __half (*sY)[264]   = (__half(*)[264])smraw;          // alias over sPrev
    __half (*sC)[72]    = (__half(*)[72])(smraw + 18432*2);
    __half (*sWo)[72]   = (__half(*)[72])(smraw + 18432*2); // alias over sC
    float* smf = (float*)(smraw + 27648*2);
    float (*sdt)[4]   = (float(*)[4])smf;
    float (*sAcs)[64] = (float(*)[64])(smf + 256);
    float (*sE)[64]   = (float(*)[64])(smf + 512);

    int c = blockIdx.x, b = blockIdx.y;
    int tid = threadIdx.x;
    int wid = tid >> 5, lane = tid & 31;
    int gid = lane >> 2, tig = lane & 3;

    float oacc[8][4] = {};

    for (int d = 0; d < 2; d++) {
        int cc = d ? (NC - 1 - c) : c;
        int base = b*SEQL + cc*CH;
        const float* Alog = d ? Al_b : Al_f;
        const float* nw   = d ? nw_b : nw_f;
        const float* Wo   = d ? Wo_b : Wo_f;

        __syncthreads();
        { int l = tid >> 2, h = tid & 3; sdt[l][h] = g_dt[d][base*NH + tid]; }
        __syncthreads();
        if (tid < 4) {
            float A = -__expf(Alog[tid]);
            float run = 0.f;
            for (int l = 0; l < 64; l++) { run += sdt[l][tid] * A; sAcs[tid][l] = run; }
        }
        __syncthreads();
        { int h = tid >> 6, l = tid & 63; sE[h][l] = __expf(sAcs[h][l]); }
        // sC: direct fp16 copy from g_C
        #pragma unroll
        for (int it = 0; it < 4; it++) {
            int q = tid + it*256;
            int row = q >> 4, nq = (q & 15) * 4;
            uint2 v = *(const uint2*)&g_C[d][(base+row)*64 + nq];
            *(uint2*)&sC[row][nq] = v;
        }
        // sPrev: fp32 g_st -> fp16
        {
            int pbase = (b*NC + cc)*NH*4096;
            #pragma unroll
            for (int it = 0; it < 16; it++) {
                int q = tid + it*256;
                int row = q >> 4, nq = (q & 15) * 4;
                float4 v = *(const float4*)&g_st[d][pbase + row*64 + nq];
                *(__half2*)&sPrev[row][nq]     = __floats2half2_rn(v.x, v.y);
                *(__half2*)&sPrev[row][nq + 2] = __floats2half2_rn(v.z, v.w);
            }
        }
        __syncthreads();

        // ---- off-diag MMAs (fp16, K=64 in 4 k16-steps) ----
        float facc[4][4][4];
        {
            int wn = wid;
            #pragma unroll
            for (int mt = 0; mt < 4; mt++)
                #pragma unroll
                for (int nt = 0; nt < 4; nt++)
                    #pragma unroll
                    for (int k = 0; k < 4; k++) facc[mt][nt][k] = 0.f;
            #pragma unroll
            for (int ks = 0; ks < 4; ks++) {
                int kb = ks*16;
                unsigned bf[4][2];
                #pragma unroll
                for (int nt = 0; nt < 4; nt++) {
                    int r = wn*32 + nt*8 + gid;
                    bf[nt][0] = *(unsigned*)&sPrev[r][kb + tig*2];
                    bf[nt][1] = *(unsigned*)&sPrev[r][kb + tig*2 + 8];
                }
                #pragma unroll
                for (int mt = 0; mt < 4; mt++) {
                    int r = mt*16 + gid;
                    unsigned a0 = *(unsigned*)&sC[r    ][kb + tig*2];
                    unsigned a1 = *(unsigned*)&sC[r + 8][kb + tig*2];
                    unsigned a2 = *(unsigned*)&sC[r    ][kb + tig*2 + 8];
                    unsigned a3 = *(unsigned*)&sC[r + 8][kb + tig*2 + 8];
                    #pragma unroll
                    for (int nt = 0; nt < 4; nt++)
                        mma_f16(facc[mt][nt], a0, a1, a2, a3, bf[nt][0], bf[nt][1]);
                }
            }
        }
        __syncthreads();   // sPrev/sC reads done — sY may overwrite region1

        // ---- epilogue: combine + gate -> sY (fp16, l-flip for d=1) ----
        {
            int wn = wid;
            #pragma unroll
            for (int mt = 0; mt < 4; mt++) {
                #pragma unroll
                for (int nt = 0; nt < 4; nt++) {
                    int q = wn*32 + nt*8 + tig*2;
                    int h = q >> 6;
                    #pragma unroll
                    for (int half = 0; half < 2; half++) {
                        int l = mt*16 + gid + half*8;
                        int row = base + l;
                        float e = sE[h][l];
                        float2 yd = __half22float2(*(const __half2*)&g_yd[d][row*DI + q]);
                        float2 z2 = __half22float2(*(const __half2*)&g_z[d][row*DI + q]);
                        float v0 = facc[mt][nt][half*2 + 0];
                        float v1 = facc[mt][nt][half*2 + 1];
                        float y0 = (yd.x + e*v0) * siluf(z2.x);
                        float y1 = (yd.y + e*v1) * siluf(z2.y);
                        int srow = d ? (63 - l) : l;
                        *(__half2*)&sY[srow][q] = __floats2half2_rn(y0, y1);
                    }
                }
            }
        }
        __syncthreads();

        // ---- RMS norm per row (4 threads/row) on fp16 sY ----
        {
            int lr = tid >> 2, part = tid & 3;
            float s = 0.f;
            #pragma unroll
            for (int q = 0; q < 16; q++) {
                int col = part*64 + q*4;
                float2 f0 = __half22float2(*(__half2*)&sY[lr][col]);
                float2 f1 = __half22float2(*(__half2*)&sY[lr][col + 2]);
                s += f0.x*f0.x + f0.y*f0.y + f1.x*f1.x + f1.y*f1.y;
            }
            s += __shfl_xor_sync(0xffffffff, s, 1);
            s += __shfl_xor_sync(0xffffffff, s, 2);
            float scale = rsqrtf(s * (1.f/256.f) + 1e-5f);
            #pragma unroll
            for (int q = 0; q < 16; q++) {
                int col = part*64 + q*4;
                float4 w = *(const float4*)&nw[col];
                float2 f0 = __half22float2(*(__half2*)&sY[lr][col]);
                float2 f1 = __half22float2(*(__half2*)&sY[lr][col + 2]);
                *(__half2*)&sY[lr][col]     = __floats2half2_rn(f0.x*scale*w.x, f0.y*scale*w.y);
                *(__half2*)&sY[lr][col + 2] = __floats2half2_rn(f1.x*scale*w.z, f1.y*scale*w.w);
            }
        }
        __syncthreads();

        // ---- out_proj (fp16): sWo x sY; oacc persists across jc and dirs ----
        {
            int wm = wid & 3, wn2 = wid >> 2;
            for (int jc = 0; jc < 4; jc++) {
                #pragma unroll
                for (int it = 0; it < 8; it++) {
                    int q = tid + it*256;
                    int row = q >> 4, jq = (q & 15) * 4;
                    float4 v = *(const float4*)&Wo[row*256 + jc*64 + jq];
                    *(__half2*)&sWo[row][jq]     = __floats2half2_rn(v.x, v.y);
                    *(__half2*)&sWo[row][jq + 2] = __floats2half2_rn(v.z, v.w);
                }
                __syncthreads();
                #pragma unroll
                for (int ks = 0; ks < 4; ks++) {
                    int kb = ks*16;
                    int ar = wm*16 + gid;
                    unsigned a0 = *(unsigned*)&sY[ar    ][jc*64 + kb + tig*2];
                    unsigned a1 = *(unsigned*)&sY[ar + 8][jc*64 + kb + tig*2];
                    unsigned a2 = *(unsigned*)&sY[ar    ][jc*64 + kb + tig*2 + 8];
                    unsigned a3 = *(unsigned*)&sY[ar + 8][jc*64 + kb + tig*2 + 8];
                    #pragma unroll
                    for (int nt = 0; nt < 8; nt++) {
                        int r = wn2*64 + nt*8 + gid;
                        unsigned b0 = *(unsigned*)&sWo[r][kb + tig*2];
                        unsigned b1 = *(unsigned*)&sWo[r][kb + tig*2 + 8];
                        mma_f16(oacc[nt], a0, a1, a2, a3, b0, b1);
                    }
                }
                __syncthreads();
            }
        }
    }

    // ---- final store ----
    {
        int wm = wid & 3, wn2 = wid >> 2;
        #pragma unroll
        for (int nt = 0; nt < 8; nt++) {
            int kout = wn2*64 + nt*8 + tig*2;
            #pragma unroll
            for (int half = 0; half < 2; half++) {
                int r = wm*16 + gid + half*8;
                int t = c*CH + r;
                *(float2*)&out[(b*SEQL + t)*DM + kout] =
                    make_float2(oacc[nt][half*2], oacc[nt][half*2 + 1]);
            }
        }
    }
}

extern "C" void kernel_launch(void* const* d_in, const int* in_sizes, int n_in,
                              void* d_out, int out_size)
{
    const float* x    = (const float*)d_in[0];
    const float* Wi_f = (const float*)d_in[1];
    const float* cw_f = (const float*)d_in[2];
    const float* cb_f = (const float*)d_in[3];
    const float* db_f = (const float*)d_in[4];
    const float* Al_f = (const float*)d_in[5];
    const float* D_f  = (const float*)d_in[6];
    const float* nw_f = (const float*)d_in[7];
    const float* Wo_f = (const float*)d_in[8];
    const float* Wi_b = (const float*)d_in[9];
    const float* cw_b = (const float*)d_in[10];
    const float* cb_b = (const float*)d_in[11];
    const float* db_b = (const float*)d_in[12];
    const float* Al_b = (const float*)d_in[13];
    const float* D_b  = (const float*)d_in[14];
    const float* nw_b = (const float*)d_in[15];
    const float* Wo_b = (const float*)d_in[16];
    float* out = (float*)d_out;

    cudaFuncSetAttribute(k_inproj, cudaFuncAttributeMaxDynamicSharedMemorySize, IP_SMEM);
    cudaFuncSetAttribute(k_chunk,  cudaFuncAttributeMaxDynamicSharedMemorySize, CH_SMEM);
    cudaFuncSetAttribute(k_out,    cudaFuncAttributeMaxDynamicSharedMemorySize, OUT_SMEM);

    dim3 g1(BL/128, 2);
    k_inproj<<<g1, 256, IP_SMEM>>>(x, Wi_f, Wi_b, db_f, db_b);

    dim3 g3(NC, BATCH, 2);
    k_chunk<<<g3, 256, CH_SMEM>>>(Al_f, Al_b, cw_f, cb_f, cw_b, cb_b, D_f, D_b);

    dim3 g4(4, BATCH*NH, 2);
    k_scan<<<g4, 256>>>();

    dim3 g5(NC, BATCH);
    k_out<<<g5, 256, OUT_SMEM>>>(Al_f, Al_b, nw_f, nw_b, Wo_f, Wo_b, out);
}

// round 16
// speedup vs baseline: 1.5420x; 1.0236x over previous
#include <cuda_runtime.h>
#include <cuda_fp16.h>
#include <math.h>

#define BATCH 16
#define SEQL  2048
#define BL    (BATCH*SEQL)      // 32768
#define DM    128
#define DI    256
#define DX    384
#define NH    4
#define HD    64
#define DS    64
#define CH    64
#define NC    32
#define NPROJ 644

// ---------------- scratch ----------------------------------------------------
__device__ __half g_z[2][BL*DI];        // fp16
__device__ __half g_xbc0[2][BL*DX];     // fp16 pre-conv xBC
__device__ __half g_C[2][BL*DS];        // fp16 post-conv C
__device__ float  g_dt[2][BL*NH];
__device__ float  g_st[2][BATCH*NC*NH*HD*DS];  // fp32 (scan precision)
__device__ __half g_yd[2][BL*DI];       // fp16 Ydiag + D*xs
__device__ float  g_cd[2][BATCH*NH*NC];

__device__ __forceinline__ float softplusf(float x){ return x > 20.f ? x : log1pf(__expf(x)); }
__device__ __forceinline__ float siluf(float x){ return x / (1.f + __expf(-x)); }
__device__ __forceinline__ float4 h4tof4(const __half* p){
    __half2 a = *(const __half2*)p;
    __half2 b = *(const __half2*)(p + 2);
    float2 fa = __half22float2(a), fb = __half22float2(b);
    return make_float4(fa.x, fa.y, fb.x, fb.y);
}
// fp16 MMA, K=16: A=4 regs (8 halves), B=2 regs (4 halves), C=f32 x4
__device__ __forceinline__ void mma_f16(float c[4],
    unsigned a0, unsigned a1, unsigned a2, unsigned a3,
    unsigned b0, unsigned b1)
{
    asm("mma.sync.aligned.m16n8k16.row.col.f32.f16.f16.f32 "
        "{%0,%1,%2,%3}, {%4,%5,%6,%7}, {%8,%9}, {%0,%1,%2,%3};"
        : "+f"(c[0]), "+f"(c[1]), "+f"(c[2]), "+f"(c[3])
        : "r"(a0), "r"(a1), "r"(a2), "r"(a3), "r"(b0), "r"(b1));
}

// ================= K1: in_proj GEMM via fp16 MMA =============================
#define IP_SMEM ((128*136 + 64*136)*2)

__device__ __forceinline__ void ip_store2(int dir, const float* db, int m, int c,
                                          float v0, float v1)
{
    if (c < DI) {
        *(__half2*)&g_z[dir][m*DI + c] = __floats2half2_rn(v0, v1);
    } else if (c < DI + DX) {
        *(__half2*)&g_xbc0[dir][m*DX + (c - DI)] = __floats2half2_rn(v0, v1);
    } else if (c < DI + DX + NH) {
        int h = c - DI - DX;
        g_dt[dir][m*NH + h]     = softplusf(v0 + db[h]);
        g_dt[dir][m*NH + h + 1] = softplusf(v1 + db[h + 1]);
    }
}

__global__ __launch_bounds__(256) void k_inproj(
    const float* __restrict__ x,
    const float* __restrict__ Wi_f, const float* __restrict__ Wi_b,
    const float* __restrict__ db_f, const float* __restrict__ db_b)
{
    extern __shared__ __align__(16) char smraw[];
    __half (*sX)[136] = (__half(*)[136])smraw;
    __half (*sW)[136] = (__half(*)[136])(smraw + 128*136*2);
    int dir = blockIdx.y;
    const float* Wi = dir ? Wi_b : Wi_f;
    const float* db = dir ? db_b : db_f;
    int tid = threadIdx.x;
    int m0 = blockIdx.x * 128;
    int wid = tid >> 5, lane = tid & 31;
    int wm = wid & 1, wn = wid >> 1;
    int gid = lane >> 2, tig = lane & 3;

    #pragma unroll
    for (int it = 0; it < 16; it++) {
        int q = tid + it*256;
        int row = q >> 5, kq = (q & 31) * 4;
        int m = m0 + row;
        int xr = dir ? ((m & ~2047) + 2047 - (m & 2047)) : m;
        float4 v = *(const float4*)&x[xr*128 + kq];
        *(__half2*)&sX[row][kq]     = __floats2half2_rn(v.x, v.y);
        *(__half2*)&sX[row][kq + 2] = __floats2half2_rn(v.z, v.w);
    }

    for (int nt0 = 0; nt0 < 11; nt0++) {
        int n0 = nt0 * 64;
        __syncthreads();
        #pragma unroll
        for (int it = 0; it < 8; it++) {
            int q = tid + it*256;
            int row = q >> 5, kq = (q & 31) * 4;
            int n = n0 + row;
            float4 v = make_float4(0.f,0.f,0.f,0.f);
            if (n < NPROJ) v = *(const float4*)&Wi[n*128 + kq];
            *(__half2*)&sW[row][kq]     = __floats2half2_rn(v.x, v.y);
            *(__half2*)&sW[row][kq + 2] = __floats2half2_rn(v.z, v.w);
        }
        __syncthreads();

        float acc[4][2][4] = {};
        #pragma unroll
        for (int ks = 0; ks < 8; ks++) {
            int kb = ks*16;
            unsigned bfr[2][2];
            #pragma unroll
            for (int ni = 0; ni < 2; ni++) {
                int n = wn*16 + ni*8 + gid;
                bfr[ni][0] = *(unsigned*)&sW[n][kb + tig*2];
                bfr[ni][1] = *(unsigned*)&sW[n][kb + tig*2 + 8];
            }
            #pragma unroll
            for (int mi = 0; mi < 4; mi++) {
                int r = wm*64 + mi*16 + gid;
                unsigned a0 = *(unsigned*)&sX[r    ][kb + tig*2];
                unsigned a1 = *(unsigned*)&sX[r + 8][kb + tig*2];
                unsigned a2 = *(unsigned*)&sX[r    ][kb + tig*2 + 8];
                unsigned a3 = *(unsigned*)&sX[r + 8][kb + tig*2 + 8];
                mma_f16(acc[mi][0], a0, a1, a2, a3, bfr[0][0], bfr[0][1]);
                mma_f16(acc[mi][1], a0, a1, a2, a3, bfr[1][0], bfr[1][1]);
            }
        }
        #pragma unroll
        for (int mi = 0; mi < 4; mi++) {
            int r0 = m0 + wm*64 + mi*16 + gid;
            #pragma unroll
            for (int ni = 0; ni < 2; ni++) {
                int c = n0 + wn*16 + ni*8 + tig*2;
                ip_store2(dir, db, r0,     c, acc[mi][ni][0], acc[mi][ni][1]);
                ip_store2(dir, db, r0 + 8, c, acc[mi][ni][2], acc[mi][ni][3]);
            }
        }
    }
}

// ================= K3: conv+silu + diag + chunk state — fp16 MMA, 2-CTA ======
// halves (stride 72): sB 0 | sCW 4608 | sCB 9216 | sXTh 13824 | sBd 18432
// floats at 46080 B: sdt 256 | sAcs 256 | sdec 64 | sed 64 | scw 1536 | scb 384
#define CH_SMEM (46080 + 2560*4)
__global__ __launch_bounds__(256, 2) void k_chunk(
    const float* __restrict__ Al_f, const float* __restrict__ Al_b,
    const float* __restrict__ cw_f, const float* __restrict__ cb_f,
    const float* __restrict__ cw_b, const float* __restrict__ cb_b,
    const float* __restrict__ D_f,  const float* __restrict__ D_b)
{
    extern __shared__ __align__(16) char smraw[];
    __half (*sB)[72]   = (__half(*)[72])smraw;               // [s][n]
    __half (*sCW)[72]  = (__half(*)[72])(smraw + 4608*2);    // C [l][n] then W [l][s]
    __half (*sCB)[72]  = (__half(*)[72])(smraw + 9216*2);    // [l][s]
    __half (*sXTh)[72] = (__half(*)[72])(smraw + 13824*2);   // [p][s]
    __half (*sBd)[72]  = (__half(*)[72])(smraw + 18432*2);   // [n][l] dec-scaled
    float* smf = (float*)(smraw + 46080);
    float (*sdt)[4]   = (float(*)[4])smf;
    float (*sAcs)[64] = (float(*)[64])(smf + 256);
    float *sdec       = smf + 512;
    float *sed        = smf + 576;
    float *scw        = smf + 640;
    float *scb        = smf + 2176;

    int c = blockIdx.x, b = blockIdx.y, dir = blockIdx.z;
    const __half* gx0 = g_xbc0[dir];
    const float* cw  = dir ? cw_b : cw_f;
    const float* cb  = dir ? cb_b : cb_f;
    const float* Dq  = dir ? D_b  : D_f;
    int tid = threadIdx.x;
    int base = b*SEQL + c*CH;
    int wid = tid >> 5, lane = tid & 31;
    int gid = lane >> 2, tig = lane & 3;
    int wm = wid & 1, wn = wid >> 1;

    for (int i = tid; i < 384*4; i += 256) scw[i] = cw[i];
    for (int i = tid; i < 384; i += 256) scb[i] = cb[i];
    { int l = tid >> 2, h = tid & 3; sdt[l][h] = g_dt[dir][base*NH + tid]; }
    __syncthreads();

    // ---- conv+silu staging: B/C columns (xbc idx 256..383), fp16 ----
    #pragma unroll
    for (int it = 0; it < 8; it++) {
        int q = tid + it*256;
        int row = q >> 5;
        int c4 = (q & 31) * 4;
        int jj = 256 + c4;
        float4 acc = *(const float4*)&scb[jj];
        #pragma unroll
        for (int k = 0; k < 4; k++) {
            int t = c*CH + row - 3 + k;
            if (t >= 0) {
                float4 v = h4tof4(&gx0[(b*SEQL + t)*DX + jj]);
                acc.x += v.x * scw[(jj+0)*4 + k];
                acc.y += v.y * scw[(jj+1)*4 + k];
                acc.z += v.z * scw[(jj+2)*4 + k];
                acc.w += v.w * scw[(jj+3)*4 + k];
            }
        }
        acc.x = siluf(acc.x); acc.y = siluf(acc.y);
        acc.z = siluf(acc.z); acc.w = siluf(acc.w);
        if (c4 < 64) {
            *(__half2*)&sB[row][c4]     = __floats2half2_rn(acc.x, acc.y);
            *(__half2*)&sB[row][c4 + 2] = __floats2half2_rn(acc.z, acc.w);
        } else {
            int n4 = c4 - 64;
            __half2 h0 = __floats2half2_rn(acc.x, acc.y);
            __half2 h1 = __floats2half2_rn(acc.z, acc.w);
            *(__half2*)&sCW[row][n4]     = h0;
            *(__half2*)&sCW[row][n4 + 2] = h1;
            *(__half2*)&g_C[dir][(base+row)*64 + n4]     = h0;
            *(__half2*)&g_C[dir][(base+row)*64 + n4 + 2] = h1;
        }
    }
    if (tid < 4) {
        float A = -__expf((dir ? Al_b : Al_f)[tid]);
        float run = 0.f;
        for (int l = 0; l < 64; l++) { run += sdt[l][tid] * A; sAcs[tid][l] = run; }
    }
    __syncthreads();

    // ---- phase 1: CB = C @ B^T -> sCB (fp16 MMA over K=64 = 4 k16 steps) ----
    {
        float cbf[2][2][4] = {};
        #pragma unroll
        for (int ks = 0; ks < 4; ks++) {
            int kb = ks*16;
            unsigned bfr[2][2];
            #pragma unroll
            for (int nt = 0; nt < 2; nt++) {
                int s = wn*16 + nt*8 + gid;
                bfr[nt][0] = *(unsigned*)&sB[s][kb + tig*2];
                bfr[nt][1] = *(unsigned*)&sB[s][kb + tig*2 + 8];
            }
            #pragma unroll
            for (int mt = 0; mt < 2; mt++) {
                int r = wm*32 + mt*16 + gid;
                unsigned a0 = *(unsigned*)&sCW[r    ][kb + tig*2];
                unsigned a1 = *(unsigned*)&sCW[r + 8][kb + tig*2];
                unsigned a2 = *(unsigned*)&sCW[r    ][kb + tig*2 + 8];
                unsigned a3 = *(unsigned*)&sCW[r + 8][kb + tig*2 + 8];
                mma_f16(cbf[mt][0], a0, a1, a2, a3, bfr[0][0], bfr[0][1]);
                mma_f16(cbf[mt][1], a0, a1, a2, a3, bfr[1][0], bfr[1][1]);
            }
        }
        #pragma unroll
        for (int mt = 0; mt < 2; mt++) {
            #pragma unroll
            for (int half = 0; half < 2; half++) {
                int l = wm*32 + mt*16 + gid + half*8;
                #pragma unroll
                for (int nt = 0; nt < 2; nt++) {
                    int s0 = wn*16 + nt*8 + tig*2;
                    *(__half2*)&sCB[l][s0] =
                        __floats2half2_rn(cbf[mt][nt][half*2], cbf[mt][nt][half*2 + 1]);
                }
            }
        }
    }

    int sbase = (b*NC + c)*NH*4096;
    for (int h = 0; h < NH; h++) {
        __syncthreads();   // phase1/prev-head reads of sCW/sXTh/sBd done

        // ---- per-head conv+silu staging of X columns h*64..h*64+63 (fp16) ----
        #pragma unroll
        for (int it = 0; it < 4; it++) {
            int q = tid + it*256;
            int s = q >> 4;
            int p4 = (q & 15) * 4;
            int jj = h*64 + p4;
            float4 acc = *(const float4*)&scb[jj];
            #pragma unroll
            for (int k = 0; k < 4; k++) {
                int t = c*CH + s - 3 + k;
                if (t >= 0) {
                    float4 v = h4tof4(&gx0[(b*SEQL + t)*DX + jj]);
                    acc.x += v.x * scw[(jj+0)*4 + k];
                    acc.y += v.y * scw[(jj+1)*4 + k];
                    acc.z += v.z * scw[(jj+2)*4 + k];
                    acc.w += v.w * scw[(jj+3)*4 + k];
                }
            }
            float dtv = sdt[s][h];
            sXTh[p4+0][s] = __float2half(siluf(acc.x) * dtv);
            sXTh[p4+1][s] = __float2half(siluf(acc.y) * dtv);
            sXTh[p4+2][s] = __float2half(siluf(acc.z) * dtv);
            sXTh[p4+3][s] = __float2half(siluf(acc.w) * dtv);
        }
        if (tid < 64) {
            sdec[tid] = __expf(sAcs[h][63] - sAcs[h][tid]);
            if (tid >= 1) sed[tid] = __expf(sAcs[h][tid] - sAcs[h][tid - 1]);
        }
        __syncthreads();

        // ---- build W[l][s] (fp16) via row scan; fold D/dt into diagonal ----
        {
            int lrow = tid >> 2, part = tid & 3;
            int s_lo = part * 16;
            if (s_lo > lrow) {
                #pragma unroll
                for (int k = 0; k < 16; k++) sCW[lrow][s_lo + k] = __float2half(0.f);
            } else {
                int shi = s_lo + 15;
                int s1 = shi < lrow ? shi : lrow;
                for (int s = shi; s > s1; s--) sCW[lrow][s] = __float2half(0.f);
                float r = __expf(sAcs[h][lrow] - sAcs[h][s1]);
                float dfold = __fdividef(Dq[h], sdt[lrow][h]);
                for (int s = s1; s >= s_lo; s--) {
                    float v = __half2float(sCB[lrow][s]);
                    if (s == lrow) v += dfold;
                    sCW[lrow][s] = __float2half(v * r);
                    if (s > s_lo) r *= sed[s];
                }
            }
        }
        // ---- build sBd[n][l] = dec[l]*B[l][n] (fp16) ----
        #pragma unroll
        for (int it = 0; it < 16; it++) {
            int q = tid + it*256;
            int n = q >> 6, l = q & 63;
            sBd[n][l] = __float2half(sdec[l] * __half2float(sB[l][n]));
        }
        __syncthreads();

        // ---- phase 2: Ydiag+D*xs: W @ XTh^T -> g_yd (fp16 MMA) ----
        {
            float f2[2][2][4] = {};
            #pragma unroll
            for (int ks = 0; ks < 4; ks++) {
                int kb = ks*16;
                unsigned bfr[2][2];
                #pragma unroll
                for (int nt = 0; nt < 2; nt++) {
                    int p = wn*16 + nt*8 + gid;
                    bfr[nt][0] = *(unsigned*)&sXTh[p][kb + tig*2];
                    bfr[nt][1] = *(unsigned*)&sXTh[p][kb + tig*2 + 8];
                }
                #pragma unroll
                for (int mt = 0; mt < 2; mt++) {
                    int r = wm*32 + mt*16 + gid;
                    unsigned a0 = *(unsigned*)&sCW[r    ][kb + tig*2];
                    unsigned a1 = *(unsigned*)&sCW[r + 8][kb + tig*2];
                    unsigned a2 = *(unsigned*)&sCW[r    ][kb + tig*2 + 8];
                    unsigned a3 = *(unsigned*)&sCW[r + 8][kb + tig*2 + 8];
                    mma_f16(f2[mt][0], a0, a1, a2, a3, bfr[0][0], bfr[0][1]);
                    mma_f16(f2[mt][1], a0, a1, a2, a3, bfr[1][0], bfr[1][1]);
                }
            }
            #pragma unroll
            for (int mt = 0; mt < 2; mt++) {
                #pragma unroll
                for (int half = 0; half < 2; half++) {
                    int l = wm*32 + mt*16 + gid + half*8;
                    #pragma unroll
                    for (int nt = 0; nt < 2; nt++) {
                        int p = wn*16 + nt*8 + tig*2;
                        *(__half2*)&g_yd[dir][(base + l)*DI + h*64 + p] =
                            __floats2half2_rn(f2[mt][nt][half*2], f2[mt][nt][half*2 + 1]);
                    }
                }
            }
        }

        // ---- phase 3: st[p][n] = XTh @ sBd^T (fp16 MMA, dec pre-folded) ----
        {
            float f3[2][2][4] = {};
            #pragma unroll
            for (int ks = 0; ks < 4; ks++) {
                int kb = ks*16;
                unsigned bfr[2][2];
                #pragma unroll
                for (int nt = 0; nt < 2; nt++) {
                    int n = wn*16 + nt*8 + gid;
                    bfr[nt][0] = *(unsigned*)&sBd[n][kb + tig*2];
                    bfr[nt][1] = *(unsigned*)&sBd[n][kb + tig*2 + 8];
                }
                #pragma unroll
                for (int mt = 0; mt < 2; mt++) {
                    int r = wm*32 + mt*16 + gid;
                    unsigned a0 = *(unsigned*)&sXTh[r    ][kb + tig*2];
                    unsigned a1 = *(unsigned*)&sXTh[r + 8][kb + tig*2];
                    unsigned a2 = *(unsigned*)&sXTh[r    ][kb + tig*2 + 8];
                    unsigned a3 = *(unsigned*)&sXTh[r + 8][kb + tig*2 + 8];
                    mma_f16(f3[mt][0], a0, a1, a2, a3, bfr[0][0], bfr[0][1]);
                    mma_f16(f3[mt][1], a0, a1, a2, a3, bfr[1][0], bfr[1][1]);
                }
            }
            #pragma unroll
            for (int mt = 0; mt < 2; mt++) {
                #pragma unroll
                for (int half = 0; half < 2; half++) {
                    int p = wm*32 + mt*16 + gid + half*8;
                    #pragma unroll
                    for (int nt = 0; nt < 2; nt++) {
                        int n = wn*16 + nt*8 + tig*2;
                        *(float2*)&g_st[dir][sbase + h*4096 + p*64 + n] =
                            make_float2(f3[mt][nt][half*2], f3[mt][nt][half*2 + 1]);
                    }
                }
            }
        }
        if (tid == 0) g_cd[dir][(b*NH + h)*NC + c] = __expf(sAcs[h][63]);
    }
}

// ================= K4: inter-chunk scan ======================================
__global__ __launch_bounds__(256) void k_scan()
{
    int grp = blockIdx.x;
    int bh  = blockIdx.y;
    int dir = blockIdx.z;
    int h = bh & 3, b = bh >> 2;
    int tid = threadIdx.x;
    int e0 = grp*1024 + tid*4;

    float cd[NC];
    #pragma unroll
    for (int c = 0; c < NC; c++) cd[c] = g_cd[dir][(b*NH + h)*NC + c];

    float* p = &g_st[dir][(b*NC*NH + h)*4096 + e0];
    const int cstride = NH*4096;

    float4 carry = make_float4(0.f, 0.f, 0.f, 0.f);
    float4 nxt = *(float4*)p;
    #pragma unroll
    for (int c = 0; c < NC; c++) {
        float4 cur = nxt;
        if (c + 1 < NC) nxt = *(float4*)(p + (c+1)*cstride);
        *(float4*)(p + c*cstride) = carry;
        float d = cd[c];
        carry.x = carry.x*d + cur.x;
        carry.y = carry.y*d + cur.y;
        carry.z = carry.z*d + cur.z;
        carry.w = carry.w*d + cur.w;
    }
}

// ================= K5: off-diag + epilogue + out_proj via fp16 MMA ===========
#define OUT_SMEM (27648*2 + 768*4)
__global__ __launch_bounds__(256, 2) void k_out(
    const float* __restrict__ Al_f, const float* __restrict__ Al_b,
    const float* __restrict__ nw_f, const float* __restrict__ nw_b,
    const float* __restrict__ Wo_f, const float* __restrict__ Wo_b,
    float* __restrict__ out)
{
    extern __shared__ __align__(16) char smraw[];
    __half (*sPrev)[72] = (__half(*)[72])smraw;
    __half (*sY)[264]   = (__half(*)[264])smraw;          // alias over sPrev
    __half (*sC)[72]    = (__half(*)[72])(smraw + 18432*2);
    __half (*sWo)[72]   = (__half(*)[72])(smraw + 18432*2); // alias over sC
    float* smf = (float*)(smraw + 27648*2);
    float (*sdt)[4]   = (float(*)[4])smf;
    float (*sAcs)[64] = (float(*)[64])(smf + 256);
    float (*sE)[64]   = (float(*)[64])(smf + 512);

    int c = blockIdx.x, b = blockIdx.y;
    int tid = threadIdx.x;
    int wid = tid >> 5, lane = tid & 31;
    int gid = lane >> 2, tig = lane & 3;

    float oacc[8][4] = {};

    for (int d = 0; d < 2; d++) {
        int cc = d ? (NC - 1 - c) : c;
        int base = b*SEQL + cc*CH;
        const float* Alog = d ? Al_b : Al_f;
        const float* nw   = d ? nw_b : nw_f;
        const float* Wo   = d ? Wo_b : Wo_f;

        __syncthreads();
        { int l = tid >> 2, h = tid & 3; sdt[l][h] = g_dt[d][base*NH + tid]; }
        __syncthreads();
        if (tid < 4) {
            float A = -__expf(Alog[tid]);
            float run = 0.f;
            for (int l = 0; l < 64; l++) { run += sdt[l][tid] * A; sAcs[tid][l] = run; }
        }
        __syncthreads();
        { int h = tid >> 6, l = tid & 63; sE[h][l] = __expf(sAcs[h][l]); }
        #pragma unroll
        for (int it = 0; it < 4; it++) {
            int q = tid + it*256;
            int row = q >> 4, nq = (q & 15) * 4;
            uint2 v = *(const uint2*)&g_C[d][(base+row)*64 + nq];
            *(uint2*)&sC[row][nq] = v;
        }
        {
            int pbase = (b*NC + cc)*NH*4096;
            #pragma unroll
            for (int it = 0; it < 16; it++) {
                int q = tid + it*256;
                int row = q >> 4, nq = (q & 15) * 4;
                float4 v = *(const float4*)&g_st[d][pbase + row*64 + nq];
                *(__half2*)&sPrev[row][nq]     = __floats2half2_rn(v.x, v.y);
                *(__half2*)&sPrev[row][nq + 2] = __floats2half2_rn(v.z, v.w);
            }
        }
        __syncthreads();

        // ---- off-diag MMAs (fp16, K=64 in 4 k16-steps) ----
        float facc[4][4][4];
        {
            int wn = wid;
            #pragma unroll
            for (int mt = 0; mt < 4; mt++)
                #pragma unroll
                for (int nt = 0; nt < 4; nt++)
                    #pragma unroll
                    for (int k = 0; k < 4; k++) facc[mt][nt][k] = 0.f;
            #pragma unroll
            for (int ks = 0; ks < 4; ks++) {
                int kb = ks*16;
                unsigned bf[4][2];
                #pragma unroll
                for (int nt = 0; nt < 4; nt++) {
                    int r = wn*32 + nt*8 + gid;
                    bf[nt][0] = *(unsigned*)&sPrev[r][kb + tig*2];
                    bf[nt][1] = *(unsigned*)&sPrev[r][kb + tig*2 + 8];
                }
                #pragma unroll
                for (int mt = 0; mt < 4; mt++) {
                    int r = mt*16 + gid;
                    unsigned a0 = *(unsigned*)&sC[r    ][kb + tig*2];
                    unsigned a1 = *(unsigned*)&sC[r + 8][kb + tig*2];
                    unsigned a2 = *(unsigned*)&sC[r    ][kb + tig*2 + 8];
                    unsigned a3 = *(unsigned*)&sC[r + 8][kb + tig*2 + 8];
                    #pragma unroll
                    for (int nt = 0; nt < 4; nt++)
                        mma_f16(facc[mt][nt], a0, a1, a2, a3, bf[nt][0], bf[nt][1]);
                }
            }
        }
        __syncthreads();   // sPrev/sC reads done — sY may overwrite region1

        // ---- epilogue: combine + gate -> sY (fp16, l-flip for d=1) ----
        {
            int wn = wid;
            #pragma unroll
            for (int mt = 0; mt < 4; mt++) {
                #pragma unroll
                for (int nt = 0; nt < 4; nt++) {
                    int q = wn*32 + nt*8 + tig*2;
                    int h = q >> 6;
                    #pragma unroll
                    for (int half = 0; half < 2; half++) {
                        int l = mt*16 + gid + half*8;
                        int row = base + l;
                        float e = sE[h][l];
                        float2 yd = __half22float2(*(const __half2*)&g_yd[d][row*DI + q]);
                        float2 z2 = __half22float2(*(const __half2*)&g_z[d][row*DI + q]);
                        float v0 = facc[mt][nt][half*2 + 0];
                        float v1 = facc[mt][nt][half*2 + 1];
                        float y0 = (yd.x + e*v0) * siluf(z2.x);
                        float y1 = (yd.y + e*v1) * siluf(z2.y);
                        int srow = d ? (63 - l) : l;
                        *(__half2*)&sY[srow][q] = __floats2half2_rn(y0, y1);
                    }
                }
            }
        }
        __syncthreads();

        // ---- RMS norm per row (4 threads/row) on fp16 sY ----
        {
            int lr = tid >> 2, part = tid & 3;
            float s = 0.f;
            #pragma unroll
            for (int q = 0; q < 16; q++) {
                int col = part*64 + q*4;
                float2 f0 = __half22float2(*(__half2*)&sY[lr][col]);
                float2 f1 = __half22float2(*(__half2*)&sY[lr][col + 2]);
                s += f0.x*f0.x + f0.y*f0.y + f1.x*f1.x + f1.y*f1.y;
            }
            s += __shfl_xor_sync(0xffffffff, s, 1);
            s += __shfl_xor_sync(0xffffffff, s, 2);
            float scale = rsqrtf(s * (1.f/256.f) + 1e-5f);
            #pragma unroll
            for (int q = 0; q < 16; q++) {
                int col = part*64 + q*4;
                float4 w = *(const float4*)&nw[col];
                float2 f0 = __half22float2(*(__half2*)&sY[lr][col]);
                float2 f1 = __half22float2(*(__half2*)&sY[lr][col + 2]);
                *(__half2*)&sY[lr][col]     = __floats2half2_rn(f0.x*scale*w.x, f0.y*scale*w.y);
                *(__half2*)&sY[lr][col + 2] = __floats2half2_rn(f1.x*scale*w.z, f1.y*scale*w.w);
            }
        }
        __syncthreads();

        // ---- out_proj (fp16): sWo x sY; oacc persists across jc and dirs ----
        {
            int wm = wid & 3, wn2 = wid >> 2;
            for (int jc = 0; jc < 4; jc++) {
                #pragma unroll
                for (int it = 0; it < 8; it++) {
                    int q = tid + it*256;
                    int row = q >> 4, jq = (q & 15) * 4;
                    float4 v = *(const float4*)&Wo[row*256 + jc*64 + jq];
                    *(__half2*)&sWo[row][jq]     = __floats2half2_rn(v.x, v.y);
                    *(__half2*)&sWo[row][jq + 2] = __floats2half2_rn(v.z, v.w);
                }
                __syncthreads();
                #pragma unroll
                for (int ks = 0; ks < 4; ks++) {
                    int kb = ks*16;
                    int ar = wm*16 + gid;
                    unsigned a0 = *(unsigned*)&sY[ar    ][jc*64 + kb + tig*2];
                    unsigned a1 = *(unsigned*)&sY[ar + 8][jc*64 + kb + tig*2];
                    unsigned a2 = *(unsigned*)&sY[ar    ][jc*64 + kb + tig*2 + 8];
                    unsigned a3 = *(unsigned*)&sY[ar + 8][jc*64 + kb + tig*2 + 8];
                    #pragma unroll
                    for (int nt = 0; nt < 8; nt++) {
                        int r = wn2*64 + nt*8 + gid;
                        unsigned b0 = *(unsigned*)&sWo[r][kb + tig*2];
                        unsigned b1 = *(unsigned*)&sWo[r][kb + tig*2 + 8];
                        mma_f16(oacc[nt], a0, a1, a2, a3, b0, b1);
                    }
                }
                __syncthreads();
            }
        }
    }

    // ---- final store ----
    {
        int wm = wid & 3, wn2 = wid >> 2;
        #pragma unroll
        for (int nt = 0; nt < 8; nt++) {
            int kout = wn2*64 + nt*8 + tig*2;
            #pragma unroll
            for (int half = 0; half < 2; half++) {
                int r = wm*16 + gid + half*8;
                int t = c*CH + r;
                *(float2*)&out[(b*SEQL + t)*DM + kout] =
                    make_float2(oacc[nt][half*2], oacc[nt][half*2 + 1]);
            }
        }
    }
}

extern "C" void kernel_launch(void* const* d_in, const int* in_sizes, int n_in,
                              void* d_out, int out_size)
{
    const float* x    = (const float*)d_in[0];
    const float* Wi_f = (const float*)d_in[1];
    const float* cw_f = (const float*)d_in[2];
    const float* cb_f = (const float*)d_in[3];
    const float* db_f = (const float*)d_in[4];
    const float* Al_f = (const float*)d_in[5];
    const float* D_f  = (const float*)d_in[6];
    const float* nw_f = (const float*)d_in[7];
    const float* Wo_f = (const float*)d_in[8];
    const float* Wi_b = (const float*)d_in[9];
    const float* cw_b = (const float*)d_in[10];
    const float* cb_b = (const float*)d_in[11];
    const float* db_b = (const float*)d_in[12];
    const float* Al_b = (const float*)d_in[13];
    const float* D_b  = (const float*)d_in[14];
    const float* nw_b = (const float*)d_in[15];
    const float* Wo_b = (const float*)d_in[16];
    float* out = (float*)d_out;

    cudaFuncSetAttribute(k_inproj, cudaFuncAttributeMaxDynamicSharedMemorySize, IP_SMEM);
    cudaFuncSetAttribute(k_chunk,  cudaFuncAttributeMaxDynamicSharedMemorySize, CH_SMEM);
    cudaFuncSetAttribute(k_out,    cudaFuncAttributeMaxDynamicSharedMemorySize, OUT_SMEM);

    dim3 g1(BL/128, 2);
    k_inproj<<<g1, 256, IP_SMEM>>>(x, Wi_f, Wi_b, db_f, db_b);

    dim3 g3(NC, BATCH, 2);
    k_chunk<<<g3, 256, CH_SMEM>>>(Al_f, Al_b, cw_f, cb_f, cw_b, cb_b, D_f, D_b);

    dim3 g4(4, BATCH*NH, 2);
    k_scan<<<g4, 256>>>();

    dim3 g5(NC, BATCH);
    k_out<<<g5, 256, OUT_SMEM>>>(Al_f, Al_b, nw_f, nw_b, Wo_f, Wo_b, out);
}

// round 17
// speedup vs baseline: 1.5735x; 1.0204x over previous
#include <cuda_runtime.h>
#include <cuda_fp16.h>
#include <math.h>

#define BATCH 16
#define SEQL  2048
#define BL    (BATCH*SEQL)      // 32768
#define DM    128
#define DI    256
#define DX    384
#define NH    4
#define HD    64
#define DS    64
#define CH    64
#define NC    32
#define NPROJ 644

// ---------------- scratch ----------------------------------------------------
__device__ __half g_z[2][BL*DI];        // fp16
__device__ __half g_xbc0[2][BL*DX];     // fp16 pre-conv xBC
__device__ __half g_C[2][BL*DS];        // fp16 post-conv C
__device__ float  g_dt[2][BL*NH];
__device__ __half g_st[2][BATCH*NC*NH*HD*DS];  // fp16 chunk states / prev
__device__ __half g_yd[2][BL*DI];       // fp16 Ydiag + D*xs
__device__ float  g_cd[2][BATCH*NH*NC];

__device__ __forceinline__ float softplusf(float x){ return x > 20.f ? x : log1pf(__expf(x)); }
__device__ __forceinline__ float siluf(float x){ return x / (1.f + __expf(-x)); }
__device__ __forceinline__ float4 h4tof4(const __half* p){
    __half2 a = *(const __half2*)p;
    __half2 b = *(const __half2*)(p + 2);
    float2 fa = __half22float2(a), fb = __half22float2(b);
    return make_float4(fa.x, fa.y, fb.x, fb.y);
}
// fp16 MMA, K=16
__device__ __forceinline__ void mma_f16(float c[4],
    unsigned a0, unsigned a1, unsigned a2, unsigned a3,
    unsigned b0, unsigned b1)
{
    asm("mma.sync.aligned.m16n8k16.row.col.f32.f16.f16.f32 "
        "{%0,%1,%2,%3}, {%4,%5,%6,%7}, {%8,%9}, {%0,%1,%2,%3};"
        : "+f"(c[0]), "+f"(c[1]), "+f"(c[2]), "+f"(c[3])
        : "r"(a0), "r"(a1), "r"(a2), "r"(a3), "r"(b0), "r"(b1));
}

// ================= K1: in_proj GEMM via fp16 MMA =============================
#define IP_SMEM ((128*136 + 64*136)*2)

__device__ __forceinline__ void ip_store2(int dir, const float* db, int m, int c,
                                          float v0, float v1)
{
    if (c < DI) {
        *(__half2*)&g_z[dir][m*DI + c] = __floats2half2_rn(v0, v1);
    } else if (c < DI + DX) {
        *(__half2*)&g_xbc0[dir][m*DX + (c - DI)] = __floats2half2_rn(v0, v1);
    } else if (c < DI + DX + NH) {
        int h = c - DI - DX;
        g_dt[dir][m*NH + h]     = softplusf(v0 + db[h]);
        g_dt[dir][m*NH + h + 1] = softplusf(v1 + db[h + 1]);
    }
}

__global__ __launch_bounds__(256) void k_inproj(
    const float* __restrict__ x,
    const float* __restrict__ Wi_f, const float* __restrict__ Wi_b,
    const float* __restrict__ db_f, const float* __restrict__ db_b)
{
    extern __shared__ __align__(16) char smraw[];
    __half (*sX)[136] = (__half(*)[136])smraw;
    __half (*sW)[136] = (__half(*)[136])(smraw + 128*136*2);
    int dir = blockIdx.y;
    const float* Wi = dir ? Wi_b : Wi_f;
    const float* db = dir ? db_b : db_f;
    int tid = threadIdx.x;
    int m0 = blockIdx.x * 128;
    int wid = tid >> 5, lane = tid & 31;
    int wm = wid & 1, wn = wid >> 1;
    int gid = lane >> 2, tig = lane & 3;

    #pragma unroll
    for (int it = 0; it < 16; it++) {
        int q = tid + it*256;
        int row = q >> 5, kq = (q & 31) * 4;
        int m = m0 + row;
        int xr = dir ? ((m & ~2047) + 2047 - (m & 2047)) : m;
        float4 v = *(const float4*)&x[xr*128 + kq];
        *(__half2*)&sX[row][kq]     = __floats2half2_rn(v.x, v.y);
        *(__half2*)&sX[row][kq + 2] = __floats2half2_rn(v.z, v.w);
    }

    for (int nt0 = 0; nt0 < 11; nt0++) {
        int n0 = nt0 * 64;
        __syncthreads();
        #pragma unroll
        for (int it = 0; it < 8; it++) {
            int q = tid + it*256;
            int row = q >> 5, kq = (q & 31) * 4;
            int n = n0 + row;
            float4 v = make_float4(0.f,0.f,0.f,0.f);
            if (n < NPROJ) v = *(const float4*)&Wi[n*128 + kq];
            *(__half2*)&sW[row][kq]     = __floats2half2_rn(v.x, v.y);
            *(__half2*)&sW[row][kq + 2] = __floats2half2_rn(v.z, v.w);
        }
        __syncthreads();

        float acc[4][2][4] = {};
        #pragma unroll
        for (int ks = 0; ks < 8; ks++) {
            int kb = ks*16;
            unsigned bfr[2][2];
            #pragma unroll
            for (int ni = 0; ni < 2; ni++) {
                int n = wn*16 + ni*8 + gid;
                bfr[ni][0] = *(unsigned*)&sW[n][kb + tig*2];
                bfr[ni][1] = *(unsigned*)&sW[n][kb + tig*2 + 8];
            }
            #pragma unroll
            for (int mi = 0; mi < 4; mi++) {
                int r = wm*64 + mi*16 + gid;
                unsigned a0 = *(unsigned*)&sX[r    ][kb + tig*2];
                unsigned a1 = *(unsigned*)&sX[r + 8][kb + tig*2];
                unsigned a2 = *(unsigned*)&sX[r    ][kb + tig*2 + 8];
                unsigned a3 = *(unsigned*)&sX[r + 8][kb + tig*2 + 8];
                mma_f16(acc[mi][0], a0, a1, a2, a3, bfr[0][0], bfr[0][1]);
                mma_f16(acc[mi][1], a0, a1, a2, a3, bfr[1][0], bfr[1][1]);
            }
        }
        #pragma unroll
        for (int mi = 0; mi < 4; mi++) {
            int r0 = m0 + wm*64 + mi*16 + gid;
            #pragma unroll
            for (int ni = 0; ni < 2; ni++) {
                int c = n0 + wn*16 + ni*8 + tig*2;
                ip_store2(dir, db, r0,     c, acc[mi][ni][0], acc[mi][ni][1]);
                ip_store2(dir, db, r0 + 8, c, acc[mi][ni][2], acc[mi][ni][3]);
            }
        }
    }
}

// ================= K3: conv+silu + diag + chunk state — fp16 MMA, 2-CTA ======
#define CH_SMEM (46080 + 2560*4)
__global__ __launch_bounds__(256, 2) void k_chunk(
    const float* __restrict__ Al_f, const float* __restrict__ Al_b,
    const float* __restrict__ cw_f, const float* __restrict__ cb_f,
    const float* __restrict__ cw_b, const float* __restrict__ cb_b,
    const float* __restrict__ D_f,  const float* __restrict__ D_b)
{
    extern __shared__ __align__(16) char smraw[];
    __half (*sB)[72]   = (__half(*)[72])smraw;               // [s][n]
    __half (*sCW)[72]  = (__half(*)[72])(smraw + 4608*2);    // C [l][n] then W [l][s]
    __half (*sCB)[72]  = (__half(*)[72])(smraw + 9216*2);    // [l][s]
    __half (*sXTh)[72] = (__half(*)[72])(smraw + 13824*2);   // [p][s]
    __half (*sBd)[72]  = (__half(*)[72])(smraw + 18432*2);   // [n][l] dec-scaled
    float* smf = (float*)(smraw + 46080);
    float (*sdt)[4]   = (float(*)[4])smf;
    float (*sAcs)[64] = (float(*)[64])(smf + 256);
    float *sdec       = smf + 512;
    float *sed        = smf + 576;
    float *scw        = smf + 640;
    float *scb        = smf + 2176;

    int c = blockIdx.x, b = blockIdx.y, dir = blockIdx.z;
    const __half* gx0 = g_xbc0[dir];
    const float* cw  = dir ? cw_b : cw_f;
    const float* cb  = dir ? cb_b : cb_f;
    const float* Dq  = dir ? D_b  : D_f;
    int tid = threadIdx.x;
    int base = b*SEQL + c*CH;
    int wid = tid >> 5, lane = tid & 31;
    int gid = lane >> 2, tig = lane & 3;
    int wm = wid & 1, wn = wid >> 1;

    for (int i = tid; i < 384*4; i += 256) scw[i] = cw[i];
    for (int i = tid; i < 384; i += 256) scb[i] = cb[i];
    { int l = tid >> 2, h = tid & 3; sdt[l][h] = g_dt[dir][base*NH + tid]; }
    __syncthreads();

    // ---- conv+silu staging: B/C columns (xbc idx 256..383), fp16 ----
    #pragma unroll
    for (int it = 0; it < 8; it++) {
        int q = tid + it*256;
        int row = q >> 5;
        int c4 = (q & 31) * 4;
        int jj = 256 + c4;
        float4 acc = *(const float4*)&scb[jj];
        #pragma unroll
        for (int k = 0; k < 4; k++) {
            int t = c*CH + row - 3 + k;
            if (t >= 0) {
                float4 v = h4tof4(&gx0[(b*SEQL + t)*DX + jj]);
                acc.x += v.x * scw[(jj+0)*4 + k];
                acc.y += v.y * scw[(jj+1)*4 + k];
                acc.z += v.z * scw[(jj+2)*4 + k];
                acc.w += v.w * scw[(jj+3)*4 + k];
            }
        }
        acc.x = siluf(acc.x); acc.y = siluf(acc.y);
        acc.z = siluf(acc.z); acc.w = siluf(acc.w);
        if (c4 < 64) {
            *(__half2*)&sB[row][c4]     = __floats2half2_rn(acc.x, acc.y);
            *(__half2*)&sB[row][c4 + 2] = __floats2half2_rn(acc.z, acc.w);
        } else {
            int n4 = c4 - 64;
            __half2 h0 = __floats2half2_rn(acc.x, acc.y);
            __half2 h1 = __floats2half2_rn(acc.z, acc.w);
            *(__half2*)&sCW[row][n4]     = h0;
            *(__half2*)&sCW[row][n4 + 2] = h1;
            *(__half2*)&g_C[dir][(base+row)*64 + n4]     = h0;
            *(__half2*)&g_C[dir][(base+row)*64 + n4 + 2] = h1;
        }
    }
    if (tid < 4) {
        float A = -__expf((dir ? Al_b : Al_f)[tid]);
        float run = 0.f;
        for (int l = 0; l < 64; l++) { run += sdt[l][tid] * A; sAcs[tid][l] = run; }
    }
    __syncthreads();

    // ---- phase 1: CB = C @ B^T -> sCB (fp16 MMA, 4 k16 steps) ----
    {
        float cbf[2][2][4] = {};
        #pragma unroll
        for (int ks = 0; ks < 4; ks++) {
            int kb = ks*16;
            unsigned bfr[2][2];
            #pragma unroll
            for (int nt = 0; nt < 2; nt++) {
                int s = wn*16 + nt*8 + gid;
                bfr[nt][0] = *(unsigned*)&sB[s][kb + tig*2];
                bfr[nt][1] = *(unsigned*)&sB[s][kb + tig*2 + 8];
            }
            #pragma unroll
            for (int mt = 0; mt < 2; mt++) {
                int r = wm*32 + mt*16 + gid;
                unsigned a0 = *(unsigned*)&sCW[r    ][kb + tig*2];
                unsigned a1 = *(unsigned*)&sCW[r + 8][kb + tig*2];
                unsigned a2 = *(unsigned*)&sCW[r    ][kb + tig*2 + 8];
                unsigned a3 = *(unsigned*)&sCW[r + 8][kb + tig*2 + 8];
                mma_f16(cbf[mt][0], a0, a1, a2, a3, bfr[0][0], bfr[0][1]);
                mma_f16(cbf[mt][1], a0, a1, a2, a3, bfr[1][0], bfr[1][1]);
            }
        }
        #pragma unroll
        for (int mt = 0; mt < 2; mt++) {
            #pragma unroll
            for (int half = 0; half < 2; half++) {
                int l = wm*32 + mt*16 + gid + half*8;
                #pragma unroll
                for (int nt = 0; nt < 2; nt++) {
                    int s0 = wn*16 + nt*8 + tig*2;
                    *(__half2*)&sCB[l][s0] =
                        __floats2half2_rn(cbf[mt][nt][half*2], cbf[mt][nt][half*2 + 1]);
                }
            }
        }
    }

    int sbase = (b*NC + c)*NH*4096;
    for (int h = 0; h < NH; h++) {
        __syncthreads();

        // ---- per-head conv+silu staging of X columns h*64..h*64+63 (fp16) ----
        #pragma unroll
        for (int it = 0; it < 4; it++) {
            int q = tid + it*256;
            int s = q >> 4;
            int p4 = (q & 15) * 4;
            int jj = h*64 + p4;
            float4 acc = *(const float4*)&scb[jj];
            #pragma unroll
            for (int k = 0; k < 4; k++) {
                int t = c*CH + s - 3 + k;
                if (t >= 0) {
                    float4 v = h4tof4(&gx0[(b*SEQL + t)*DX + jj]);
                    acc.x += v.x * scw[(jj+0)*4 + k];
                    acc.y += v.y * scw[(jj+1)*4 + k];
                    acc.z += v.z * scw[(jj+2)*4 + k];
                    acc.w += v.w * scw[(jj+3)*4 + k];
                }
            }
            float dtv = sdt[s][h];
            sXTh[p4+0][s] = __float2half(siluf(acc.x) * dtv);
            sXTh[p4+1][s] = __float2half(siluf(acc.y) * dtv);
            sXTh[p4+2][s] = __float2half(siluf(acc.z) * dtv);
            sXTh[p4+3][s] = __float2half(siluf(acc.w) * dtv);
        }
        if (tid < 64) {
            sdec[tid] = __expf(sAcs[h][63] - sAcs[h][tid]);
            if (tid >= 1) sed[tid] = __expf(sAcs[h][tid] - sAcs[h][tid - 1]);
        }
        __syncthreads();

        // ---- build W[l][s] (fp16) via row scan; fold D/dt into diagonal ----
        {
            int lrow = tid >> 2, part = tid & 3;
            int s_lo = part * 16;
            if (s_lo > lrow) {
                #pragma unroll
                for (int k = 0; k < 16; k++) sCW[lrow][s_lo + k] = __float2half(0.f);
            } else {
                int shi = s_lo + 15;
                int s1 = shi < lrow ? shi : lrow;
                for (int s = shi; s > s1; s--) sCW[lrow][s] = __float2half(0.f);
                float r = __expf(sAcs[h][lrow] - sAcs[h][s1]);
                float dfold = __fdividef(Dq[h], sdt[lrow][h]);
                for (int s = s1; s >= s_lo; s--) {
                    float v = __half2float(sCB[lrow][s]);
                    if (s == lrow) v += dfold;
                    sCW[lrow][s] = __float2half(v * r);
                    if (s > s_lo) r *= sed[s];
                }
            }
        }
        // ---- build sBd[n][l] = dec[l]*B[l][n] (fp16) ----
        #pragma unroll
        for (int it = 0; it < 16; it++) {
            int q = tid + it*256;
            int n = q >> 6, l = q & 63;
            sBd[n][l] = __float2half(sdec[l] * __half2float(sB[l][n]));
        }
        __syncthreads();

        // ---- phase 2: Ydiag+D*xs -> g_yd (fp16 MMA) ----
        {
            float f2[2][2][4] = {};
            #pragma unroll
            for (int ks = 0; ks < 4; ks++) {
                int kb = ks*16;
                unsigned bfr[2][2];
                #pragma unroll
                for (int nt = 0; nt < 2; nt++) {
                    int p = wn*16 + nt*8 + gid;
                    bfr[nt][0] = *(unsigned*)&sXTh[p][kb + tig*2];
                    bfr[nt][1] = *(unsigned*)&sXTh[p][kb + tig*2 + 8];
                }
                #pragma unroll
                for (int mt = 0; mt < 2; mt++) {
                    int r = wm*32 + mt*16 + gid;
                    unsigned a0 = *(unsigned*)&sCW[r    ][kb + tig*2];
                    unsigned a1 = *(unsigned*)&sCW[r + 8][kb + tig*2];
                    unsigned a2 = *(unsigned*)&sCW[r    ][kb + tig*2 + 8];
                    unsigned a3 = *(unsigned*)&sCW[r + 8][kb + tig*2 + 8];
                    mma_f16(f2[mt][0], a0, a1, a2, a3, bfr[0][0], bfr[0][1]);
                    mma_f16(f2[mt][1], a0, a1, a2, a3, bfr[1][0], bfr[1][1]);
                }
            }
            #pragma unroll
            for (int mt = 0; mt < 2; mt++) {
                #pragma unroll
                for (int half = 0; half < 2; half++) {
                    int l = wm*32 + mt*16 + gid + half*8;
                    #pragma unroll
                    for (int nt = 0; nt < 2; nt++) {
                        int p = wn*16 + nt*8 + tig*2;
                        *(__half2*)&g_yd[dir][(base + l)*DI + h*64 + p] =
                            __floats2half2_rn(f2[mt][nt][half*2], f2[mt][nt][half*2 + 1]);
                    }
                }
            }
        }

        // ---- phase 3: st[p][n] = XTh @ sBd^T (fp16 MMA) -> g_st (fp16) ----
        {
            float f3[2][2][4] = {};
            #pragma unroll
            for (int ks = 0; ks < 4; ks++) {
                int kb = ks*16;
                unsigned bfr[2][2];
                #pragma unroll
                for (int nt = 0; nt < 2; nt++) {
                    int n = wn*16 + nt*8 + gid;
                    bfr[nt][0] = *(unsigned*)&sBd[n][kb + tig*2];
                    bfr[nt][1] = *(unsigned*)&sBd[n][kb + tig*2 + 8];
                }
                #pragma unroll
                for (int mt = 0; mt < 2; mt++) {
                    int r = wm*32 + mt*16 + gid;
                    unsigned a0 = *(unsigned*)&sXTh[r    ][kb + tig*2];
                    unsigned a1 = *(unsigned*)&sXTh[r + 8][kb + tig*2];
                    unsigned a2 = *(unsigned*)&sXTh[r    ][kb + tig*2 + 8];
                    unsigned a3 = *(unsigned*)&sXTh[r + 8][kb + tig*2 + 8];
                    mma_f16(f3[mt][0], a0, a1, a2, a3, bfr[0][0], bfr[0][1]);
                    mma_f16(f3[mt][1], a0, a1, a2, a3, bfr[1][0], bfr[1][1]);
                }
            }
            #pragma unroll
            for (int mt = 0; mt < 2; mt++) {
                #pragma unroll
                for (int half = 0; half < 2; half++) {
                    int p = wm*32 + mt*16 + gid + half*8;
                    #pragma unroll
                    for (int nt = 0; nt < 2; nt++) {
                        int n = wn*16 + nt*8 + tig*2;
                        *(__half2*)&g_st[dir][sbase + h*4096 + p*64 + n] =
                            __floats2half2_rn(f3[mt][nt][half*2], f3[mt][nt][half*2 + 1]);
                    }
                }
            }
        }
        if (tid == 0) g_cd[dir][(b*NH + h)*NC + c] = __expf(sAcs[h][63]);
    }
}

// ================= K4: inter-chunk scan — fp16 storage, fp32 carry ===========
// grid: (2 groups of 2048 halves, BATCH*NH, 2); 256 thr, 8 halves/thread.
__global__ __launch_bounds__(256) void k_scan()
{
    int grp = blockIdx.x;
    int bh  = blockIdx.y;
    int dir = blockIdx.z;
    int h = bh & 3, b = bh >> 2;
    int tid = threadIdx.x;
    int e0 = grp*2048 + tid*8;

    float cd[NC];
    #pragma unroll
    for (int c = 0; c < NC; c++) cd[c] = g_cd[dir][(b*NH + h)*NC + c];

    __half* p = &g_st[dir][(b*NC*NH + h)*4096 + e0];
    const int cstride = NH*4096;

    float carry[8];
    #pragma unroll
    for (int k = 0; k < 8; k++) carry[k] = 0.f;
    uint4 nxt = *(uint4*)p;
    #pragma unroll
    for (int c = 0; c < NC; c++) {
        uint4 cur = nxt;
        if (c + 1 < NC) nxt = *(uint4*)(p + (c+1)*cstride);
        // store carry (fp16)
        uint4 cv;
        ((__half2*)&cv)[0] = __floats2half2_rn(carry[0], carry[1]);
        ((__half2*)&cv)[1] = __floats2half2_rn(carry[2], carry[3]);
        ((__half2*)&cv)[2] = __floats2half2_rn(carry[4], carry[5]);
        ((__half2*)&cv)[3] = __floats2half2_rn(carry[6], carry[7]);
        *(uint4*)(p + c*cstride) = cv;
        float d = cd[c];
        #pragma unroll
        for (int k = 0; k < 4; k++) {
            float2 f = __half22float2(((__half2*)&cur)[k]);
            carry[2*k]     = carry[2*k]*d     + f.x;
            carry[2*k + 1] = carry[2*k + 1]*d + f.y;
        }
    }
}

// ================= K5: off-diag + epilogue + out_proj via fp16 MMA ===========
#define OUT_SMEM (27648*2 + 768*4)
__global__ __launch_bounds__(256, 2) void k_out(
    const float* __restrict__ Al_f, const float* __restrict__ Al_b,
    const float* __restrict__ nw_f, const float* __restrict__ nw_b,
    const float* __restrict__ Wo_f, const float* __restrict__ Wo_b,
    float* __restrict__ out)
{
    extern __shared__ __align__(16) char smraw[];
    __half (*sPrev)[72] = (__half(*)[72])smraw;
    __half (*sY)[264]   = (__half(*)[264])smraw;          // alias over sPrev
    __half (*sC)[72]    = (__half(*)[72])(smraw + 18432*2);
    __half (*sWo)[72]   = (__half(*)[72])(smraw + 18432*2); // alias over sC
    float* smf = (float*)(smraw + 27648*2);
    float (*sdt)[4]   = (float(*)[4])smf;
    float (*sAcs)[64] = (float(*)[64])(smf + 256);
    float (*sE)[64]   = (float(*)[64])(smf + 512);

    int c = blockIdx.x, b = blockIdx.y;
    int tid = threadIdx.x;
    int wid = tid >> 5, lane = tid & 31;
    int gid = lane >> 2, tig = lane & 3;

    float oacc[8][4] = {};

    for (int d = 0; d < 2; d++) {
        int cc = d ? (NC - 1 - c) : c;
        int base = b*SEQL + cc*CH;
        const float* Alog = d ? Al_b : Al_f;
        const float* nw   = d ? nw_b : nw_f;
        const float* Wo   = d ? Wo_b : Wo_f;

        __syncthreads();
        { int l = tid >> 2, h = tid & 3; sdt[l][h] = g_dt[d][base*NH + tid]; }
        __syncthreads();
        if (tid < 4) {
            float A = -__expf(Alog[tid]);
            float run = 0.f;
            for (int l = 0; l < 64; l++) { run += sdt[l][tid] * A; sAcs[tid][l] = run; }
        }
        __syncthreads();
        { int h = tid >> 6, l = tid & 63; sE[h][l] = __expf(sAcs[h][l]); }
        #pragma unroll
        for (int it = 0; it < 4; it++) {
            int q = tid + it*256;
            int row = q >> 4, nq = (q & 15) * 4;
            uint2 v = *(const uint2*)&g_C[d][(base+row)*64 + nq];
            *(uint2*)&sC[row][nq] = v;
        }
        // sPrev: direct fp16 copy (8 halves per thread-iter)
        {
            int pbase = (b*NC + cc)*NH*4096;
            #pragma unroll
            for (int it = 0; it < 8; it++) {
                int q = tid + it*256;
                int row = q >> 3, nq = (q & 7) * 8;
                uint4 v = *(const uint4*)&g_st[d][pbase + row*64 + nq];
                *(uint4*)&sPrev[row][nq] = v;
            }
        }
        __syncthreads();

        // ---- off-diag MMAs (fp16, K=64 in 4 k16-steps) ----
        float facc[4][4][4];
        {
            int wn = wid;
            #pragma unroll
            for (int mt = 0; mt < 4; mt++)
                #pragma unroll
                for (int nt = 0; nt < 4; nt++)
                    #pragma unroll
                    for (int k = 0; k < 4; k++) facc[mt][nt][k] = 0.f;
            #pragma unroll
            for (int ks = 0; ks < 4; ks++) {
                int kb = ks*16;
                unsigned bf[4][2];
                #pragma unroll
                for (int nt = 0; nt < 4; nt++) {
                    int r = wn*32 + nt*8 + gid;
                    bf[nt][0] = *(unsigned*)&sPrev[r][kb + tig*2];
                    bf[nt][1] = *(unsigned*)&sPrev[r][kb + tig*2 + 8];
                }
                #pragma unroll
                for (int mt = 0; mt < 4; mt++) {
                    int r = mt*16 + gid;
                    unsigned a0 = *(unsigned*)&sC[r    ][kb + tig*2];
                    unsigned a1 = *(unsigned*)&sC[r + 8][kb + tig*2];
                    unsigned a2 = *(unsigned*)&sC[r    ][kb + tig*2 + 8];
                    unsigned a3 = *(unsigned*)&sC[r + 8][kb + tig*2 + 8];
                    #pragma unroll
                    for (int nt = 0; nt < 4; nt++)
                        mma_f16(facc[mt][nt], a0, a1, a2, a3, bf[nt][0], bf[nt][1]);
                }
            }
        }
        __syncthreads();

        // ---- epilogue: combine + gate -> sY (fp16, l-flip for d=1) ----
        {
            int wn = wid;
            #pragma unroll
            for (int mt = 0; mt < 4; mt++) {
                #pragma unroll
                for (int nt = 0; nt < 4; nt++) {
                    int q = wn*32 + nt*8 + tig*2;
                    int h = q >> 6;
                    #pragma unroll
                    for (int half = 0; half < 2; half++) {
                        int l = mt*16 + gid + half*8;
                        int row = base + l;
                        float e = sE[h][l];
                        float2 yd = __half22float2(*(const __half2*)&g_yd[d][row*DI + q]);
                        float2 z2 = __half22float2(*(const __half2*)&g_z[d][row*DI + q]);
                        float v0 = facc[mt][nt][half*2 + 0];
                        float v1 = facc[mt][nt][half*2 + 1];
                        float y0 = (yd.x + e*v0) * siluf(z2.x);
                        float y1 = (yd.y + e*v1) * siluf(z2.y);
                        int srow = d ? (63 - l) : l;
                        *(__half2*)&sY[srow][q] = __floats2half2_rn(y0, y1);
                    }
                }
            }
        }
        __syncthreads();

        // ---- RMS norm per row (4 threads/row) on fp16 sY ----
        {
            int lr = tid >> 2, part = tid & 3;
            float s = 0.f;
            #pragma unroll
            for (int q = 0; q < 16; q++) {
                int col = part*64 + q*4;
                float2 f0 = __half22float2(*(__half2*)&sY[lr][col]);
                float2 f1 = __half22float2(*(__half2*)&sY[lr][col + 2]);
                s += f0.x*f0.x + f0.y*f0.y + f1.x*f1.x + f1.y*f1.y;
            }
            s += __shfl_xor_sync(0xffffffff, s, 1);
            s += __shfl_xor_sync(0xffffffff, s, 2);
            float scale = rsqrtf(s * (1.f/256.f) + 1e-5f);
            #pragma unroll
            for (int q = 0; q < 16; q++) {
                int col = part*64 + q*4;
                float4 w = *(const float4*)&nw[col];
                float2 f0 = __half22float2(*(__half2*)&sY[lr][col]);
                float2 f1 = __half22float2(*(__half2*)&sY[lr][col + 2]);
                *(__half2*)&sY[lr][col]     = __floats2half2_rn(f0.x*scale*w.x, f0.y*scale*w.y);
                *(__half2*)&sY[lr][col + 2] = __floats2half2_rn(f1.x*scale*w.z, f1.y*scale*w.w);
            }
        }
        __syncthreads();

        // ---- out_proj (fp16): sWo x sY; oacc persists across jc and dirs ----
        {
            int wm = wid & 3, wn2 = wid >> 2;
            for (int jc = 0; jc < 4; jc++) {
                #pragma unroll
                for (int it = 0; it < 8; it++) {
                    int q = tid + it*256;
                    int row = q >> 4, jq = (q & 15) * 4;
                    float4 v = *(const float4*)&Wo[row*256 + jc*64 + jq];
                    *(__half2*)&sWo[row][jq]     = __floats2half2_rn(v.x, v.y);
                    *(__half2*)&sWo[row][jq + 2] = __floats2half2_rn(v.z, v.w);
                }
                __syncthreads();
                #pragma unroll
                for (int ks = 0; ks < 4; ks++) {
                    int kb = ks*16;
                    int ar = wm*16 + gid;
                    unsigned a0 = *(unsigned*)&sY[ar    ][jc*64 + kb + tig*2];
                    unsigned a1 = *(unsigned*)&sY[ar + 8][jc*64 + kb + tig*2];
                    unsigned a2 = *(unsigned*)&sY[ar    ][jc*64 + kb + tig*2 + 8];
                    unsigned a3 = *(unsigned*)&sY[ar + 8][jc*64 + kb + tig*2 + 8];
                    #pragma unroll
                    for (int nt = 0; nt < 8; nt++) {
                        int r = wn2*64 + nt*8 + gid;
                        unsigned b0 = *(unsigned*)&sWo[r][kb + tig*2];
                        unsigned b1 = *(unsigned*)&sWo[r][kb + tig*2 + 8];
                        mma_f16(oacc[nt], a0, a1, a2, a3, b0, b1);
                    }
                }
                __syncthreads();
            }
        }
    }

    // ---- final store ----
    {
        int wm = wid & 3, wn2 = wid >> 2;
        #pragma unroll
        for (int nt = 0; nt < 8; nt++) {
            int kout = wn2*64 + nt*8 + tig*2;
            #pragma unroll
            for (int half = 0; half < 2; half++) {
                int r = wm*16 + gid + half*8;
                int t = c*CH + r;
                *(float2*)&out[(b*SEQL + t)*DM + kout] =
                    make_float2(oacc[nt][half*2], oacc[nt][half*2 + 1]);
            }
        }
    }
}

extern "C" void kernel_launch(void* const* d_in, const int* in_sizes, int n_in,
                              void* d_out, int out_size)
{
    const float* x    = (const float*)d_in[0];
    const float* Wi_f = (const float*)d_in[1];
    const float* cw_f = (const float*)d_in[2];
    const float* cb_f = (const float*)d_in[3];
    const float* db_f = (const float*)d_in[4];
    const float* Al_f = (const float*)d_in[5];
    const float* D_f  = (const float*)d_in[6];
    const float* nw_f = (const float*)d_in[7];
    const float* Wo_f = (const float*)d_in[8];
    const float* Wi_b = (const float*)d_in[9];
    const float* cw_b = (const float*)d_in[10];
    const float* cb_b = (const float*)d_in[11];
    const float* db_b = (const float*)d_in[12];
    const float* Al_b = (const float*)d_in[13];
    const float* D_b  = (const float*)d_in[14];
    const float* nw_b = (const float*)d_in[15];
    const float* Wo_b = (const float*)d_in[16];
    float* out = (float*)d_out;

    cudaFuncSetAttribute(k_inproj, cudaFuncAttributeMaxDynamicSharedMemorySize, IP_SMEM);
    cudaFuncSetAttribute(k_chunk,  cudaFuncAttributeMaxDynamicSharedMemorySize, CH_SMEM);
    cudaFuncSetAttribute(k_out,    cudaFuncAttributeMaxDynamicSharedMemorySize, OUT_SMEM);

    dim3 g1(BL/128, 2);
    k_inproj<<<g1, 256, IP_SMEM>>>(x, Wi_f, Wi_b, db_f, db_b);

    dim3 g3(NC, BATCH, 2);
    k_chunk<<<g3, 256, CH_SMEM>>>(Al_f, Al_b, cw_f, cb_f, cw_b, cb_b, D_f, D_b);

    dim3 g4(2, BATCH*NH, 2);
    k_scan<<<g4, 256>>>();

    dim3 g5(NC, BATCH);
    k_out<<<g5, 256, OUT_SMEM>>>(Al_f, Al_b, nw_f, nw_b, Wo_f, Wo_b, out);
}